// round 2
// baseline (speedup 1.0000x reference)
#include <cuda_runtime.h>

typedef unsigned long long ull;

#define BB 4
#define HH 224
#define WL 224
#define HW 50176
#define NC 64
#define EE 768
#define SS 256

// ---- scratch (static device allocations; no cudaMalloc allowed) ----
__device__ float g_buf1[BB*NC*HW];   // conv1 output  (51.4 MB)
__device__ float g_buf2[BB*NC*HW];   // conv2 output  (51.4 MB)
__device__ int   g_cnt[BB*SS];
__device__ int   g_off[BB*SS];
__device__ int   g_cur[BB*SS];
__device__ int   g_order[BB*HW];

// ---- packed fp32x2 helpers (sm_100+) ----
__device__ __forceinline__ ull pack2(float a, float b){
    ull d; asm("mov.b64 %0,{%1,%2};" : "=l"(d) : "f"(a), "f"(b)); return d;
}
__device__ __forceinline__ void ffma2(ull& d, ull a, ull b){
    asm("fma.rn.f32x2 %0,%1,%2,%0;" : "+l"(d) : "l"(a), "l"(b));
}
__device__ __forceinline__ float2 unpack2(ull d){
    float2 f; asm("mov.b64 {%0,%1},%2;" : "=f"(f.x), "=f"(f.y) : "l"(d)); return f;
}

// ================= zero counters (re-zero every launch / graph replay) ======
__global__ void k_zero(){
    int t = threadIdx.x;   // 1024 threads == BB*SS
    g_cnt[t] = 0; g_cur[t] = 0;
}

// ================= conv1: 3->64, 3x3 SAME, relu =============================
__global__ __launch_bounds__(256) void k_conv1(const float* __restrict__ img,
                                               const float* __restrict__ w1){
    __shared__ float ws[64*27];
    int tid = threadIdx.x;
    for (int i = tid; i < 64*27; i += 256) ws[i] = w1[i];
    __syncthreads();
    int b = blockIdx.y;
    int p = blockIdx.x*256 + tid;
    int y = p / WL, x = p % WL;
    float v[27];
#pragma unroll
    for (int ci = 0; ci < 3; ci++)
#pragma unroll
    for (int ky = 0; ky < 3; ky++)
#pragma unroll
    for (int kx = 0; kx < 3; kx++){
        int yy = y + ky - 1, xx = x + kx - 1;
        float val = 0.f;
        if (yy >= 0 && yy < HH && xx >= 0 && xx < WL)
            val = img[(size_t)(b*3+ci)*HW + yy*WL + xx];
        v[ci*9 + ky*3 + kx] = val;
    }
#pragma unroll 4
    for (int co = 0; co < 64; co++){
        float a = 0.f;
#pragma unroll
        for (int t = 0; t < 27; t++) a = fmaf(ws[co*27+t], v[t], a);
        g_buf1[(size_t)(b*64+co)*HW + p] = fmaxf(a, 0.f);
    }
}

// ================= conv2: 64->64, 3x3 SAME, relu ============================
__global__ __launch_bounds__(256) void k_conv2(const float* __restrict__ w2){
    __shared__ float ins[8][10][35];
    __shared__ ull   wsh[8][9][64];
    int tid = threadIdx.x;
    int b  = blockIdx.z;
    int x0 = blockIdx.x*32, y0 = blockIdx.y*8;
    int cog = tid >> 5;
    int r   = tid & 31;
    int ty  = r >> 2;
    int xl0 = (r & 3) * 8;

    ull acc[8][4];
#pragma unroll
    for (int c = 0; c < 8; c++)
#pragma unroll
    for (int q = 0; q < 4; q++) acc[c][q] = 0ULL;

    for (int cc = 0; cc < 8; cc++){
        for (int lin = tid; lin < 2720; lin += 256){
            int ci = lin / 340, rem = lin % 340;
            int rr = rem / 34, ccol = rem % 34;
            int gy = y0 + rr - 1, gx = x0 + ccol - 1;
            float v = 0.f;
            if (gy >= 0 && gy < HH && gx >= 0 && gx < WL)
                v = g_buf1[(size_t)(b*64 + cc*8 + ci)*HW + gy*WL + gx];
            ins[ci][rr][ccol] = v;
        }
        for (int lin = tid; lin < 4608; lin += 256){
            int co = lin / 72, rem = lin % 72;
            int ci = rem / 9, k = rem % 9;
            float v = w2[co*576 + (cc*8+ci)*9 + k];
            wsh[ci][k][co] = pack2(v, v);
        }
        __syncthreads();
#pragma unroll 2
        for (int ci = 0; ci < 8; ci++){
#pragma unroll
            for (int ky = 0; ky < 3; ky++){
                float a[10];
#pragma unroll
                for (int m = 0; m < 10; m++) a[m] = ins[ci][ty+ky][xl0+m];
                ull P[9];
#pragma unroll
                for (int m = 0; m < 9; m++) P[m] = pack2(a[m], a[m+1]);
#pragma unroll
                for (int kx = 0; kx < 3; kx++){
#pragma unroll
                    for (int c = 0; c < 8; c++){
                        ull w = wsh[ci][ky*3+kx][cog*8+c];
                        ffma2(acc[c][0], P[kx+0], w);
                        ffma2(acc[c][1], P[kx+2], w);
                        ffma2(acc[c][2], P[kx+4], w);
                        ffma2(acc[c][3], P[kx+6], w);
                    }
                }
            }
        }
        __syncthreads();
    }
    int y = y0 + ty;
#pragma unroll
    for (int c = 0; c < 8; c++){
        int co = cog*8 + c;
        float* outp = &g_buf2[(size_t)(b*64+co)*HW + y*WL + x0 + xl0];
#pragma unroll
        for (int q = 0; q < 4; q++){
            float2 v = unpack2(acc[c][q]);
            v.x = fmaxf(v.x, 0.f); v.y = fmaxf(v.y, 0.f);
            *(float2*)(outp + 2*q) = v;
        }
    }
}

// ================= segment counting sort =====================================
__global__ __launch_bounds__(256) void k_hist(const int* __restrict__ seg){
    __shared__ int hist[SS];
    int tid = threadIdx.x;
    hist[tid] = 0;
    __syncthreads();
    int b = blockIdx.y;
    int base = blockIdx.x * 1024;
#pragma unroll
    for (int i = 0; i < 4; i++){
        int s = seg[(size_t)b*HW + base + i*256 + tid];
        atomicAdd(&hist[s], 1);
    }
    __syncthreads();
    atomicAdd(&g_cnt[b*SS + tid], hist[tid]);
}

__global__ void k_scan(){
    __shared__ int s[1024];
    int t = threadIdx.x;
    int v = g_cnt[t];
    s[t] = v;
    __syncthreads();
    for (int d = 1; d < 1024; d <<= 1){
        int add = (t >= d) ? s[t-d] : 0;
        __syncthreads();
        s[t] += add;
        __syncthreads();
    }
    g_off[t] = s[t] - v;
}

__global__ __launch_bounds__(256) void k_scatter(const int* __restrict__ seg){
    int b = blockIdx.y;
    int p = blockIdx.x*256 + threadIdx.x;
    int sgm = seg[(size_t)b*HW + p];
    int bin = b*SS + sgm;
    int idx = atomicAdd(&g_cur[bin], 1);
    g_order[g_off[bin] + idx] = p;
}

// ================= conv3 (1x1, 64->768, relu) fused with mean pooling =======
// Register-tiled micro-GEMM. Grid = (1024 bins, 3 e-chunks of 256).
// CTA 256 threads: tid = p + 8*g; e-group g (0..31) owns 8 e's, px-group p
// (0..7) owns 8 pixels of a 64-px staged block. Thread tile: 8e x 8px in
// 32 ull accumulators (64 regs). Per ci: 2 LDS.128 (weights, 8-way bcast) +
// 4 LDS.128 (features, 4-way bcast) feed 32 FFMA2 -> FMA-pipe bound.
// Per-pixel relu drained from registers after each 64-px block; zero-padded
// pixels contribute relu(0)=0 (conv3 has no bias).
#define C3_SMEM (32768 + 65536 + 256 + 8192)
__global__ __launch_bounds__(256) void k_conv3pool(const float* __restrict__ w3,
                                                   float* __restrict__ out){
    extern __shared__ char sm[];
    ull (*fs)[64]  = (ull(*)[64])sm;                 // [64][64] (f,f) dup
    ull (*ws)[128] = (ull(*)[128])(sm + 32768);      // [64][128] (e0,e1) pairs
    int* pixsm     = (int*)(sm + 98304);             // [64]
    float (*red)[8]= (float(*)[8])(sm + 98560);      // [256][8]

    int tid = threadIdx.x;
    int bin = blockIdx.x;          // 0..1023
    int ec  = blockIdx.y;          // 0..2
    int b   = bin >> 8;
    int npix = g_cnt[bin];
    int off  = g_off[bin];
    const float* fbase = g_buf2 + (size_t)b*64*HW;

    // stage weights for this 256-e chunk
    for (int lin = tid; lin < 64*128; lin += 256){
        int ci = lin >> 7, pl = lin & 127;
        int e0 = ec*256 + pl*2;
        ws[ci][pl] = pack2(w3[(size_t)e0*64 + ci], w3[(size_t)(e0+1)*64 + ci]);
    }

    int g = tid >> 3;              // e-group
    int p = tid & 7;               // px-group

    ull acc[4][8];
#pragma unroll
    for (int pl = 0; pl < 4; pl++)
#pragma unroll
    for (int q = 0; q < 8; q++) acc[pl][q] = 0ULL;
    float sums[8];
#pragma unroll
    for (int k = 0; k < 8; k++) sums[k] = 0.f;

    for (int pb = 0; pb < npix; pb += 64){
        int rem = npix - pb; if (rem > 64) rem = 64;
        __syncthreads();           // ws ready (1st iter) / fs reads done (later)
        if (tid < 64) pixsm[tid] = (tid < rem) ? g_order[off + pb + tid] : -1;
        __syncthreads();
        for (int lin = tid; lin < 4096; lin += 256){
            int ci = lin >> 6, px = lin & 63;
            int pix = pixsm[px];
            float v = (pix >= 0) ? fbase[(size_t)ci*HW + pix] : 0.f;
            fs[ci][px] = pack2(v, v);
        }
        __syncthreads();
#pragma unroll 4
        for (int ci = 0; ci < 64; ci++){
            ulonglong2 wa = *(const ulonglong2*)&ws[ci][g*4];
            ulonglong2 wb = *(const ulonglong2*)&ws[ci][g*4+2];
            ulonglong2 f0 = *(const ulonglong2*)&fs[ci][p*8];
            ulonglong2 f1 = *(const ulonglong2*)&fs[ci][p*8+2];
            ulonglong2 f2 = *(const ulonglong2*)&fs[ci][p*8+4];
            ulonglong2 f3 = *(const ulonglong2*)&fs[ci][p*8+6];
            ull w[4] = {wa.x, wa.y, wb.x, wb.y};
            ull f[8] = {f0.x, f0.y, f1.x, f1.y, f2.x, f2.y, f3.x, f3.y};
#pragma unroll
            for (int pl = 0; pl < 4; pl++)
#pragma unroll
            for (int q = 0; q < 8; q++)
                ffma2(acc[pl][q], f[q], w[pl]);
        }
        // drain: per-pixel relu, accumulate into per-e partial sums
#pragma unroll
        for (int pl = 0; pl < 4; pl++)
#pragma unroll
        for (int q = 0; q < 8; q++){
            float2 v = unpack2(acc[pl][q]);
            sums[2*pl]   += fmaxf(v.x, 0.f);
            sums[2*pl+1] += fmaxf(v.y, 0.f);
            acc[pl][q] = 0ULL;
        }
    }

    __syncthreads();
#pragma unroll
    for (int k = 0; k < 8; k++) red[g*8+k][p] = sums[k];
    __syncthreads();
    float s = 0.f;
#pragma unroll
    for (int j = 0; j < 8; j++) s += red[tid][j];
    float inv = 1.f / (float)max(npix, 1);
    out[(size_t)bin*EE + ec*256 + tid] = s * inv;
}

// ================= positional MLP ===========================================
__global__ __launch_bounds__(256) void k_pos(const float* __restrict__ cent,
        const float* __restrict__ w1, const float* __restrict__ b1,
        const float* __restrict__ w2, const float* __restrict__ b2,
        float* __restrict__ out){
    __shared__ __align__(8) float h2[384*16];
    int tid = threadIdx.x;
    int rb = blockIdx.x * 16;
    for (int lin = tid; lin < 6144; lin += 256){
        int j = lin >> 4, r = lin & 15;
        int rid = rb + r;
        float c0 = cent[rid*2+0] * (1.f/223.f);
        float c1 = cent[rid*2+1] * (1.f/223.f);
        float h = fmaxf(fmaf(c0, w1[j], fmaf(c1, w1[384+j], b1[j])), 0.f);
        h2[j*16 + r] = h;
    }
    __syncthreads();
    ull acc[3][8];
#pragma unroll
    for (int es = 0; es < 3; es++)
#pragma unroll
    for (int q = 0; q < 8; q++) acc[es][q] = 0ULL;
    for (int j = 0; j < 384; j++){
        ull hp[8];
#pragma unroll
        for (int q = 0; q < 8; q++) hp[q] = *(const ull*)&h2[j*16 + 2*q];
#pragma unroll
        for (int es = 0; es < 3; es++){
            float wv = w2[j*768 + tid + es*256];
            ull wp = pack2(wv, wv);
#pragma unroll
            for (int q = 0; q < 8; q++) ffma2(acc[es][q], hp[q], wp);
        }
    }
#pragma unroll
    for (int es = 0; es < 3; es++){
        int e = tid + es*256;
        float bv = b2[e];
#pragma unroll
        for (int q = 0; q < 8; q++){
            float2 v = unpack2(acc[es][q]);
            int rid = rb + 2*q;
            out[(size_t)rid*768 + e]     = v.x + bv;
            out[(size_t)(rid+1)*768 + e] = v.y + bv;
        }
    }
}

// ================= launcher =================================================
extern "C" void kernel_launch(void* const* d_in, const int* in_sizes, int n_in,
                              void* d_out, int out_size){
    const float* img  = (const float*)d_in[0];
    const int*   seg  = (const int*)d_in[1];
    const float* cent = (const float*)d_in[2];
    const float* w1   = (const float*)d_in[3];
    const float* w2   = (const float*)d_in[4];
    const float* w3   = (const float*)d_in[5];
    const float* pw1  = (const float*)d_in[6];
    const float* pb1  = (const float*)d_in[7];
    const float* pw2  = (const float*)d_in[8];
    const float* pb2  = (const float*)d_in[9];
    float* out = (float*)d_out;

    cudaFuncSetAttribute(k_conv3pool,
                         cudaFuncAttributeMaxDynamicSharedMemorySize, C3_SMEM);

    k_zero<<<1, 1024>>>();
    k_conv1<<<dim3(196,4), 256>>>(img, w1);
    k_conv2<<<dim3(7,28,4), 256>>>(w2);
    k_hist<<<dim3(49,4), 256>>>(seg);
    k_scan<<<1, 1024>>>();
    k_scatter<<<dim3(196,4), 256>>>(seg);
    k_conv3pool<<<dim3(BB*SS, 3), 256, C3_SMEM>>>(w3, out);
    k_pos<<<64, 256>>>(cent, pw1, pb1, pw2, pb2, out + (size_t)BB*SS*EE);
}

// round 3
// speedup vs baseline: 1.7625x; 1.7625x over previous
#include <cuda_runtime.h>

typedef unsigned long long ull;

#define BB 4
#define HH 224
#define WL 224
#define HW 50176
#define NC 64
#define EE 768
#define SS 256

// ---- scratch (static device allocations; no cudaMalloc allowed) ----
__device__ float g_buf1[BB*NC*HW];   // conv1 output  (51.4 MB)
__device__ float g_buf2[BB*NC*HW];   // conv2 output  (51.4 MB)
__device__ int   g_cnt[BB*SS];
__device__ int   g_off[BB*SS];
__device__ int   g_cur[BB*SS];
__device__ int   g_order[BB*HW];

// ---- packed fp32x2 helpers (sm_100+) ----
__device__ __forceinline__ ull pack2(float a, float b){
    ull d; asm("mov.b64 %0,{%1,%2};" : "=l"(d) : "f"(a), "f"(b)); return d;
}
__device__ __forceinline__ void ffma2(ull& d, ull a, ull b){
    asm("fma.rn.f32x2 %0,%1,%2,%0;" : "+l"(d) : "l"(a), "l"(b));
}
__device__ __forceinline__ float2 unpack2(ull d){
    float2 f; asm("mov.b64 {%0,%1},%2;" : "=f"(f.x), "=f"(f.y) : "l"(d)); return f;
}

// ================= zero counters ============================================
__global__ void k_zero(){
    int t = threadIdx.x;   // 1024 threads == BB*SS
    g_cnt[t] = 0; g_cur[t] = 0;
}

// ================= conv1: 3->64, 3x3 SAME, relu =============================
__global__ __launch_bounds__(256) void k_conv1(const float* __restrict__ img,
                                               const float* __restrict__ w1){
    __shared__ float ws[64*27];
    int tid = threadIdx.x;
    for (int i = tid; i < 64*27; i += 256) ws[i] = w1[i];
    __syncthreads();
    int b = blockIdx.y;
    int p = blockIdx.x*256 + tid;
    int y = p / WL, x = p % WL;
    float v[27];
#pragma unroll
    for (int ci = 0; ci < 3; ci++)
#pragma unroll
    for (int ky = 0; ky < 3; ky++)
#pragma unroll
    for (int kx = 0; kx < 3; kx++){
        int yy = y + ky - 1, xx = x + kx - 1;
        float val = 0.f;
        if (yy >= 0 && yy < HH && xx >= 0 && xx < WL)
            val = img[(size_t)(b*3+ci)*HW + yy*WL + xx];
        v[ci*9 + ky*3 + kx] = val;
    }
#pragma unroll 4
    for (int co = 0; co < 64; co++){
        float a = 0.f;
#pragma unroll
        for (int t = 0; t < 27; t++) a = fmaf(ws[co*27+t], v[t], a);
        g_buf1[(size_t)(b*64+co)*HW + p] = fmaxf(a, 0.f);
    }
}

// ================= conv2: 64->64, 3x3 SAME, relu ============================
__global__ __launch_bounds__(256) void k_conv2(const float* __restrict__ w2){
    __shared__ float ins[8][10][35];
    __shared__ ull   wsh[8][9][64];
    int tid = threadIdx.x;
    int b  = blockIdx.z;
    int x0 = blockIdx.x*32, y0 = blockIdx.y*8;
    int cog = tid >> 5;
    int r   = tid & 31;
    int ty  = r >> 2;
    int xl0 = (r & 3) * 8;

    ull acc[8][4];
#pragma unroll
    for (int c = 0; c < 8; c++)
#pragma unroll
    for (int q = 0; q < 4; q++) acc[c][q] = 0ULL;

    for (int cc = 0; cc < 8; cc++){
        for (int lin = tid; lin < 2720; lin += 256){
            int ci = lin / 340, rem = lin % 340;
            int rr = rem / 34, ccol = rem % 34;
            int gy = y0 + rr - 1, gx = x0 + ccol - 1;
            float v = 0.f;
            if (gy >= 0 && gy < HH && gx >= 0 && gx < WL)
                v = g_buf1[(size_t)(b*64 + cc*8 + ci)*HW + gy*WL + gx];
            ins[ci][rr][ccol] = v;
        }
        for (int lin = tid; lin < 4608; lin += 256){
            int co = lin / 72, rem = lin % 72;
            int ci = rem / 9, k = rem % 9;
            float v = w2[co*576 + (cc*8+ci)*9 + k];
            wsh[ci][k][co] = pack2(v, v);
        }
        __syncthreads();
#pragma unroll 2
        for (int ci = 0; ci < 8; ci++){
#pragma unroll
            for (int ky = 0; ky < 3; ky++){
                float a[10];
#pragma unroll
                for (int m = 0; m < 10; m++) a[m] = ins[ci][ty+ky][xl0+m];
                ull P[9];
#pragma unroll
                for (int m = 0; m < 9; m++) P[m] = pack2(a[m], a[m+1]);
#pragma unroll
                for (int kx = 0; kx < 3; kx++){
#pragma unroll
                    for (int c = 0; c < 8; c++){
                        ull w = wsh[ci][ky*3+kx][cog*8+c];
                        ffma2(acc[c][0], P[kx+0], w);
                        ffma2(acc[c][1], P[kx+2], w);
                        ffma2(acc[c][2], P[kx+4], w);
                        ffma2(acc[c][3], P[kx+6], w);
                    }
                }
            }
        }
        __syncthreads();
    }
    int y = y0 + ty;
#pragma unroll
    for (int c = 0; c < 8; c++){
        int co = cog*8 + c;
        float* outp = &g_buf2[(size_t)(b*64+co)*HW + y*WL + x0 + xl0];
#pragma unroll
        for (int q = 0; q < 4; q++){
            float2 v = unpack2(acc[c][q]);
            v.x = fmaxf(v.x, 0.f); v.y = fmaxf(v.y, 0.f);
            *(float2*)(outp + 2*q) = v;
        }
    }
}

// ================= segment counting sort =====================================
__global__ __launch_bounds__(256) void k_hist(const int* __restrict__ seg){
    __shared__ int hist[SS];
    int tid = threadIdx.x;
    hist[tid] = 0;
    __syncthreads();
    int b = blockIdx.y;
    int base = blockIdx.x * 1024;
#pragma unroll
    for (int i = 0; i < 4; i++){
        int s = seg[(size_t)b*HW + base + i*256 + tid];
        atomicAdd(&hist[s], 1);
    }
    __syncthreads();
    atomicAdd(&g_cnt[b*SS + tid], hist[tid]);
}

__global__ void k_scan(){
    __shared__ int s[1024];
    int t = threadIdx.x;
    int v = g_cnt[t];
    s[t] = v;
    __syncthreads();
    for (int d = 1; d < 1024; d <<= 1){
        int add = (t >= d) ? s[t-d] : 0;
        __syncthreads();
        s[t] += add;
        __syncthreads();
    }
    g_off[t] = s[t] - v;
}

__global__ __launch_bounds__(256) void k_scatter(const int* __restrict__ seg){
    int b = blockIdx.y;
    int p = blockIdx.x*256 + threadIdx.x;
    int sgm = seg[(size_t)b*HW + p];
    int bin = b*SS + sgm;
    int idx = atomicAdd(&g_cur[bin], 1);
    g_order[g_off[bin] + idx] = p;
}

// ================= conv3 (1x1, 64->768, relu) fused with mean pooling =======
// One CTA per bin; all 768 e's per CTA (features gathered ONCE).
// Weights staged once: ws[ci][pair] (192 KB). 16-px blocks double-buffered.
// Thread: p = tid&1 (px half, 8 px), g = tid>>1 (pairs g, 128+g, 256+g).
// acc = 3 pairs x 8 px = 24 ull (48 regs). Per ci: 3 LDS.64 + 4 LDS.128 +
// 24 FFMA2 -> FMA-bound. Next block's scattered gathers prefetched into regs
// before compute, STS'd after -> latency hidden. shfl-xor reduce, no atomics.
#define C3_SMEM (196608 + 16384)
__global__ __launch_bounds__(256) void k_conv3pool(const float* __restrict__ w3,
                                                   float* __restrict__ out){
    extern __shared__ char sm[];
    ull (*ws)[384]    = (ull(*)[384])sm;                 // [64][384]
    ull (*fs)[64][16] = (ull(*)[64][16])(sm + 196608);   // [2][64][16] (f,f)

    int tid = threadIdx.x;
    int bin = blockIdx.x;
    int b   = bin >> 8;
    int npix = g_cnt[bin];
    int off  = g_off[bin];
    const float* fbase = g_buf2 + (size_t)b*64*HW;

    // ---- stage all weights: ws[ci][pr] = (w3[2pr][ci], w3[2pr+1][ci]) ----
    for (int lin = tid; lin < 384*16; lin += 256){
        int pr = lin % 384, ci4 = lin / 384;
        const float4 a = *(const float4*)&w3[(size_t)(2*pr)*64   + ci4*4];
        const float4 c = *(const float4*)&w3[(size_t)(2*pr+1)*64 + ci4*4];
        ws[ci4*4+0][pr] = pack2(a.x, c.x);
        ws[ci4*4+1][pr] = pack2(a.y, c.y);
        ws[ci4*4+2][pr] = pack2(a.z, c.z);
        ws[ci4*4+3][pr] = pack2(a.w, c.w);
    }

    int nblk = (npix + 15) >> 4;
    int px  = tid & 15;          // staging role
    int ci0 = (tid >> 4) * 4;    // staging role: 4 ci's
    int p   = tid & 1;           // compute role: px half
    int g   = tid >> 1;          // compute role: pair group

    // ---- prologue: stage block 0 into fs[0] ----
    if (nblk > 0){
        bool valid = px < npix;
        int pix = valid ? g_order[off + px] : 0;
        float v0=0.f,v1=0.f,v2=0.f,v3=0.f;
        if (valid){
            v0 = fbase[(size_t)(ci0+0)*HW + pix];
            v1 = fbase[(size_t)(ci0+1)*HW + pix];
            v2 = fbase[(size_t)(ci0+2)*HW + pix];
            v3 = fbase[(size_t)(ci0+3)*HW + pix];
        }
        fs[0][ci0+0][px] = pack2(v0, v0);
        fs[0][ci0+1][px] = pack2(v1, v1);
        fs[0][ci0+2][px] = pack2(v2, v2);
        fs[0][ci0+3][px] = pack2(v3, v3);
    }
    __syncthreads();

    float sums[6];
#pragma unroll
    for (int k = 0; k < 6; k++) sums[k] = 0.f;

    for (int blk = 0; blk < nblk; blk++){
        int cur = blk & 1;
        // prefetch next block's features into registers (hide gather latency)
        float v0=0.f,v1=0.f,v2=0.f,v3=0.f;
        bool hav = (blk + 1 < nblk);
        if (hav){
            int idx = (blk+1)*16 + px;
            bool valid = idx < npix;
            int pix = valid ? g_order[off + idx] : 0;
            if (valid){
                v0 = fbase[(size_t)(ci0+0)*HW + pix];
                v1 = fbase[(size_t)(ci0+1)*HW + pix];
                v2 = fbase[(size_t)(ci0+2)*HW + pix];
                v3 = fbase[(size_t)(ci0+3)*HW + pix];
            }
        }
        // compute on fs[cur]
        ull acc[3][8];
#pragma unroll
        for (int j = 0; j < 3; j++)
#pragma unroll
        for (int q = 0; q < 8; q++) acc[j][q] = 0ULL;

#pragma unroll 2
        for (int ci = 0; ci < 64; ci++){
            ull w0 = ws[ci][g];
            ull w1 = ws[ci][128+g];
            ull w2 = ws[ci][256+g];
            const ull* fr = &fs[cur][ci][p*8];
            ulonglong2 fa = *(const ulonglong2*)(fr+0);
            ulonglong2 fb = *(const ulonglong2*)(fr+2);
            ulonglong2 fc = *(const ulonglong2*)(fr+4);
            ulonglong2 fd = *(const ulonglong2*)(fr+6);
            ull f[8] = {fa.x, fa.y, fb.x, fb.y, fc.x, fc.y, fd.x, fd.y};
#pragma unroll
            for (int q = 0; q < 8; q++){
                ffma2(acc[0][q], f[q], w0);
                ffma2(acc[1][q], f[q], w1);
                ffma2(acc[2][q], f[q], w2);
            }
        }
        // store prefetched block
        if (hav){
            fs[cur^1][ci0+0][px] = pack2(v0, v0);
            fs[cur^1][ci0+1][px] = pack2(v1, v1);
            fs[cur^1][ci0+2][px] = pack2(v2, v2);
            fs[cur^1][ci0+3][px] = pack2(v3, v3);
        }
        // drain: per-pixel relu -> per-e partial sums
#pragma unroll
        for (int j = 0; j < 3; j++)
#pragma unroll
        for (int q = 0; q < 8; q++){
            float2 v = unpack2(acc[j][q]);
            sums[2*j]   += fmaxf(v.x, 0.f);
            sums[2*j+1] += fmaxf(v.y, 0.f);
        }
        __syncthreads();
    }

    // reduce across the two px halves (partner = tid^1), then write
#pragma unroll
    for (int k = 0; k < 6; k++)
        sums[k] += __shfl_xor_sync(0xffffffffu, sums[k], 1);
    if (p == 0){
        float inv = 1.f / (float)max(npix, 1);
        float* ob = out + (size_t)bin*EE;
#pragma unroll
        for (int j = 0; j < 3; j++){
            float2 o; o.x = sums[2*j]*inv; o.y = sums[2*j+1]*inv;
            *(float2*)(ob + 2*(g + 128*j)) = o;
        }
    }
}

// ================= positional MLP ===========================================
__global__ __launch_bounds__(256) void k_pos(const float* __restrict__ cent,
        const float* __restrict__ w1, const float* __restrict__ b1,
        const float* __restrict__ w2, const float* __restrict__ b2,
        float* __restrict__ out){
    __shared__ __align__(8) float h2[384*16];
    int tid = threadIdx.x;
    int rb = blockIdx.x * 16;
    for (int lin = tid; lin < 6144; lin += 256){
        int j = lin >> 4, r = lin & 15;
        int rid = rb + r;
        float c0 = cent[rid*2+0] * (1.f/223.f);
        float c1 = cent[rid*2+1] * (1.f/223.f);
        float h = fmaxf(fmaf(c0, w1[j], fmaf(c1, w1[384+j], b1[j])), 0.f);
        h2[j*16 + r] = h;
    }
    __syncthreads();
    ull acc[3][8];
#pragma unroll
    for (int es = 0; es < 3; es++)
#pragma unroll
    for (int q = 0; q < 8; q++) acc[es][q] = 0ULL;
    for (int j = 0; j < 384; j++){
        ull hp[8];
#pragma unroll
        for (int q = 0; q < 8; q++) hp[q] = *(const ull*)&h2[j*16 + 2*q];
#pragma unroll
        for (int es = 0; es < 3; es++){
            float wv = w2[j*768 + tid + es*256];
            ull wp = pack2(wv, wv);
#pragma unroll
            for (int q = 0; q < 8; q++) ffma2(acc[es][q], hp[q], wp);
        }
    }
#pragma unroll
    for (int es = 0; es < 3; es++){
        int e = tid + es*256;
        float bv = b2[e];
#pragma unroll
        for (int q = 0; q < 8; q++){
            float2 v = unpack2(acc[es][q]);
            int rid = rb + 2*q;
            out[(size_t)rid*768 + e]     = v.x + bv;
            out[(size_t)(rid+1)*768 + e] = v.y + bv;
        }
    }
}

// ================= launcher =================================================
extern "C" void kernel_launch(void* const* d_in, const int* in_sizes, int n_in,
                              void* d_out, int out_size){
    const float* img  = (const float*)d_in[0];
    const int*   seg  = (const int*)d_in[1];
    const float* cent = (const float*)d_in[2];
    const float* w1   = (const float*)d_in[3];
    const float* w2   = (const float*)d_in[4];
    const float* w3   = (const float*)d_in[5];
    const float* pw1  = (const float*)d_in[6];
    const float* pb1  = (const float*)d_in[7];
    const float* pw2  = (const float*)d_in[8];
    const float* pb2  = (const float*)d_in[9];
    float* out = (float*)d_out;

    cudaFuncSetAttribute(k_conv3pool,
                         cudaFuncAttributeMaxDynamicSharedMemorySize, C3_SMEM);

    k_zero<<<1, 1024>>>();
    k_conv1<<<dim3(196,4), 256>>>(img, w1);
    k_conv2<<<dim3(7,28,4), 256>>>(w2);
    k_hist<<<dim3(49,4), 256>>>(seg);
    k_scan<<<1, 1024>>>();
    k_scatter<<<dim3(196,4), 256>>>(seg);
    k_conv3pool<<<BB*SS, 256, C3_SMEM>>>(w3, out);
    k_pos<<<64, 256>>>(cent, pw1, pb1, pw2, pb2, out + (size_t)BB*SS*EE);
}

// round 7
// speedup vs baseline: 3.1038x; 1.7611x over previous
#include <cuda_runtime.h>
#include <cuda_fp16.h>
#include <cstdint>

typedef unsigned long long ull;

#define BB 4
#define HH 224
#define WL 224
#define HW 50176
#define NC 64
#define EE 768
#define SS 256

// ---- scratch ----
__device__ float g_buf1[BB*NC*HW];   // conv1 output (planar)
__device__ float g_buf2[BB*NC*HW];   // conv2 output (PIXEL-MAJOR: [b][pix][ci])
__device__ int   g_cnt[BB*SS];
__device__ int   g_off[BB*SS];
__device__ int   g_cur[BB*SS];
__device__ int   g_order[BB*HW];

// ---- packed fp32x2 helpers ----
__device__ __forceinline__ ull pack2(float a, float b){
    ull d; asm("mov.b64 %0,{%1,%2};" : "=l"(d) : "f"(a), "f"(b)); return d;
}
__device__ __forceinline__ void ffma2(ull& d, ull a, ull b){
    asm("fma.rn.f32x2 %0,%1,%2,%0;" : "+l"(d) : "l"(a), "l"(b));
}
__device__ __forceinline__ float2 unpack2(ull d){
    float2 f; asm("mov.b64 {%0,%1},%2;" : "=f"(f.x), "=f"(f.y) : "l"(d)); return f;
}

__device__ __forceinline__ uint32_t smem_u32(const void* p){
    uint32_t a;
    asm("{ .reg .u64 t; cvta.to.shared.u64 t, %1; cvt.u32.u64 %0, t; }" : "=r"(a) : "l"(p));
    return a;
}
__device__ __forceinline__ uint32_t sw128(uint32_t off){ return off ^ ((off >> 3) & 0x70); }

// ---- mma.sync fp16 helpers (sm_80 PTX, works on compute_100) ----
__device__ __forceinline__ void ldsm_x4(uint32_t* r, uint32_t a){
    asm volatile("ldmatrix.sync.aligned.m8n8.x4.shared.b16 {%0,%1,%2,%3}, [%4];"
        : "=r"(r[0]),"=r"(r[1]),"=r"(r[2]),"=r"(r[3]) : "r"(a));
}
__device__ __forceinline__ void ldsm_x2(uint32_t* r, uint32_t a){
    asm volatile("ldmatrix.sync.aligned.m8n8.x2.shared.b16 {%0,%1}, [%2];"
        : "=r"(r[0]),"=r"(r[1]) : "r"(a));
}
__device__ __forceinline__ void mma_fp16(float* d, const uint32_t* a, const uint32_t* b){
    asm volatile("mma.sync.aligned.m16n8k16.row.col.f32.f16.f16.f32 "
        "{%0,%1,%2,%3}, {%4,%5,%6,%7}, {%8,%9}, {%0,%1,%2,%3};"
        : "+f"(d[0]),"+f"(d[1]),"+f"(d[2]),"+f"(d[3])
        : "r"(a[0]),"r"(a[1]),"r"(a[2]),"r"(a[3]), "r"(b[0]),"r"(b[1]));
}

// ================= zero counters ============================================
__global__ void k_zero(){
    int t = threadIdx.x;
    g_cnt[t] = 0; g_cur[t] = 0;
}

// ================= conv1 ====================================================
__global__ __launch_bounds__(256) void k_conv1(const float* __restrict__ img,
                                               const float* __restrict__ w1){
    __shared__ float ws[64*27];
    int tid = threadIdx.x;
    for (int i = tid; i < 64*27; i += 256) ws[i] = w1[i];
    __syncthreads();
    int b = blockIdx.y;
    int p = blockIdx.x*256 + tid;
    int y = p / WL, x = p % WL;
    float v[27];
#pragma unroll
    for (int ci = 0; ci < 3; ci++)
#pragma unroll
    for (int ky = 0; ky < 3; ky++)
#pragma unroll
    for (int kx = 0; kx < 3; kx++){
        int yy = y + ky - 1, xx = x + kx - 1;
        float val = 0.f;
        if (yy >= 0 && yy < HH && xx >= 0 && xx < WL)
            val = img[(size_t)(b*3+ci)*HW + yy*WL + xx];
        v[ci*9 + ky*3 + kx] = val;
    }
#pragma unroll 4
    for (int co = 0; co < 64; co++){
        float a = 0.f;
#pragma unroll
        for (int t = 0; t < 27; t++) a = fmaf(ws[co*27+t], v[t], a);
        g_buf1[(size_t)(b*64+co)*HW + p] = fmaxf(a, 0.f);
    }
}

// ================= conv2 (writes PIXEL-MAJOR) ===============================
__global__ __launch_bounds__(256) void k_conv2(const float* __restrict__ w2){
    __shared__ float ins[8][10][35];
    __shared__ ull   wsh[8][9][64];
    int tid = threadIdx.x;
    int b  = blockIdx.z;
    int x0 = blockIdx.x*32, y0 = blockIdx.y*8;
    int cog = tid >> 5;
    int r   = tid & 31;
    int ty  = r >> 2;
    int xl0 = (r & 3) * 8;

    ull acc[8][4];
#pragma unroll
    for (int c = 0; c < 8; c++)
#pragma unroll
    for (int q = 0; q < 4; q++) acc[c][q] = 0ULL;

    for (int cc = 0; cc < 8; cc++){
        for (int lin = tid; lin < 2720; lin += 256){
            int ci = lin / 340, rem = lin % 340;
            int rr = rem / 34, ccol = rem % 34;
            int gy = y0 + rr - 1, gx = x0 + ccol - 1;
            float v = 0.f;
            if (gy >= 0 && gy < HH && gx >= 0 && gx < WL)
                v = g_buf1[(size_t)(b*64 + cc*8 + ci)*HW + gy*WL + gx];
            ins[ci][rr][ccol] = v;
        }
        for (int lin = tid; lin < 4608; lin += 256){
            int co = lin / 72, rem = lin % 72;
            int ci = rem / 9, k = rem % 9;
            float v = w2[co*576 + (cc*8+ci)*9 + k];
            wsh[ci][k][co] = pack2(v, v);
        }
        __syncthreads();
#pragma unroll 2
        for (int ci = 0; ci < 8; ci++){
#pragma unroll
            for (int ky = 0; ky < 3; ky++){
                float a[10];
#pragma unroll
                for (int m = 0; m < 10; m++) a[m] = ins[ci][ty+ky][xl0+m];
                ull P[9];
#pragma unroll
                for (int m = 0; m < 9; m++) P[m] = pack2(a[m], a[m+1]);
#pragma unroll
                for (int kx = 0; kx < 3; kx++){
#pragma unroll
                    for (int c = 0; c < 8; c++){
                        ull w = wsh[ci][ky*3+kx][cog*8+c];
                        ffma2(acc[c][0], P[kx+0], w);
                        ffma2(acc[c][1], P[kx+2], w);
                        ffma2(acc[c][2], P[kx+4], w);
                        ffma2(acc[c][3], P[kx+6], w);
                    }
                }
            }
        }
        __syncthreads();
    }
    int y = y0 + ty;
    size_t pixbase = (size_t)b*HW + (size_t)y*WL + x0 + xl0;
#pragma unroll
    for (int p = 0; p < 8; p++){
        float o[8];
#pragma unroll
        for (int c = 0; c < 8; c++){
            float2 v = unpack2(acc[c][p>>1]);
            o[c] = fmaxf((p & 1) ? v.y : v.x, 0.f);
        }
        float* dst = &g_buf2[(pixbase + p)*64 + cog*8];
        *(float4*)(dst)   = make_float4(o[0], o[1], o[2], o[3]);
        *(float4*)(dst+4) = make_float4(o[4], o[5], o[6], o[7]);
    }
}

// ================= segment counting sort ====================================
__global__ __launch_bounds__(256) void k_hist(const int* __restrict__ seg){
    __shared__ int hist[SS];
    int tid = threadIdx.x;
    hist[tid] = 0;
    __syncthreads();
    int b = blockIdx.y;
    int base = blockIdx.x * 1024;
#pragma unroll
    for (int i = 0; i < 4; i++){
        int s = seg[(size_t)b*HW + base + i*256 + tid];
        atomicAdd(&hist[s], 1);
    }
    __syncthreads();
    atomicAdd(&g_cnt[b*SS + tid], hist[tid]);
}

__global__ void k_scan(){
    __shared__ int s[1024];
    int t = threadIdx.x;
    int v = g_cnt[t];
    s[t] = v;
    __syncthreads();
    for (int d = 1; d < 1024; d <<= 1){
        int add = (t >= d) ? s[t-d] : 0;
        __syncthreads();
        s[t] += add;
        __syncthreads();
    }
    g_off[t] = s[t] - v;
}

__global__ __launch_bounds__(256) void k_scatter(const int* __restrict__ seg){
    int b = blockIdx.y;
    int p = blockIdx.x*256 + threadIdx.x;
    int sgm = seg[(size_t)b*HW + p];
    int bin = b*SS + sgm;
    int idx = atomicAdd(&g_cur[bin], 1);
    g_order[g_off[bin] + idx] = p;
}

// ================= conv3+pool via mma.sync fp16 =============================
// One CTA per bin (1024 CTAs). W[768,64]->fp16 smem (96KB, SW128), feature
// blocks of 128 px -> fp16 smem (16KB). Warp w owns e in [96w, 96w+96):
// 6 m-tiles x 16 n-tiles(px) x 4 k-steps of mma.m16n8k16 f32.f16.f16.f32.
// D-frags relu'd and folded into 12 per-lane register accumulators; final
// shfl-xor(1,2) reduce -> direct out write. Mean error averages down ~28x
// over ~784 px (post-relu sums are positive), so fp16 keeps rel_err ~3e-5.
#define W_OFF 0
#define F_OFF 98304
#define C3_SMEM 114688
__global__ __launch_bounds__(256, 2) void k_conv3pool(const float* __restrict__ w3,
                                                      float* __restrict__ out){
    extern __shared__ __align__(1024) char sm[];
    int tid  = threadIdx.x;
    int wid  = tid >> 5;
    int lane = tid & 31;
    int bin  = blockIdx.x;
    int b    = bin >> 8;
    int npix = g_cnt[bin];
    int off  = g_off[bin];
    const float* featb = g_buf2 + ((size_t)b*HW)*64;
    uint32_t sbase = smem_u32(sm);

    // ---- stage W: rows e = tid, tid+256, tid+512 ----
#pragma unroll
    for (int rr = 0; rr < 3; rr++){
        int e = tid + rr*256;
        const float4* wrow = (const float4*)(w3 + (size_t)e*64);
#pragma unroll
        for (int k = 0; k < 16; k++){
            float4 f4 = wrow[k];
            __half2 h0 = __float22half2_rn(make_float2(f4.x, f4.y));
            __half2 h1 = __float22half2_rn(make_float2(f4.z, f4.w));
            uint2 u; u.x = *(uint32_t*)&h0; u.y = *(uint32_t*)&h1;
            *(uint2*)(sm + W_OFF + sw128((uint32_t)(e*128 + k*8))) = u;
        }
    }

    // per-lane ldmatrix address components
    int rowA = lane & 15, chA = lane >> 4;          // A: W rows
    int rowB = lane & 7,  chB = (lane >> 3) & 1;    // B: px rows (lanes 0-15 used)

    float acc[6][2];
#pragma unroll
    for (int i = 0; i < 6; i++){ acc[i][0] = 0.f; acc[i][1] = 0.f; }

    int ntiles = (npix + 127) >> 7;
    int r  = tid >> 1;          // staging: px row
    int h  = tid & 1;           // staging: ci half
    int ci0 = h*32;

    for (int t = 0; t < ntiles; t++){
        // ---- stage features: 128 px x 64 ci -> fp16 ----
        {
            int idx = t*128 + r;
            if (idx < npix){
                int pix = g_order[off + idx];
                const float4* fp = (const float4*)(featb + (size_t)pix*64 + ci0);
#pragma unroll
                for (int k = 0; k < 8; k++){
                    float4 f4 = fp[k];
                    __half2 h0 = __float22half2_rn(make_float2(f4.x, f4.y));
                    __half2 h1 = __float22half2_rn(make_float2(f4.z, f4.w));
                    uint2 u; u.x = *(uint32_t*)&h0; u.y = *(uint32_t*)&h1;
                    *(uint2*)(sm + F_OFF + sw128((uint32_t)(r*128 + (ci0 + k*4)*2))) = u;
                }
            } else {
                uint2 z; z.x = 0u; z.y = 0u;
#pragma unroll
                for (int k = 0; k < 8; k++)
                    *(uint2*)(sm + F_OFF + sw128((uint32_t)(r*128 + (ci0 + k*4)*2))) = z;
            }
        }
        __syncthreads();

#pragma unroll 1
        for (int ntc = 0; ntc < 4; ntc++){
            // load B frags: 4 n-tiles x 4 k-steps
            uint32_t bf[4][4][2];
#pragma unroll
            for (int j = 0; j < 4; j++){
                int px = (ntc*4 + j)*8 + rowB;
#pragma unroll
                for (int kt = 0; kt < 4; kt++){
                    uint32_t a = sbase + F_OFF + sw128((uint32_t)(px*128 + kt*32 + chB*16));
                    ldsm_x2(bf[j][kt], a);
                }
            }
#pragma unroll 1
            for (int i = 0; i < 6; i++){
                int e0 = (wid*6 + i)*16;
                uint32_t af[4][4];
#pragma unroll
                for (int kt = 0; kt < 4; kt++){
                    uint32_t a = sbase + W_OFF + sw128((uint32_t)((e0 + rowA)*128 + kt*32 + chA*16));
                    ldsm_x4(af[kt], a);
                }
                float d[4][4];
#pragma unroll
                for (int j = 0; j < 4; j++)
#pragma unroll
                for (int q = 0; q < 4; q++) d[j][q] = 0.f;
#pragma unroll
                for (int kt = 0; kt < 4; kt++)
#pragma unroll
                for (int j = 0; j < 4; j++)
                    mma_fp16(d[j], af[kt], bf[j][kt]);
                // fold: relu per (e,px), accumulate over px
#pragma unroll
                for (int j = 0; j < 4; j++){
                    acc[i][0] += fmaxf(d[j][0], 0.f) + fmaxf(d[j][1], 0.f);
                    acc[i][1] += fmaxf(d[j][2], 0.f) + fmaxf(d[j][3], 0.f);
                }
            }
        }
        __syncthreads();
    }

    // ---- reduce across the 4 lanes sharing an e-row, write mean ----
    float inv = 1.f / (float)max(npix, 1);
#pragma unroll
    for (int i = 0; i < 6; i++){
        acc[i][0] += __shfl_xor_sync(0xffffffffu, acc[i][0], 1);
        acc[i][0] += __shfl_xor_sync(0xffffffffu, acc[i][0], 2);
        acc[i][1] += __shfl_xor_sync(0xffffffffu, acc[i][1], 1);
        acc[i][1] += __shfl_xor_sync(0xffffffffu, acc[i][1], 2);
    }
    if ((lane & 3) == 0){
        int row = lane >> 2;
        float* ob = out + (size_t)bin*EE;
#pragma unroll
        for (int i = 0; i < 6; i++){
            int e = (wid*6 + i)*16 + row;
            ob[e]     = acc[i][0] * inv;
            ob[e + 8] = acc[i][1] * inv;
        }
    }
}

// ================= positional MLP ===========================================
__global__ __launch_bounds__(256) void k_pos(const float* __restrict__ cent,
        const float* __restrict__ w1, const float* __restrict__ b1,
        const float* __restrict__ w2, const float* __restrict__ b2,
        float* __restrict__ out){
    __shared__ __align__(8) float h2[384*16];
    int tid = threadIdx.x;
    int rb = blockIdx.x * 16;
    for (int lin = tid; lin < 6144; lin += 256){
        int j = lin >> 4, r = lin & 15;
        int rid = rb + r;
        float c0 = cent[rid*2+0] * (1.f/223.f);
        float c1 = cent[rid*2+1] * (1.f/223.f);
        float h = fmaxf(fmaf(c0, w1[j], fmaf(c1, w1[384+j], b1[j])), 0.f);
        h2[j*16 + r] = h;
    }
    __syncthreads();
    ull acc[3][8];
#pragma unroll
    for (int es = 0; es < 3; es++)
#pragma unroll
    for (int q = 0; q < 8; q++) acc[es][q] = 0ULL;
    for (int j = 0; j < 384; j++){
        ull hp[8];
#pragma unroll
        for (int q = 0; q < 8; q++) hp[q] = *(const ull*)&h2[j*16 + 2*q];
#pragma unroll
        for (int es = 0; es < 3; es++){
            float wv = w2[j*768 + tid + es*256];
            ull wp = pack2(wv, wv);
#pragma unroll
            for (int q = 0; q < 8; q++) ffma2(acc[es][q], hp[q], wp);
        }
    }
#pragma unroll
    for (int es = 0; es < 3; es++){
        int e = tid + es*256;
        float bv = b2[e];
#pragma unroll
        for (int q = 0; q < 8; q++){
            float2 v = unpack2(acc[es][q]);
            int rid = rb + 2*q;
            out[(size_t)rid*768 + e]     = v.x + bv;
            out[(size_t)(rid+1)*768 + e] = v.y + bv;
        }
    }
}

// ================= launcher =================================================
extern "C" void kernel_launch(void* const* d_in, const int* in_sizes, int n_in,
                              void* d_out, int out_size){
    const float* img  = (const float*)d_in[0];
    const int*   seg  = (const int*)d_in[1];
    const float* cent = (const float*)d_in[2];
    const float* w1   = (const float*)d_in[3];
    const float* w2   = (const float*)d_in[4];
    const float* w3   = (const float*)d_in[5];
    const float* pw1  = (const float*)d_in[6];
    const float* pb1  = (const float*)d_in[7];
    const float* pw2  = (const float*)d_in[8];
    const float* pb2  = (const float*)d_in[9];
    float* out = (float*)d_out;

    cudaFuncSetAttribute(k_conv3pool,
                         cudaFuncAttributeMaxDynamicSharedMemorySize, C3_SMEM);

    k_zero<<<1, 1024>>>();
    k_conv1<<<dim3(196,4), 256>>>(img, w1);
    k_conv2<<<dim3(7,28,4), 256>>>(w2);
    k_hist<<<dim3(49,4), 256>>>(seg);
    k_scan<<<1, 1024>>>();
    k_scatter<<<dim3(196,4), 256>>>(seg);
    k_conv3pool<<<BB*SS, 256, C3_SMEM>>>(w3, out);
    k_pos<<<64, 256>>>(cent, pw1, pb1, pw2, pb2, out + (size_t)BB*SS*EE);
}

// round 8
// speedup vs baseline: 6.2318x; 2.0078x over previous
#include <cuda_runtime.h>
#include <cuda_fp16.h>
#include <cstdint>

typedef unsigned long long ull;

#define BB 4
#define HH 224
#define WL 224
#define HW 50176
#define NC 64
#define EE 768
#define SS 256

// ---- scratch ----
__device__ __half g_h1[BB*HW*64];    // conv1 output, PIXEL-MAJOR fp16 [b][pix][ci]
__device__ __half g_h2[BB*HW*64];    // conv2 output, PIXEL-MAJOR fp16 [b][pix][ci]
__device__ int   g_cnt[BB*SS];
__device__ int   g_off[BB*SS];
__device__ int   g_cur[BB*SS];
__device__ int   g_order[BB*HW];

// ---- packed fp32x2 helpers ----
__device__ __forceinline__ ull pack2(float a, float b){
    ull d; asm("mov.b64 %0,{%1,%2};" : "=l"(d) : "f"(a), "f"(b)); return d;
}
__device__ __forceinline__ void ffma2(ull& d, ull a, ull b){
    asm("fma.rn.f32x2 %0,%1,%2,%0;" : "+l"(d) : "l"(a), "l"(b));
}
__device__ __forceinline__ float2 unpack2(ull d){
    float2 f; asm("mov.b64 {%0,%1},%2;" : "=f"(f.x), "=f"(f.y) : "l"(d)); return f;
}

__device__ __forceinline__ uint32_t smem_u32(const void* p){
    uint32_t a;
    asm("{ .reg .u64 t; cvta.to.shared.u64 t, %1; cvt.u32.u64 %0, t; }" : "=r"(a) : "l"(p));
    return a;
}
__device__ __forceinline__ uint32_t sw128(uint32_t off){ return off ^ ((off >> 3) & 0x70); }

// ---- mma.sync fp16 helpers (sm_80 PTX, works on compute_100) ----
__device__ __forceinline__ void ldsm_x4(uint32_t* r, uint32_t a){
    asm volatile("ldmatrix.sync.aligned.m8n8.x4.shared.b16 {%0,%1,%2,%3}, [%4];"
        : "=r"(r[0]),"=r"(r[1]),"=r"(r[2]),"=r"(r[3]) : "r"(a));
}
__device__ __forceinline__ void ldsm_x2(uint32_t* r, uint32_t a){
    asm volatile("ldmatrix.sync.aligned.m8n8.x2.shared.b16 {%0,%1}, [%2];"
        : "=r"(r[0]),"=r"(r[1]) : "r"(a));
}
__device__ __forceinline__ void mma_fp16(float* d, const uint32_t* a, const uint32_t* b){
    asm volatile("mma.sync.aligned.m16n8k16.row.col.f32.f16.f16.f32 "
        "{%0,%1,%2,%3}, {%4,%5,%6,%7}, {%8,%9}, {%0,%1,%2,%3};"
        : "+f"(d[0]),"+f"(d[1]),"+f"(d[2]),"+f"(d[3])
        : "r"(a[0]),"r"(a[1]),"r"(a[2]),"r"(a[3]), "r"(b[0]),"r"(b[1]));
}

// ================= zero counters ============================================
__global__ void k_zero(){
    int t = threadIdx.x;
    g_cnt[t] = 0; g_cur[t] = 0;
}

// ================= conv1: 3->64 3x3 relu, writes fp16 pixel-major ===========
__global__ __launch_bounds__(256) void k_conv1(const float* __restrict__ img,
                                               const float* __restrict__ w1){
    __shared__ float ws[64*27];
    int tid = threadIdx.x;
    for (int i = tid; i < 64*27; i += 256) ws[i] = w1[i];
    __syncthreads();
    int b = blockIdx.y;
    int p = blockIdx.x*256 + tid;
    int y = p / WL, x = p % WL;
    float v[27];
#pragma unroll
    for (int ci = 0; ci < 3; ci++)
#pragma unroll
    for (int ky = 0; ky < 3; ky++)
#pragma unroll
    for (int kx = 0; kx < 3; kx++){
        int yy = y + ky - 1, xx = x + kx - 1;
        float val = 0.f;
        if (yy >= 0 && yy < HH && xx >= 0 && xx < WL)
            val = img[(size_t)(b*3+ci)*HW + yy*WL + xx];
        v[ci*9 + ky*3 + kx] = val;
    }
    uint32_t pk[32];
#pragma unroll 4
    for (int cp = 0; cp < 32; cp++){
        float a0 = 0.f, a1 = 0.f;
#pragma unroll
        for (int t = 0; t < 27; t++){
            a0 = fmaf(ws[(2*cp)*27+t],   v[t], a0);
            a1 = fmaf(ws[(2*cp+1)*27+t], v[t], a1);
        }
        __half2 h = __floats2half2_rn(fmaxf(a0,0.f), fmaxf(a1,0.f));
        pk[cp] = *(uint32_t*)&h;
    }
    uint4* dst = (uint4*)(g_h1 + ((size_t)b*HW + p)*64);
#pragma unroll
    for (int j = 0; j < 8; j++)
        dst[j] = make_uint4(pk[4*j], pk[4*j+1], pk[4*j+2], pk[4*j+3]);
}

// ================= conv2 via mma.sync fp16 (split weights) ==================
// Tap decomposition: out[px][co] = sum over 9 shifts of X_shift[px][ci]*W_k[ci][co].
// A = pixels (fp16, pixel-major rows, 128B), B = weights (hi/lo split -> 18
// passes == fp32-exact weights). CTA = 16y x 32x tile, 8 warps; warp owns
// output row ty = half*8+wid, 2 m-tiles of 16 px. acc f32, relu, fp16 out.
#define C2_WS 0
#define C2_FS 147456
#define C2_SMEM 225792
__global__ __launch_bounds__(256) void k_conv2(const float* __restrict__ w2){
    extern __shared__ __align__(1024) char sm[];
    uint32_t sb = smem_u32(sm);
    int tid = threadIdx.x, wid = tid>>5, lane = tid&31;
    int b = blockIdx.z;
    int x0 = blockIdx.x*32, y0 = blockIdx.y*16;
    const __half* src = g_h1 + (size_t)b*HW*64;
    __half* dsth = g_h2 + (size_t)b*HW*64;

    // stage split weights: pass k (0-8)=hi, (9-17)=lo; [pass][co][ci] 128B rows
    for (int lin = tid; lin < 9*64*32; lin += 256){
        int k = lin >> 11;
        int rem = lin & 2047;
        int co = rem >> 5, cp = rem & 31;
        float v0 = w2[co*576 + (2*cp)*9 + k];
        float v1 = w2[co*576 + (2*cp+1)*9 + k];
        __half h0 = __float2half_rn(v0), h1 = __float2half_rn(v1);
        __half l0 = __float2half_rn(v0 - __half2float(h0));
        __half l1 = __float2half_rn(v1 - __half2float(h1));
        __half2 hh = __halves2half2(h0, h1), llh = __halves2half2(l0, l1);
        uint32_t o = sw128((uint32_t)(co*128 + cp*4));
        *(uint32_t*)(sm + C2_WS + k*8192 + o)     = *(uint32_t*)&hh;
        *(uint32_t*)(sm + C2_WS + (9+k)*8192 + o) = *(uint32_t*)&llh;
    }
    // stage features: 18 rows x 34 px halo, 128B per pixel
    for (int lin = tid; lin < 612*8; lin += 256){
        int slot = lin >> 3, part = lin & 7;
        int gy = y0 + slot/34 - 1, gx = x0 + (slot%34) - 1;
        uint4 v = make_uint4(0,0,0,0);
        if (gy >= 0 && gy < HH && gx >= 0 && gx < WL)
            v = *(const uint4*)(src + ((size_t)gy*WL + gx)*64 + part*8);
        *(uint4*)(sm + C2_FS + sw128((uint32_t)(slot*128 + part*16))) = v;
    }
    __syncthreads();

    int rowA = lane & 15, chA = lane >> 4;
    int rowB8 = lane & 7, chB = (lane>>3)&1, grpB = lane>>4;

#pragma unroll 1
    for (int half = 0; half < 2; half++){
        float acc[2][8][4];
#pragma unroll
        for (int mx = 0; mx < 2; mx++)
#pragma unroll
        for (int nt = 0; nt < 8; nt++)
#pragma unroll
        for (int q = 0; q < 4; q++) acc[mx][nt][q] = 0.f;

        int ty = half*8 + wid;
#pragma unroll 1
        for (int pass = 0; pass < 18; pass++){
            int k9 = (pass < 9) ? pass : pass - 9;
            int ky = k9 / 3, kx = k9 - ky*3;
            uint32_t wbase = sb + C2_WS + pass*8192;
            uint32_t bf[8][4][2];
#pragma unroll
            for (int kt = 0; kt < 4; kt++)
#pragma unroll
            for (int ntp = 0; ntp < 4; ntp++){
                uint32_t r[4];
                uint32_t a = wbase + sw128((uint32_t)(((ntp*2 + grpB)*8 + rowB8)*128 + kt*32 + chB*16));
                ldsm_x4(r, a);
                bf[2*ntp][kt][0]   = r[0]; bf[2*ntp][kt][1]   = r[1];
                bf[2*ntp+1][kt][0] = r[2]; bf[2*ntp+1][kt][1] = r[3];
            }
#pragma unroll
            for (int mx = 0; mx < 2; mx++){
                int slot = (ty + ky)*34 + mx*16 + rowA + kx;
                uint32_t af[4][4];
#pragma unroll
                for (int kt = 0; kt < 4; kt++)
                    ldsm_x4(af[kt], sb + C2_FS + sw128((uint32_t)(slot*128 + kt*32 + chA*16)));
#pragma unroll
                for (int nt = 0; nt < 8; nt++)
#pragma unroll
                for (int kt = 0; kt < 4; kt++)
                    mma_fp16(acc[mx][nt], af[kt], bf[nt][kt]);
            }
        }
        // epilogue: relu -> fp16 pixel-major
        int gy = y0 + ty;
#pragma unroll
        for (int mx = 0; mx < 2; mx++){
            int px = x0 + mx*16 + (lane>>2);
            size_t base0 = ((size_t)gy*WL + px)*64;
            size_t base1 = ((size_t)gy*WL + px + 8)*64;
#pragma unroll
            for (int nt = 0; nt < 8; nt++){
                int co = nt*8 + (lane&3)*2;
                __half2 u0 = __floats2half2_rn(fmaxf(acc[mx][nt][0],0.f), fmaxf(acc[mx][nt][1],0.f));
                __half2 u1 = __floats2half2_rn(fmaxf(acc[mx][nt][2],0.f), fmaxf(acc[mx][nt][3],0.f));
                *(uint32_t*)(dsth + base0 + co) = *(uint32_t*)&u0;
                *(uint32_t*)(dsth + base1 + co) = *(uint32_t*)&u1;
            }
        }
    }
}

// ================= segment counting sort ====================================
__global__ __launch_bounds__(256) void k_hist(const int* __restrict__ seg){
    __shared__ int hist[SS];
    int tid = threadIdx.x;
    hist[tid] = 0;
    __syncthreads();
    int b = blockIdx.y;
    int base = blockIdx.x * 1024;
#pragma unroll
    for (int i = 0; i < 4; i++){
        int s = seg[(size_t)b*HW + base + i*256 + tid];
        atomicAdd(&hist[s], 1);
    }
    __syncthreads();
    atomicAdd(&g_cnt[b*SS + tid], hist[tid]);
}

__global__ void k_scan(){
    __shared__ int s[1024];
    int t = threadIdx.x;
    int v = g_cnt[t];
    s[t] = v;
    __syncthreads();
    for (int d = 1; d < 1024; d <<= 1){
        int add = (t >= d) ? s[t-d] : 0;
        __syncthreads();
        s[t] += add;
        __syncthreads();
    }
    g_off[t] = s[t] - v;
}

__global__ __launch_bounds__(256) void k_scatter(const int* __restrict__ seg){
    int b = blockIdx.y;
    int p = blockIdx.x*256 + threadIdx.x;
    int sgm = seg[(size_t)b*HW + p];
    int bin = b*SS + sgm;
    int idx = atomicAdd(&g_cur[bin], 1);
    g_order[g_off[bin] + idx] = p;
}

// ================= conv3+pool via mma.sync fp16 =============================
#define W_OFF 0
#define F_OFF 98304
#define C3_SMEM 114688
__global__ __launch_bounds__(256, 2) void k_conv3pool(const float* __restrict__ w3,
                                                      float* __restrict__ out){
    extern __shared__ __align__(1024) char sm[];
    int tid  = threadIdx.x;
    int wid  = tid >> 5;
    int lane = tid & 31;
    int bin  = blockIdx.x;
    int b    = bin >> 8;
    int npix = g_cnt[bin];
    int off  = g_off[bin];
    const __half* featb = g_h2 + (size_t)b*HW*64;
    uint32_t sbase = smem_u32(sm);

    // ---- stage W: rows e = tid, tid+256, tid+512 ----
#pragma unroll
    for (int rr = 0; rr < 3; rr++){
        int e = tid + rr*256;
        const float4* wrow = (const float4*)(w3 + (size_t)e*64);
#pragma unroll
        for (int k = 0; k < 16; k++){
            float4 f4 = wrow[k];
            __half2 h0 = __float22half2_rn(make_float2(f4.x, f4.y));
            __half2 h1 = __float22half2_rn(make_float2(f4.z, f4.w));
            uint2 u; u.x = *(uint32_t*)&h0; u.y = *(uint32_t*)&h1;
            *(uint2*)(sm + W_OFF + sw128((uint32_t)(e*128 + k*8))) = u;
        }
    }

    int rowA = lane & 15, chA = lane >> 4;
    int rowB = lane & 7,  chB = (lane >> 3) & 1;

    float acc[6][2];
#pragma unroll
    for (int i = 0; i < 6; i++){ acc[i][0] = 0.f; acc[i][1] = 0.f; }

    int ntiles = (npix + 127) >> 7;
    int r  = tid >> 1;
    int h  = tid & 1;

    for (int t = 0; t < ntiles; t++){
        // ---- stage features: pure fp16 copy, 64B per thread ----
        {
            int idx = t*128 + r;
            if (idx < npix){
                int pix = g_order[off + idx];
                const uint4* fp = (const uint4*)(featb + (size_t)pix*64 + h*32);
#pragma unroll
                for (int j = 0; j < 4; j++)
                    *(uint4*)(sm + F_OFF + sw128((uint32_t)(r*128 + h*64 + j*16))) = fp[j];
            } else {
                uint4 z = make_uint4(0,0,0,0);
#pragma unroll
                for (int j = 0; j < 4; j++)
                    *(uint4*)(sm + F_OFF + sw128((uint32_t)(r*128 + h*64 + j*16))) = z;
            }
        }
        __syncthreads();

#pragma unroll 1
        for (int ntc = 0; ntc < 4; ntc++){
            uint32_t bf[4][4][2];
#pragma unroll
            for (int j = 0; j < 4; j++){
                int px = (ntc*4 + j)*8 + rowB;
#pragma unroll
                for (int kt = 0; kt < 4; kt++){
                    uint32_t a = sbase + F_OFF + sw128((uint32_t)(px*128 + kt*32 + chB*16));
                    ldsm_x2(bf[j][kt], a);
                }
            }
#pragma unroll 1
            for (int i = 0; i < 6; i++){
                int e0 = (wid*6 + i)*16;
                uint32_t af[4][4];
#pragma unroll
                for (int kt = 0; kt < 4; kt++){
                    uint32_t a = sbase + W_OFF + sw128((uint32_t)((e0 + rowA)*128 + kt*32 + chA*16));
                    ldsm_x4(af[kt], a);
                }
                float d[4][4];
#pragma unroll
                for (int j = 0; j < 4; j++)
#pragma unroll
                for (int q = 0; q < 4; q++) d[j][q] = 0.f;
#pragma unroll
                for (int kt = 0; kt < 4; kt++)
#pragma unroll
                for (int j = 0; j < 4; j++)
                    mma_fp16(d[j], af[kt], bf[j][kt]);
#pragma unroll
                for (int j = 0; j < 4; j++){
                    acc[i][0] += fmaxf(d[j][0], 0.f) + fmaxf(d[j][1], 0.f);
                    acc[i][1] += fmaxf(d[j][2], 0.f) + fmaxf(d[j][3], 0.f);
                }
            }
        }
        __syncthreads();
    }

    float inv = 1.f / (float)max(npix, 1);
#pragma unroll
    for (int i = 0; i < 6; i++){
        acc[i][0] += __shfl_xor_sync(0xffffffffu, acc[i][0], 1);
        acc[i][0] += __shfl_xor_sync(0xffffffffu, acc[i][0], 2);
        acc[i][1] += __shfl_xor_sync(0xffffffffu, acc[i][1], 1);
        acc[i][1] += __shfl_xor_sync(0xffffffffu, acc[i][1], 2);
    }
    if ((lane & 3) == 0){
        int row = lane >> 2;
        float* ob = out + (size_t)bin*EE;
#pragma unroll
        for (int i = 0; i < 6; i++){
            int e = (wid*6 + i)*16 + row;
            ob[e]     = acc[i][0] * inv;
            ob[e + 8] = acc[i][1] * inv;
        }
    }
}

// ================= positional MLP ===========================================
__global__ __launch_bounds__(256) void k_pos(const float* __restrict__ cent,
        const float* __restrict__ w1, const float* __restrict__ b1,
        const float* __restrict__ w2, const float* __restrict__ b2,
        float* __restrict__ out){
    __shared__ __align__(8) float h2[384*16];
    int tid = threadIdx.x;
    int rb = blockIdx.x * 16;
    for (int lin = tid; lin < 6144; lin += 256){
        int j = lin >> 4, r = lin & 15;
        int rid = rb + r;
        float c0 = cent[rid*2+0] * (1.f/223.f);
        float c1 = cent[rid*2+1] * (1.f/223.f);
        float h = fmaxf(fmaf(c0, w1[j], fmaf(c1, w1[384+j], b1[j])), 0.f);
        h2[j*16 + r] = h;
    }
    __syncthreads();
    ull acc[3][8];
#pragma unroll
    for (int es = 0; es < 3; es++)
#pragma unroll
    for (int q = 0; q < 8; q++) acc[es][q] = 0ULL;
    for (int j = 0; j < 384; j++){
        ull hp[8];
#pragma unroll
        for (int q = 0; q < 8; q++) hp[q] = *(const ull*)&h2[j*16 + 2*q];
#pragma unroll
        for (int es = 0; es < 3; es++){
            float wv = w2[j*768 + tid + es*256];
            ull wp = pack2(wv, wv);
#pragma unroll
            for (int q = 0; q < 8; q++) ffma2(acc[es][q], hp[q], wp);
        }
    }
#pragma unroll
    for (int es = 0; es < 3; es++){
        int e = tid + es*256;
        float bv = b2[e];
#pragma unroll
        for (int q = 0; q < 8; q++){
            float2 v = unpack2(acc[es][q]);
            int rid = rb + 2*q;
            out[(size_t)rid*768 + e]     = v.x + bv;
            out[(size_t)(rid+1)*768 + e] = v.y + bv;
        }
    }
}

// ================= launcher =================================================
extern "C" void kernel_launch(void* const* d_in, const int* in_sizes, int n_in,
                              void* d_out, int out_size){
    const float* img  = (const float*)d_in[0];
    const int*   seg  = (const int*)d_in[1];
    const float* cent = (const float*)d_in[2];
    const float* w1   = (const float*)d_in[3];
    const float* w2   = (const float*)d_in[4];
    const float* w3   = (const float*)d_in[5];
    const float* pw1  = (const float*)d_in[6];
    const float* pb1  = (const float*)d_in[7];
    const float* pw2  = (const float*)d_in[8];
    const float* pb2  = (const float*)d_in[9];
    float* out = (float*)d_out;

    cudaFuncSetAttribute(k_conv2,
                         cudaFuncAttributeMaxDynamicSharedMemorySize, C2_SMEM);
    cudaFuncSetAttribute(k_conv3pool,
                         cudaFuncAttributeMaxDynamicSharedMemorySize, C3_SMEM);

    k_zero<<<1, 1024>>>();
    k_conv1<<<dim3(196,4), 256>>>(img, w1);
    k_conv2<<<dim3(7,14,4), 256, C2_SMEM>>>(w2);
    k_hist<<<dim3(49,4), 256>>>(seg);
    k_scan<<<1, 1024>>>();
    k_scatter<<<dim3(196,4), 256>>>(seg);
    k_conv3pool<<<BB*SS, 256, C3_SMEM>>>(w3, out);
    k_pos<<<64, 256>>>(cent, pw1, pb1, pw2, pb2, out + (size_t)BB*SS*EE);
}

// round 9
// speedup vs baseline: 6.7869x; 1.0891x over previous
#include <cuda_runtime.h>
#include <cuda_fp16.h>
#include <cstdint>

typedef unsigned long long ull;

#define BB 4
#define HH 224
#define WL 224
#define HW 50176
#define NC 64
#define EE 768
#define SS 256

// ---- scratch ----
__device__ __half g_h1[BB*HW*64];    // conv1 output, PIXEL-MAJOR fp16 [b][pix][ci]
__device__ __half g_h2[BB*HW*64];    // conv2 output, PIXEL-MAJOR fp16 [b][pix][ci]
__device__ int   g_cnt[BB*SS];
__device__ int   g_off[BB*SS];
__device__ int   g_cur[BB*SS];
__device__ int   g_order[BB*HW];

// ---- packed fp32x2 helpers ----
__device__ __forceinline__ ull pack2(float a, float b){
    ull d; asm("mov.b64 %0,{%1,%2};" : "=l"(d) : "f"(a), "f"(b)); return d;
}
__device__ __forceinline__ void ffma2(ull& d, ull a, ull b){
    asm("fma.rn.f32x2 %0,%1,%2,%0;" : "+l"(d) : "l"(a), "l"(b));
}
__device__ __forceinline__ float2 unpack2(ull d){
    float2 f; asm("mov.b64 {%0,%1},%2;" : "=f"(f.x), "=f"(f.y) : "l"(d)); return f;
}

__device__ __forceinline__ uint32_t smem_u32(const void* p){
    uint32_t a;
    asm("{ .reg .u64 t; cvta.to.shared.u64 t, %1; cvt.u32.u64 %0, t; }" : "=r"(a) : "l"(p));
    return a;
}
__device__ __forceinline__ uint32_t sw128(uint32_t off){ return off ^ ((off >> 3) & 0x70); }

// ---- mma.sync fp16 helpers (sm_80 PTX, works on compute_100) ----
__device__ __forceinline__ void ldsm_x4(uint32_t* r, uint32_t a){
    asm volatile("ldmatrix.sync.aligned.m8n8.x4.shared.b16 {%0,%1,%2,%3}, [%4];"
        : "=r"(r[0]),"=r"(r[1]),"=r"(r[2]),"=r"(r[3]) : "r"(a));
}
__device__ __forceinline__ void ldsm_x2(uint32_t* r, uint32_t a){
    asm volatile("ldmatrix.sync.aligned.m8n8.x2.shared.b16 {%0,%1}, [%2];"
        : "=r"(r[0]),"=r"(r[1]) : "r"(a));
}
__device__ __forceinline__ void mma_fp16(float* d, const uint32_t* a, const uint32_t* b){
    asm volatile("mma.sync.aligned.m16n8k16.row.col.f32.f16.f16.f32 "
        "{%0,%1,%2,%3}, {%4,%5,%6,%7}, {%8,%9}, {%0,%1,%2,%3};"
        : "+f"(d[0]),"+f"(d[1]),"+f"(d[2]),"+f"(d[3])
        : "r"(a[0]),"r"(a[1]),"r"(a[2]),"r"(a[3]), "r"(b[0]),"r"(b[1]));
}

// ================= zero counters ============================================
__global__ void k_zero(){
    int t = threadIdx.x;
    g_cnt[t] = 0; g_cur[t] = 0;
}

// ================= conv1: 3->64 3x3 relu, writes fp16 pixel-major ===========
__global__ __launch_bounds__(256) void k_conv1(const float* __restrict__ img,
                                               const float* __restrict__ w1){
    __shared__ float ws[64*27];
    int tid = threadIdx.x;
    for (int i = tid; i < 64*27; i += 256) ws[i] = w1[i];
    __syncthreads();
    int b = blockIdx.y;
    int p = blockIdx.x*256 + tid;
    int y = p / WL, x = p % WL;
    float v[27];
#pragma unroll
    for (int ci = 0; ci < 3; ci++)
#pragma unroll
    for (int ky = 0; ky < 3; ky++)
#pragma unroll
    for (int kx = 0; kx < 3; kx++){
        int yy = y + ky - 1, xx = x + kx - 1;
        float val = 0.f;
        if (yy >= 0 && yy < HH && xx >= 0 && xx < WL)
            val = img[(size_t)(b*3+ci)*HW + yy*WL + xx];
        v[ci*9 + ky*3 + kx] = val;
    }
    uint32_t pk[32];
#pragma unroll 4
    for (int cp = 0; cp < 32; cp++){
        float a0 = 0.f, a1 = 0.f;
#pragma unroll
        for (int t = 0; t < 27; t++){
            a0 = fmaf(ws[(2*cp)*27+t],   v[t], a0);
            a1 = fmaf(ws[(2*cp+1)*27+t], v[t], a1);
        }
        __half2 h = __floats2half2_rn(fmaxf(a0,0.f), fmaxf(a1,0.f));
        pk[cp] = *(uint32_t*)&h;
    }
    uint4* dst = (uint4*)(g_h1 + ((size_t)b*HW + p)*64);
#pragma unroll
    for (int j = 0; j < 8; j++)
        dst[j] = make_uint4(pk[4*j], pk[4*j+1], pk[4*j+2], pk[4*j+3]);
}

// ================= conv2 via mma.sync fp16 (split weights) ==================
#define C2_WS 0
#define C2_FS 147456
#define C2_SMEM 225792
__global__ __launch_bounds__(256) void k_conv2(const float* __restrict__ w2){
    extern __shared__ __align__(1024) char sm[];
    uint32_t sb = smem_u32(sm);
    int tid = threadIdx.x, wid = tid>>5, lane = tid&31;
    int b = blockIdx.z;
    int x0 = blockIdx.x*32, y0 = blockIdx.y*16;
    const __half* src = g_h1 + (size_t)b*HW*64;
    __half* dsth = g_h2 + (size_t)b*HW*64;

    // stage split weights: pass k (0-8)=hi, (9-17)=lo; [pass][co][ci] 128B rows
    for (int lin = tid; lin < 9*64*32; lin += 256){
        int k = lin >> 11;
        int rem = lin & 2047;
        int co = rem >> 5, cp = rem & 31;
        float v0 = w2[co*576 + (2*cp)*9 + k];
        float v1 = w2[co*576 + (2*cp+1)*9 + k];
        __half h0 = __float2half_rn(v0), h1 = __float2half_rn(v1);
        __half l0 = __float2half_rn(v0 - __half2float(h0));
        __half l1 = __float2half_rn(v1 - __half2float(h1));
        __half2 hh = __halves2half2(h0, h1), llh = __halves2half2(l0, l1);
        uint32_t o = sw128((uint32_t)(co*128 + cp*4));
        *(uint32_t*)(sm + C2_WS + k*8192 + o)     = *(uint32_t*)&hh;
        *(uint32_t*)(sm + C2_WS + (9+k)*8192 + o) = *(uint32_t*)&llh;
    }
    // stage features: 18 rows x 34 px halo, 128B per pixel
    for (int lin = tid; lin < 612*8; lin += 256){
        int slot = lin >> 3, part = lin & 7;
        int gy = y0 + slot/34 - 1, gx = x0 + (slot%34) - 1;
        uint4 v = make_uint4(0,0,0,0);
        if (gy >= 0 && gy < HH && gx >= 0 && gx < WL)
            v = *(const uint4*)(src + ((size_t)gy*WL + gx)*64 + part*8);
        *(uint4*)(sm + C2_FS + sw128((uint32_t)(slot*128 + part*16))) = v;
    }
    __syncthreads();

    int rowA = lane & 15, chA = lane >> 4;
    int rowB8 = lane & 7, chB = (lane>>3)&1, grpB = lane>>4;

#pragma unroll 1
    for (int half = 0; half < 2; half++){
        float acc[2][8][4];
#pragma unroll
        for (int mx = 0; mx < 2; mx++)
#pragma unroll
        for (int nt = 0; nt < 8; nt++)
#pragma unroll
        for (int q = 0; q < 4; q++) acc[mx][nt][q] = 0.f;

        int ty = half*8 + wid;
#pragma unroll 1
        for (int pass = 0; pass < 18; pass++){
            int k9 = (pass < 9) ? pass : pass - 9;
            int ky = k9 / 3, kx = k9 - ky*3;
            uint32_t wbase = sb + C2_WS + pass*8192;
            uint32_t bf[8][4][2];
#pragma unroll
            for (int kt = 0; kt < 4; kt++)
#pragma unroll
            for (int ntp = 0; ntp < 4; ntp++){
                uint32_t r[4];
                uint32_t a = wbase + sw128((uint32_t)(((ntp*2 + grpB)*8 + rowB8)*128 + kt*32 + chB*16));
                ldsm_x4(r, a);
                bf[2*ntp][kt][0]   = r[0]; bf[2*ntp][kt][1]   = r[1];
                bf[2*ntp+1][kt][0] = r[2]; bf[2*ntp+1][kt][1] = r[3];
            }
#pragma unroll
            for (int mx = 0; mx < 2; mx++){
                int slot = (ty + ky)*34 + mx*16 + rowA + kx;
                uint32_t af[4][4];
#pragma unroll
                for (int kt = 0; kt < 4; kt++)
                    ldsm_x4(af[kt], sb + C2_FS + sw128((uint32_t)(slot*128 + kt*32 + chA*16)));
#pragma unroll
                for (int nt = 0; nt < 8; nt++)
#pragma unroll
                for (int kt = 0; kt < 4; kt++)
                    mma_fp16(acc[mx][nt], af[kt], bf[nt][kt]);
            }
        }
        // epilogue: relu -> fp16 pixel-major
        int gy = y0 + ty;
#pragma unroll
        for (int mx = 0; mx < 2; mx++){
            int px = x0 + mx*16 + (lane>>2);
            size_t base0 = ((size_t)gy*WL + px)*64;
            size_t base1 = ((size_t)gy*WL + px + 8)*64;
#pragma unroll
            for (int nt = 0; nt < 8; nt++){
                int co = nt*8 + (lane&3)*2;
                __half2 u0 = __floats2half2_rn(fmaxf(acc[mx][nt][0],0.f), fmaxf(acc[mx][nt][1],0.f));
                __half2 u1 = __floats2half2_rn(fmaxf(acc[mx][nt][2],0.f), fmaxf(acc[mx][nt][3],0.f));
                *(uint32_t*)(dsth + base0 + co) = *(uint32_t*)&u0;
                *(uint32_t*)(dsth + base1 + co) = *(uint32_t*)&u1;
            }
        }
    }
}

// ================= segment counting sort ====================================
__global__ __launch_bounds__(256) void k_hist(const int* __restrict__ seg){
    __shared__ int hist[SS];
    int tid = threadIdx.x;
    hist[tid] = 0;
    __syncthreads();
    int b = blockIdx.y;
    int base = blockIdx.x * 1024;
#pragma unroll
    for (int i = 0; i < 4; i++){
        int s = seg[(size_t)b*HW + base + i*256 + tid];
        atomicAdd(&hist[s], 1);
    }
    __syncthreads();
    atomicAdd(&g_cnt[b*SS + tid], hist[tid]);
}

__global__ void k_scan(){
    __shared__ int s[1024];
    int t = threadIdx.x;
    int v = g_cnt[t];
    s[t] = v;
    __syncthreads();
    for (int d = 1; d < 1024; d <<= 1){
        int add = (t >= d) ? s[t-d] : 0;
        __syncthreads();
        s[t] += add;
        __syncthreads();
    }
    g_off[t] = s[t] - v;
}

__global__ __launch_bounds__(256) void k_scatter(const int* __restrict__ seg){
    int b = blockIdx.y;
    int p = blockIdx.x*256 + threadIdx.x;
    int sgm = seg[(size_t)b*HW + p];
    int bin = b*SS + sgm;
    int idx = atomicAdd(&g_cur[bin], 1);
    g_order[g_off[bin] + idx] = p;
}

// ================= conv3+pool via mma.sync fp16 (persistent) ================
// Grid = 256 CTAs, one wave at 2 CTAs/SM. Each CTA stages W3 (fp16, SW128)
// ONCE, then loops over 4 bins (segment s across the 4 batches). Per tile,
// only ceil(rem/32) 32-px n-tile groups are staged and computed (adaptive).
#define W_OFF 0
#define F_OFF 98304
#define C3_SMEM 114688
#define C3_BINS 4
__global__ __launch_bounds__(256, 2) void k_conv3pool(const float* __restrict__ w3,
                                                      float* __restrict__ out){
    extern __shared__ __align__(1024) char sm[];
    int tid  = threadIdx.x;
    int wid  = tid >> 5;
    int lane = tid & 31;
    uint32_t sbase = smem_u32(sm);

    // ---- stage W once: rows e = tid, tid+256, tid+512 ----
#pragma unroll
    for (int rr = 0; rr < 3; rr++){
        int e = tid + rr*256;
        const float4* wrow = (const float4*)(w3 + (size_t)e*64);
#pragma unroll
        for (int k = 0; k < 16; k++){
            float4 f4 = wrow[k];
            __half2 h0 = __float22half2_rn(make_float2(f4.x, f4.y));
            __half2 h1 = __float22half2_rn(make_float2(f4.z, f4.w));
            uint2 u; u.x = *(uint32_t*)&h0; u.y = *(uint32_t*)&h1;
            *(uint2*)(sm + W_OFF + sw128((uint32_t)(e*128 + k*8))) = u;
        }
    }

    int rowA = lane & 15, chA = lane >> 4;
    int rowB = lane & 7,  chB = (lane >> 3) & 1;
    int r  = tid >> 1;          // staging: px row
    int h  = tid & 1;           // staging: ci half

#pragma unroll 1
    for (int bi = 0; bi < C3_BINS; bi++){
        int bin  = blockIdx.x + bi*256;
        int b    = bin >> 8;
        int npix = g_cnt[bin];
        int off  = g_off[bin];
        const __half* featb = g_h2 + (size_t)b*HW*64;

        float acc[6][2];
#pragma unroll
        for (int i = 0; i < 6; i++){ acc[i][0] = 0.f; acc[i][1] = 0.f; }

        int ntiles = (npix + 127) >> 7;

        for (int t = 0; t < ntiles; t++){
            int rem = npix - t*128; if (rem > 128) rem = 128;
            int ntcN = (rem + 31) >> 5;          // active 32-px groups
            __syncthreads();                      // fs reads of prev tile/bin done
            // ---- stage features (only active rows) ----
            if (r < ntcN*32){
                int idx = t*128 + r;
                if (idx < npix){
                    int pix = g_order[off + idx];
                    const uint4* fp = (const uint4*)(featb + (size_t)pix*64 + h*32);
#pragma unroll
                    for (int j = 0; j < 4; j++)
                        *(uint4*)(sm + F_OFF + sw128((uint32_t)(r*128 + h*64 + j*16))) = fp[j];
                } else {
                    uint4 z = make_uint4(0,0,0,0);
#pragma unroll
                    for (int j = 0; j < 4; j++)
                        *(uint4*)(sm + F_OFF + sw128((uint32_t)(r*128 + h*64 + j*16))) = z;
                }
            }
            __syncthreads();

#pragma unroll 1
            for (int ntc = 0; ntc < ntcN; ntc++){
                uint32_t bf[4][4][2];
#pragma unroll
                for (int j = 0; j < 4; j++){
                    int px = (ntc*4 + j)*8 + rowB;
#pragma unroll
                    for (int kt = 0; kt < 4; kt++){
                        uint32_t a = sbase + F_OFF + sw128((uint32_t)(px*128 + kt*32 + chB*16));
                        ldsm_x2(bf[j][kt], a);
                    }
                }
#pragma unroll 1
                for (int i = 0; i < 6; i++){
                    int e0 = (wid*6 + i)*16;
                    uint32_t af[4][4];
#pragma unroll
                    for (int kt = 0; kt < 4; kt++){
                        uint32_t a = sbase + W_OFF + sw128((uint32_t)((e0 + rowA)*128 + kt*32 + chA*16));
                        ldsm_x4(af[kt], a);
                    }
                    float d[4][4];
#pragma unroll
                    for (int j = 0; j < 4; j++)
#pragma unroll
                    for (int q = 0; q < 4; q++) d[j][q] = 0.f;
#pragma unroll
                    for (int kt = 0; kt < 4; kt++)
#pragma unroll
                    for (int j = 0; j < 4; j++)
                        mma_fp16(d[j], af[kt], bf[j][kt]);
#pragma unroll
                    for (int j = 0; j < 4; j++){
                        acc[i][0] += fmaxf(d[j][0], 0.f) + fmaxf(d[j][1], 0.f);
                        acc[i][1] += fmaxf(d[j][2], 0.f) + fmaxf(d[j][3], 0.f);
                    }
                }
            }
        }

        float inv = 1.f / (float)max(npix, 1);
#pragma unroll
        for (int i = 0; i < 6; i++){
            acc[i][0] += __shfl_xor_sync(0xffffffffu, acc[i][0], 1);
            acc[i][0] += __shfl_xor_sync(0xffffffffu, acc[i][0], 2);
            acc[i][1] += __shfl_xor_sync(0xffffffffu, acc[i][1], 1);
            acc[i][1] += __shfl_xor_sync(0xffffffffu, acc[i][1], 2);
        }
        if ((lane & 3) == 0){
            int row = lane >> 2;
            float* ob = out + (size_t)bin*EE;
#pragma unroll
            for (int i = 0; i < 6; i++){
                int e = (wid*6 + i)*16 + row;
                ob[e]     = acc[i][0] * inv;
                ob[e + 8] = acc[i][1] * inv;
            }
        }
    }
}

// ================= positional MLP ===========================================
__global__ __launch_bounds__(256) void k_pos(const float* __restrict__ cent,
        const float* __restrict__ w1, const float* __restrict__ b1,
        const float* __restrict__ w2, const float* __restrict__ b2,
        float* __restrict__ out){
    __shared__ __align__(8) float h2[384*16];
    int tid = threadIdx.x;
    int rb = blockIdx.x * 16;
    for (int lin = tid; lin < 6144; lin += 256){
        int j = lin >> 4, r = lin & 15;
        int rid = rb + r;
        float c0 = cent[rid*2+0] * (1.f/223.f);
        float c1 = cent[rid*2+1] * (1.f/223.f);
        float h = fmaxf(fmaf(c0, w1[j], fmaf(c1, w1[384+j], b1[j])), 0.f);
        h2[j*16 + r] = h;
    }
    __syncthreads();
    ull acc[3][8];
#pragma unroll
    for (int es = 0; es < 3; es++)
#pragma unroll
    for (int q = 0; q < 8; q++) acc[es][q] = 0ULL;
    for (int j = 0; j < 384; j++){
        ull hp[8];
#pragma unroll
        for (int q = 0; q < 8; q++) hp[q] = *(const ull*)&h2[j*16 + 2*q];
#pragma unroll
        for (int es = 0; es < 3; es++){
            float wv = w2[j*768 + tid + es*256];
            ull wp = pack2(wv, wv);
#pragma unroll
            for (int q = 0; q < 8; q++) ffma2(acc[es][q], hp[q], wp);
        }
    }
#pragma unroll
    for (int es = 0; es < 3; es++){
        int e = tid + es*256;
        float bv = b2[e];
#pragma unroll
        for (int q = 0; q < 8; q++){
            float2 v = unpack2(acc[es][q]);
            int rid = rb + 2*q;
            out[(size_t)rid*768 + e]     = v.x + bv;
            out[(size_t)(rid+1)*768 + e] = v.y + bv;
        }
    }
}

// ================= launcher =================================================
extern "C" void kernel_launch(void* const* d_in, const int* in_sizes, int n_in,
                              void* d_out, int out_size){
    const float* img  = (const float*)d_in[0];
    const int*   seg  = (const int*)d_in[1];
    const float* cent = (const float*)d_in[2];
    const float* w1   = (const float*)d_in[3];
    const float* w2   = (const float*)d_in[4];
    const float* w3   = (const float*)d_in[5];
    const float* pw1  = (const float*)d_in[6];
    const float* pb1  = (const float*)d_in[7];
    const float* pw2  = (const float*)d_in[8];
    const float* pb2  = (const float*)d_in[9];
    float* out = (float*)d_out;

    cudaFuncSetAttribute(k_conv2,
                         cudaFuncAttributeMaxDynamicSharedMemorySize, C2_SMEM);
    cudaFuncSetAttribute(k_conv3pool,
                         cudaFuncAttributeMaxDynamicSharedMemorySize, C3_SMEM);

    k_zero<<<1, 1024>>>();
    k_conv1<<<dim3(196,4), 256>>>(img, w1);
    k_conv2<<<dim3(7,14,4), 256, C2_SMEM>>>(w2);
    k_hist<<<dim3(49,4), 256>>>(seg);
    k_scan<<<1, 1024>>>();
    k_scatter<<<dim3(196,4), 256>>>(seg);
    k_conv3pool<<<256, 256, C3_SMEM>>>(w3, out);
    k_pos<<<64, 256>>>(cent, pw1, pb1, pw2, pb2, out + (size_t)BB*SS*EE);
}

// round 10
// speedup vs baseline: 7.8778x; 1.1607x over previous
#include <cuda_runtime.h>
#include <cuda_fp16.h>
#include <cstdint>

typedef unsigned long long ull;

#define BB 4
#define HH 224
#define WL 224
#define HW 50176
#define NC 64
#define EE 768
#define SS 256

// ---- scratch ----
__device__ __half g_h1[BB*HW*64];    // conv1 output, PIXEL-MAJOR fp16 [b][pix][ci]
__device__ __half g_h2[BB*HW*64];    // conv2 output, PIXEL-MAJOR fp16 [b][pix][ci]
__device__ int   g_cnt[BB*SS];
__device__ int   g_off[BB*SS];
__device__ int   g_cur[BB*SS];
__device__ int   g_order[BB*HW];

// ---- packed fp32x2 helpers ----
__device__ __forceinline__ ull pack2(float a, float b){
    ull d; asm("mov.b64 %0,{%1,%2};" : "=l"(d) : "f"(a), "f"(b)); return d;
}
__device__ __forceinline__ void ffma2(ull& d, ull a, ull b){
    asm("fma.rn.f32x2 %0,%1,%2,%0;" : "+l"(d) : "l"(a), "l"(b));
}
__device__ __forceinline__ float2 unpack2(ull d){
    float2 f; asm("mov.b64 {%0,%1},%2;" : "=f"(f.x), "=f"(f.y) : "l"(d)); return f;
}

__device__ __forceinline__ uint32_t smem_u32(const void* p){
    uint32_t a;
    asm("{ .reg .u64 t; cvta.to.shared.u64 t, %1; cvt.u32.u64 %0, t; }" : "=r"(a) : "l"(p));
    return a;
}
__device__ __forceinline__ uint32_t sw128(uint32_t off){ return off ^ ((off >> 3) & 0x70); }

// ---- mma.sync fp16 helpers (sm_80 PTX, works on compute_100) ----
__device__ __forceinline__ void ldsm_x4(uint32_t* r, uint32_t a){
    asm volatile("ldmatrix.sync.aligned.m8n8.x4.shared.b16 {%0,%1,%2,%3}, [%4];"
        : "=r"(r[0]),"=r"(r[1]),"=r"(r[2]),"=r"(r[3]) : "r"(a));
}
__device__ __forceinline__ void ldsm_x2(uint32_t* r, uint32_t a){
    asm volatile("ldmatrix.sync.aligned.m8n8.x2.shared.b16 {%0,%1}, [%2];"
        : "=r"(r[0]),"=r"(r[1]) : "r"(a));
}
__device__ __forceinline__ void mma_fp16(float* d, const uint32_t* a, const uint32_t* b){
    asm volatile("mma.sync.aligned.m16n8k16.row.col.f32.f16.f16.f32 "
        "{%0,%1,%2,%3}, {%4,%5,%6,%7}, {%8,%9}, {%0,%1,%2,%3};"
        : "+f"(d[0]),"+f"(d[1]),"+f"(d[2]),"+f"(d[3])
        : "r"(a[0]),"r"(a[1]),"r"(a[2]),"r"(a[3]), "r"(b[0]),"r"(b[1]));
}

// ================= zero counters ============================================
__global__ void k_zero(){
    int t = threadIdx.x;
    g_cnt[t] = 0; g_cur[t] = 0;
}

// ================= conv1: 3->64 3x3 relu, writes fp16 pixel-major ===========
__global__ __launch_bounds__(256) void k_conv1(const float* __restrict__ img,
                                               const float* __restrict__ w1){
    __shared__ float ws[64*27];
    int tid = threadIdx.x;
    for (int i = tid; i < 64*27; i += 256) ws[i] = w1[i];
    __syncthreads();
    int b = blockIdx.y;
    int p = blockIdx.x*256 + tid;
    int y = p / WL, x = p % WL;
    float v[27];
#pragma unroll
    for (int ci = 0; ci < 3; ci++)
#pragma unroll
    for (int ky = 0; ky < 3; ky++)
#pragma unroll
    for (int kx = 0; kx < 3; kx++){
        int yy = y + ky - 1, xx = x + kx - 1;
        float val = 0.f;
        if (yy >= 0 && yy < HH && xx >= 0 && xx < WL)
            val = img[(size_t)(b*3+ci)*HW + yy*WL + xx];
        v[ci*9 + ky*3 + kx] = val;
    }
    uint32_t pk[32];
#pragma unroll 4
    for (int cp = 0; cp < 32; cp++){
        float a0 = 0.f, a1 = 0.f;
#pragma unroll
        for (int t = 0; t < 27; t++){
            a0 = fmaf(ws[(2*cp)*27+t],   v[t], a0);
            a1 = fmaf(ws[(2*cp+1)*27+t], v[t], a1);
        }
        __half2 h = __floats2half2_rn(fmaxf(a0,0.f), fmaxf(a1,0.f));
        pk[cp] = *(uint32_t*)&h;
    }
    uint4* dst = (uint4*)(g_h1 + ((size_t)b*HW + p)*64);
#pragma unroll
    for (int j = 0; j < 8; j++)
        dst[j] = make_uint4(pk[4*j], pk[4*j+1], pk[4*j+2], pk[4*j+3]);
}

// ================= conv2 via mma.sync fp16 (9 passes, coalesced staging) ====
// Single fp16 weights (no hi/lo split): weight rounding adds an independent
// ~2.4e-4 systematic term (combined rel_err ~2.6e-4, 3.8x under threshold)
// but HALVES mainloop HMMA+LDSM. Weight staging reads w2 linearly (coalesced
// LDG.32) and scatters STS.16 into [pass][co][ci] 128B swizzled rows.
#define C2_WS 0
#define C2_FS 73728
#define C2_SMEM 152064
__global__ __launch_bounds__(256) void k_conv2(const float* __restrict__ w2){
    extern __shared__ __align__(1024) char sm[];
    uint32_t sb = smem_u32(sm);
    int tid = threadIdx.x, wid = tid>>5, lane = tid&31;
    int b = blockIdx.z;
    int x0 = blockIdx.x*32, y0 = blockIdx.y*16;
    const __half* src = g_h1 + (size_t)b*HW*64;
    __half* dsth = g_h2 + (size_t)b*HW*64;

    // stage weights: coalesced linear read of w2[co][ci][k], scatter to
    // pass-k plane at [co][ci] (128B rows, SW128)
    for (int lin = tid; lin < 64*64*9; lin += 256){
        float v = w2[lin];
        int co = lin / 576;
        int rem = lin - co*576;
        int ci = rem / 9;
        int k  = rem - ci*9;
        __half hv = __float2half_rn(v);
        *(__half*)(sm + C2_WS + k*8192 + sw128((uint32_t)(co*128 + ci*2))) = hv;
    }
    // stage features: 18 rows x 34 px halo, 128B per pixel
    for (int lin = tid; lin < 612*8; lin += 256){
        int slot = lin >> 3, part = lin & 7;
        int gy = y0 + slot/34 - 1, gx = x0 + (slot%34) - 1;
        uint4 v = make_uint4(0,0,0,0);
        if (gy >= 0 && gy < HH && gx >= 0 && gx < WL)
            v = *(const uint4*)(src + ((size_t)gy*WL + gx)*64 + part*8);
        *(uint4*)(sm + C2_FS + sw128((uint32_t)(slot*128 + part*16))) = v;
    }
    __syncthreads();

    int rowA = lane & 15, chA = lane >> 4;
    int rowB8 = lane & 7, chB = (lane>>3)&1, grpB = lane>>4;

#pragma unroll 1
    for (int half = 0; half < 2; half++){
        float acc[2][8][4];
#pragma unroll
        for (int mx = 0; mx < 2; mx++)
#pragma unroll
        for (int nt = 0; nt < 8; nt++)
#pragma unroll
        for (int q = 0; q < 4; q++) acc[mx][nt][q] = 0.f;

        int ty = half*8 + wid;
#pragma unroll 1
        for (int pass = 0; pass < 9; pass++){
            int ky = pass / 3, kx = pass - ky*3;
            uint32_t wbase = sb + C2_WS + pass*8192;
            uint32_t bf[8][4][2];
#pragma unroll
            for (int kt = 0; kt < 4; kt++)
#pragma unroll
            for (int ntp = 0; ntp < 4; ntp++){
                uint32_t r[4];
                uint32_t a = wbase + sw128((uint32_t)(((ntp*2 + grpB)*8 + rowB8)*128 + kt*32 + chB*16));
                ldsm_x4(r, a);
                bf[2*ntp][kt][0]   = r[0]; bf[2*ntp][kt][1]   = r[1];
                bf[2*ntp+1][kt][0] = r[2]; bf[2*ntp+1][kt][1] = r[3];
            }
#pragma unroll
            for (int mx = 0; mx < 2; mx++){
                int slot = (ty + ky)*34 + mx*16 + rowA + kx;
                uint32_t af[4][4];
#pragma unroll
                for (int kt = 0; kt < 4; kt++)
                    ldsm_x4(af[kt], sb + C2_FS + sw128((uint32_t)(slot*128 + kt*32 + chA*16)));
#pragma unroll
                for (int nt = 0; nt < 8; nt++)
#pragma unroll
                for (int kt = 0; kt < 4; kt++)
                    mma_fp16(acc[mx][nt], af[kt], bf[nt][kt]);
            }
        }
        // epilogue: relu -> fp16 pixel-major
        int gy = y0 + ty;
#pragma unroll
        for (int mx = 0; mx < 2; mx++){
            int px = x0 + mx*16 + (lane>>2);
            size_t base0 = ((size_t)gy*WL + px)*64;
            size_t base1 = ((size_t)gy*WL + px + 8)*64;
#pragma unroll
            for (int nt = 0; nt < 8; nt++){
                int co = nt*8 + (lane&3)*2;
                __half2 u0 = __floats2half2_rn(fmaxf(acc[mx][nt][0],0.f), fmaxf(acc[mx][nt][1],0.f));
                __half2 u1 = __floats2half2_rn(fmaxf(acc[mx][nt][2],0.f), fmaxf(acc[mx][nt][3],0.f));
                *(uint32_t*)(dsth + base0 + co) = *(uint32_t*)&u0;
                *(uint32_t*)(dsth + base1 + co) = *(uint32_t*)&u1;
            }
        }
    }
}

// ================= segment counting sort ====================================
__global__ __launch_bounds__(256) void k_hist(const int* __restrict__ seg){
    __shared__ int hist[SS];
    int tid = threadIdx.x;
    hist[tid] = 0;
    __syncthreads();
    int b = blockIdx.y;
    int base = blockIdx.x * 1024;
#pragma unroll
    for (int i = 0; i < 4; i++){
        int s = seg[(size_t)b*HW + base + i*256 + tid];
        atomicAdd(&hist[s], 1);
    }
    __syncthreads();
    atomicAdd(&g_cnt[b*SS + tid], hist[tid]);
}

__global__ void k_scan(){
    __shared__ int s[1024];
    int t = threadIdx.x;
    int v = g_cnt[t];
    s[t] = v;
    __syncthreads();
    for (int d = 1; d < 1024; d <<= 1){
        int add = (t >= d) ? s[t-d] : 0;
        __syncthreads();
        s[t] += add;
        __syncthreads();
    }
    g_off[t] = s[t] - v;
}

__global__ __launch_bounds__(256) void k_scatter(const int* __restrict__ seg){
    int b = blockIdx.y;
    int p = blockIdx.x*256 + threadIdx.x;
    int sgm = seg[(size_t)b*HW + p];
    int bin = b*SS + sgm;
    int idx = atomicAdd(&g_cur[bin], 1);
    g_order[g_off[bin] + idx] = p;
}

// ================= conv3+pool via mma.sync fp16 (persistent) ================
#define W_OFF 0
#define F_OFF 98304
#define C3_SMEM 114688
#define C3_BINS 4
__global__ __launch_bounds__(256, 2) void k_conv3pool(const float* __restrict__ w3,
                                                      float* __restrict__ out){
    extern __shared__ __align__(1024) char sm[];
    int tid  = threadIdx.x;
    int wid  = tid >> 5;
    int lane = tid & 31;
    uint32_t sbase = smem_u32(sm);

    // ---- stage W once: rows e = tid, tid+256, tid+512 ----
#pragma unroll
    for (int rr = 0; rr < 3; rr++){
        int e = tid + rr*256;
        const float4* wrow = (const float4*)(w3 + (size_t)e*64);
#pragma unroll
        for (int k = 0; k < 16; k++){
            float4 f4 = wrow[k];
            __half2 h0 = __float22half2_rn(make_float2(f4.x, f4.y));
            __half2 h1 = __float22half2_rn(make_float2(f4.z, f4.w));
            uint2 u; u.x = *(uint32_t*)&h0; u.y = *(uint32_t*)&h1;
            *(uint2*)(sm + W_OFF + sw128((uint32_t)(e*128 + k*8))) = u;
        }
    }

    int rowA = lane & 15, chA = lane >> 4;
    int rowB = lane & 7,  chB = (lane >> 3) & 1;
    int r  = tid >> 1;          // staging: px row
    int h  = tid & 1;           // staging: ci half

#pragma unroll 1
    for (int bi = 0; bi < C3_BINS; bi++){
        int bin  = blockIdx.x + bi*256;
        int b    = bin >> 8;
        int npix = g_cnt[bin];
        int off  = g_off[bin];
        const __half* featb = g_h2 + (size_t)b*HW*64;

        float acc[6][2];
#pragma unroll
        for (int i = 0; i < 6; i++){ acc[i][0] = 0.f; acc[i][1] = 0.f; }

        int ntiles = (npix + 127) >> 7;

        for (int t = 0; t < ntiles; t++){
            int rem = npix - t*128; if (rem > 128) rem = 128;
            int ntcN = (rem + 31) >> 5;          // active 32-px groups
            __syncthreads();                      // fs reads of prev tile/bin done
            // ---- stage features (only active rows) ----
            if (r < ntcN*32){
                int idx = t*128 + r;
                if (idx < npix){
                    int pix = g_order[off + idx];
                    const uint4* fp = (const uint4*)(featb + (size_t)pix*64 + h*32);
#pragma unroll
                    for (int j = 0; j < 4; j++)
                        *(uint4*)(sm + F_OFF + sw128((uint32_t)(r*128 + h*64 + j*16))) = fp[j];
                } else {
                    uint4 z = make_uint4(0,0,0,0);
#pragma unroll
                    for (int j = 0; j < 4; j++)
                        *(uint4*)(sm + F_OFF + sw128((uint32_t)(r*128 + h*64 + j*16))) = z;
                }
            }
            __syncthreads();

#pragma unroll 1
            for (int ntc = 0; ntc < ntcN; ntc++){
                uint32_t bf[4][4][2];
#pragma unroll
                for (int j = 0; j < 4; j++){
                    int px = (ntc*4 + j)*8 + rowB;
#pragma unroll
                    for (int kt = 0; kt < 4; kt++){
                        uint32_t a = sbase + F_OFF + sw128((uint32_t)(px*128 + kt*32 + chB*16));
                        ldsm_x2(bf[j][kt], a);
                    }
                }
#pragma unroll 1
                for (int i = 0; i < 6; i++){
                    int e0 = (wid*6 + i)*16;
                    uint32_t af[4][4];
#pragma unroll
                    for (int kt = 0; kt < 4; kt++){
                        uint32_t a = sbase + W_OFF + sw128((uint32_t)((e0 + rowA)*128 + kt*32 + chA*16));
                        ldsm_x4(af[kt], a);
                    }
                    float d[4][4];
#pragma unroll
                    for (int j = 0; j < 4; j++)
#pragma unroll
                    for (int q = 0; q < 4; q++) d[j][q] = 0.f;
#pragma unroll
                    for (int kt = 0; kt < 4; kt++)
#pragma unroll
                    for (int j = 0; j < 4; j++)
                        mma_fp16(d[j], af[kt], bf[j][kt]);
#pragma unroll
                    for (int j = 0; j < 4; j++){
                        acc[i][0] += fmaxf(d[j][0], 0.f) + fmaxf(d[j][1], 0.f);
                        acc[i][1] += fmaxf(d[j][2], 0.f) + fmaxf(d[j][3], 0.f);
                    }
                }
            }
        }

        float inv = 1.f / (float)max(npix, 1);
#pragma unroll
        for (int i = 0; i < 6; i++){
            acc[i][0] += __shfl_xor_sync(0xffffffffu, acc[i][0], 1);
            acc[i][0] += __shfl_xor_sync(0xffffffffu, acc[i][0], 2);
            acc[i][1] += __shfl_xor_sync(0xffffffffu, acc[i][1], 1);
            acc[i][1] += __shfl_xor_sync(0xffffffffu, acc[i][1], 2);
        }
        if ((lane & 3) == 0){
            int row = lane >> 2;
            float* ob = out + (size_t)bin*EE;
#pragma unroll
            for (int i = 0; i < 6; i++){
                int e = (wid*6 + i)*16 + row;
                ob[e]     = acc[i][0] * inv;
                ob[e + 8] = acc[i][1] * inv;
            }
        }
    }
}

// ================= positional MLP ===========================================
__global__ __launch_bounds__(256) void k_pos(const float* __restrict__ cent,
        const float* __restrict__ w1, const float* __restrict__ b1,
        const float* __restrict__ w2, const float* __restrict__ b2,
        float* __restrict__ out){
    __shared__ __align__(8) float h2[384*16];
    int tid = threadIdx.x;
    int rb = blockIdx.x * 16;
    for (int lin = tid; lin < 6144; lin += 256){
        int j = lin >> 4, r = lin & 15;
        int rid = rb + r;
        float c0 = cent[rid*2+0] * (1.f/223.f);
        float c1 = cent[rid*2+1] * (1.f/223.f);
        float h = fmaxf(fmaf(c0, w1[j], fmaf(c1, w1[384+j], b1[j])), 0.f);
        h2[j*16 + r] = h;
    }
    __syncthreads();
    ull acc[3][8];
#pragma unroll
    for (int es = 0; es < 3; es++)
#pragma unroll
    for (int q = 0; q < 8; q++) acc[es][q] = 0ULL;
    for (int j = 0; j < 384; j++){
        ull hp[8];
#pragma unroll
        for (int q = 0; q < 8; q++) hp[q] = *(const ull*)&h2[j*16 + 2*q];
#pragma unroll
        for (int es = 0; es < 3; es++){
            float wv = w2[j*768 + tid + es*256];
            ull wp = pack2(wv, wv);
#pragma unroll
            for (int q = 0; q < 8; q++) ffma2(acc[es][q], hp[q], wp);
        }
    }
#pragma unroll
    for (int es = 0; es < 3; es++){
        int e = tid + es*256;
        float bv = b2[e];
#pragma unroll
        for (int q = 0; q < 8; q++){
            float2 v = unpack2(acc[es][q]);
            int rid = rb + 2*q;
            out[(size_t)rid*768 + e]     = v.x + bv;
            out[(size_t)(rid+1)*768 + e] = v.y + bv;
        }
    }
}

// ================= launcher =================================================
extern "C" void kernel_launch(void* const* d_in, const int* in_sizes, int n_in,
                              void* d_out, int out_size){
    const float* img  = (const float*)d_in[0];
    const int*   seg  = (const int*)d_in[1];
    const float* cent = (const float*)d_in[2];
    const float* w1   = (const float*)d_in[3];
    const float* w2   = (const float*)d_in[4];
    const float* w3   = (const float*)d_in[5];
    const float* pw1  = (const float*)d_in[6];
    const float* pb1  = (const float*)d_in[7];
    const float* pw2  = (const float*)d_in[8];
    const float* pb2  = (const float*)d_in[9];
    float* out = (float*)d_out;

    cudaFuncSetAttribute(k_conv2,
                         cudaFuncAttributeMaxDynamicSharedMemorySize, C2_SMEM);
    cudaFuncSetAttribute(k_conv3pool,
                         cudaFuncAttributeMaxDynamicSharedMemorySize, C3_SMEM);

    k_zero<<<1, 1024>>>();
    k_conv1<<<dim3(196,4), 256>>>(img, w1);
    k_conv2<<<dim3(7,14,4), 256, C2_SMEM>>>(w2);
    k_hist<<<dim3(49,4), 256>>>(seg);
    k_scan<<<1, 1024>>>();
    k_scatter<<<dim3(196,4), 256>>>(seg);
    k_conv3pool<<<256, 256, C3_SMEM>>>(w3, out);
    k_pos<<<64, 256>>>(cent, pw1, pb1, pw2, pb2, out + (size_t)BB*SS*EE);
}

// round 11
// speedup vs baseline: 9.3551x; 1.1875x over previous
#include <cuda_runtime.h>
#include <cuda_fp16.h>
#include <cstdint>

typedef unsigned long long ull;

#define BB 4
#define HH 224
#define WL 224
#define HW 50176
#define NC 64
#define EE 768
#define SS 256

// ---- scratch ----
__device__ __half g_h1[BB*HW*64];    // conv1 output, PIXEL-MAJOR fp16 [b][pix][ci]
__device__ __half g_h2[BB*HW*64];    // conv2 output, PIXEL-MAJOR fp16 [b][pix][ci]
__device__ int   g_cnt[BB*SS];
__device__ int   g_off[BB*SS];
__device__ int   g_cur[BB*SS];
__device__ int   g_order[BB*HW];

// ---- packed fp32x2 helpers ----
__device__ __forceinline__ ull pack2(float a, float b){
    ull d; asm("mov.b64 %0,{%1,%2};" : "=l"(d) : "f"(a), "f"(b)); return d;
}
__device__ __forceinline__ void ffma2(ull& d, ull a, ull b){
    asm("fma.rn.f32x2 %0,%1,%2,%0;" : "+l"(d) : "l"(a), "l"(b));
}
__device__ __forceinline__ float2 unpack2(ull d){
    float2 f; asm("mov.b64 {%0,%1},%2;" : "=f"(f.x), "=f"(f.y) : "l"(d)); return f;
}

__device__ __forceinline__ uint32_t smem_u32(const void* p){
    uint32_t a;
    asm("{ .reg .u64 t; cvta.to.shared.u64 t, %1; cvt.u32.u64 %0, t; }" : "=r"(a) : "l"(p));
    return a;
}
__device__ __forceinline__ uint32_t sw128(uint32_t off){ return off ^ ((off >> 3) & 0x70); }

// ---- mma.sync fp16 helpers (sm_80 PTX, works on compute_100) ----
__device__ __forceinline__ void ldsm_x4(uint32_t* r, uint32_t a){
    asm volatile("ldmatrix.sync.aligned.m8n8.x4.shared.b16 {%0,%1,%2,%3}, [%4];"
        : "=r"(r[0]),"=r"(r[1]),"=r"(r[2]),"=r"(r[3]) : "r"(a));
}
__device__ __forceinline__ void ldsm_x2(uint32_t* r, uint32_t a){
    asm volatile("ldmatrix.sync.aligned.m8n8.x2.shared.b16 {%0,%1}, [%2];"
        : "=r"(r[0]),"=r"(r[1]) : "r"(a));
}
__device__ __forceinline__ void mma_fp16(float* d, const uint32_t* a, const uint32_t* b){
    asm volatile("mma.sync.aligned.m16n8k16.row.col.f32.f16.f16.f32 "
        "{%0,%1,%2,%3}, {%4,%5,%6,%7}, {%8,%9}, {%0,%1,%2,%3};"
        : "+f"(d[0]),"+f"(d[1]),"+f"(d[2]),"+f"(d[3])
        : "r"(a[0]),"r"(a[1]),"r"(a[2]),"r"(a[3]), "r"(b[0]),"r"(b[1]));
}

// ================= zero counters ============================================
__global__ void k_zero(){
    int t = threadIdx.x;
    g_cnt[t] = 0; g_cur[t] = 0;
}

// ================= conv1: 3->64 3x3 relu, f32x2 packed, fp16 pixel-major ====
// Weights staged as (co,co+1) f32x2 pairs, layout [cp][t] (t padded to 28 so
// rows are 16B-aligned for LDS.128). Activations pre-packed (v,v). Inner:
// 32 cp x (14 LDS.128 + 28 FFMA2) -> ~1792 FMA-cyc vs 3456 scalar.
__global__ __launch_bounds__(256) void k_conv1(const float* __restrict__ img,
                                               const float* __restrict__ w1){
    __shared__ ull ws[32*28];
    int tid = threadIdx.x;
    for (int i = tid; i < 32*28; i += 256){
        int cp = i / 28, t = i % 28;
        ws[i] = (t < 27) ? pack2(w1[(2*cp)*27+t], w1[(2*cp+1)*27+t]) : 0ULL;
    }
    __syncthreads();
    int b = blockIdx.y;
    int p = blockIdx.x*256 + tid;
    int y = p / WL, x = p % WL;
    ull vp[28];
#pragma unroll
    for (int ci = 0; ci < 3; ci++)
#pragma unroll
    for (int ky = 0; ky < 3; ky++)
#pragma unroll
    for (int kx = 0; kx < 3; kx++){
        int yy = y + ky - 1, xx = x + kx - 1;
        float val = 0.f;
        if (yy >= 0 && yy < HH && xx >= 0 && xx < WL)
            val = img[(size_t)(b*3+ci)*HW + yy*WL + xx];
        vp[ci*9 + ky*3 + kx] = pack2(val, val);
    }
    vp[27] = 0ULL;
    uint32_t pk[32];
#pragma unroll 2
    for (int cp = 0; cp < 32; cp++){
        ull acc = 0ULL;
        const ulonglong2* wp = (const ulonglong2*)&ws[cp*28];
#pragma unroll
        for (int tp = 0; tp < 14; tp++){
            ulonglong2 w = wp[tp];
            ffma2(acc, vp[2*tp],   w.x);
            ffma2(acc, vp[2*tp+1], w.y);
        }
        float2 r = unpack2(acc);
        __half2 h = __floats2half2_rn(fmaxf(r.x,0.f), fmaxf(r.y,0.f));
        pk[cp] = *(uint32_t*)&h;
    }
    uint4* dst = (uint4*)(g_h1 + ((size_t)b*HW + p)*64);
#pragma unroll
    for (int j = 0; j < 8; j++)
        dst[j] = make_uint4(pk[4*j], pk[4*j+1], pk[4*j+2], pk[4*j+3]);
}

// ================= conv2 via mma.sync fp16 (9 passes, coalesced staging) ====
#define C2_WS 0
#define C2_FS 73728
#define C2_SMEM 152064
__global__ __launch_bounds__(256) void k_conv2(const float* __restrict__ w2){
    extern __shared__ __align__(1024) char sm[];
    uint32_t sb = smem_u32(sm);
    int tid = threadIdx.x, wid = tid>>5, lane = tid&31;
    int b = blockIdx.z;
    int x0 = blockIdx.x*32, y0 = blockIdx.y*16;
    const __half* src = g_h1 + (size_t)b*HW*64;
    __half* dsth = g_h2 + (size_t)b*HW*64;

    // stage weights: coalesced linear read of w2[co][ci][k], scatter STS.16
    for (int lin = tid; lin < 64*64*9; lin += 256){
        float v = w2[lin];
        int co = lin / 576;
        int rem = lin - co*576;
        int ci = rem / 9;
        int k  = rem - ci*9;
        __half hv = __float2half_rn(v);
        *(__half*)(sm + C2_WS + k*8192 + sw128((uint32_t)(co*128 + ci*2))) = hv;
    }
    // stage features: 18 rows x 34 px halo, 128B per pixel
    for (int lin = tid; lin < 612*8; lin += 256){
        int slot = lin >> 3, part = lin & 7;
        int gy = y0 + slot/34 - 1, gx = x0 + (slot%34) - 1;
        uint4 v = make_uint4(0,0,0,0);
        if (gy >= 0 && gy < HH && gx >= 0 && gx < WL)
            v = *(const uint4*)(src + ((size_t)gy*WL + gx)*64 + part*8);
        *(uint4*)(sm + C2_FS + sw128((uint32_t)(slot*128 + part*16))) = v;
    }
    __syncthreads();

    int rowA = lane & 15, chA = lane >> 4;
    int rowB8 = lane & 7, chB = (lane>>3)&1, grpB = lane>>4;

#pragma unroll 1
    for (int half = 0; half < 2; half++){
        float acc[2][8][4];
#pragma unroll
        for (int mx = 0; mx < 2; mx++)
#pragma unroll
        for (int nt = 0; nt < 8; nt++)
#pragma unroll
        for (int q = 0; q < 4; q++) acc[mx][nt][q] = 0.f;

        int ty = half*8 + wid;
#pragma unroll 1
        for (int pass = 0; pass < 9; pass++){
            int ky = pass / 3, kx = pass - ky*3;
            uint32_t wbase = sb + C2_WS + pass*8192;
            uint32_t bf[8][4][2];
#pragma unroll
            for (int kt = 0; kt < 4; kt++)
#pragma unroll
            for (int ntp = 0; ntp < 4; ntp++){
                uint32_t r[4];
                uint32_t a = wbase + sw128((uint32_t)(((ntp*2 + grpB)*8 + rowB8)*128 + kt*32 + chB*16));
                ldsm_x4(r, a);
                bf[2*ntp][kt][0]   = r[0]; bf[2*ntp][kt][1]   = r[1];
                bf[2*ntp+1][kt][0] = r[2]; bf[2*ntp+1][kt][1] = r[3];
            }
#pragma unroll
            for (int mx = 0; mx < 2; mx++){
                int slot = (ty + ky)*34 + mx*16 + rowA + kx;
                uint32_t af[4][4];
#pragma unroll
                for (int kt = 0; kt < 4; kt++)
                    ldsm_x4(af[kt], sb + C2_FS + sw128((uint32_t)(slot*128 + kt*32 + chA*16)));
#pragma unroll
                for (int nt = 0; nt < 8; nt++)
#pragma unroll
                for (int kt = 0; kt < 4; kt++)
                    mma_fp16(acc[mx][nt], af[kt], bf[nt][kt]);
            }
        }
        // epilogue: relu -> fp16 pixel-major
        int gy = y0 + ty;
#pragma unroll
        for (int mx = 0; mx < 2; mx++){
            int px = x0 + mx*16 + (lane>>2);
            size_t base0 = ((size_t)gy*WL + px)*64;
            size_t base1 = ((size_t)gy*WL + px + 8)*64;
#pragma unroll
            for (int nt = 0; nt < 8; nt++){
                int co = nt*8 + (lane&3)*2;
                __half2 u0 = __floats2half2_rn(fmaxf(acc[mx][nt][0],0.f), fmaxf(acc[mx][nt][1],0.f));
                __half2 u1 = __floats2half2_rn(fmaxf(acc[mx][nt][2],0.f), fmaxf(acc[mx][nt][3],0.f));
                *(uint32_t*)(dsth + base0 + co) = *(uint32_t*)&u0;
                *(uint32_t*)(dsth + base1 + co) = *(uint32_t*)&u1;
            }
        }
    }
}

// ================= segment counting sort ====================================
__global__ __launch_bounds__(256) void k_hist(const int* __restrict__ seg){
    __shared__ int hist[SS];
    int tid = threadIdx.x;
    hist[tid] = 0;
    __syncthreads();
    int b = blockIdx.y;
    int base = blockIdx.x * 1024;
#pragma unroll
    for (int i = 0; i < 4; i++){
        int s = seg[(size_t)b*HW + base + i*256 + tid];
        atomicAdd(&hist[s], 1);
    }
    __syncthreads();
    atomicAdd(&g_cnt[b*SS + tid], hist[tid]);
}

__global__ void k_scan(){
    __shared__ int s[1024];
    int t = threadIdx.x;
    int v = g_cnt[t];
    s[t] = v;
    __syncthreads();
    for (int d = 1; d < 1024; d <<= 1){
        int add = (t >= d) ? s[t-d] : 0;
        __syncthreads();
        s[t] += add;
        __syncthreads();
    }
    g_off[t] = s[t] - v;
}

__global__ __launch_bounds__(256) void k_scatter(const int* __restrict__ seg){
    int b = blockIdx.y;
    int p = blockIdx.x*256 + threadIdx.x;
    int sgm = seg[(size_t)b*HW + p];
    int bin = b*SS + sgm;
    int idx = atomicAdd(&g_cur[bin], 1);
    g_order[g_off[bin] + idx] = p;
}

// ================= conv3+pool via mma.sync fp16 (persistent) ================
#define W_OFF 0
#define F_OFF 98304
#define C3_SMEM 114688
#define C3_BINS 4
__global__ __launch_bounds__(256, 2) void k_conv3pool(const float* __restrict__ w3,
                                                      float* __restrict__ out){
    extern __shared__ __align__(1024) char sm[];
    int tid  = threadIdx.x;
    int wid  = tid >> 5;
    int lane = tid & 31;
    uint32_t sbase = smem_u32(sm);

    // ---- stage W once: rows e = tid, tid+256, tid+512 ----
#pragma unroll
    for (int rr = 0; rr < 3; rr++){
        int e = tid + rr*256;
        const float4* wrow = (const float4*)(w3 + (size_t)e*64);
#pragma unroll
        for (int k = 0; k < 16; k++){
            float4 f4 = wrow[k];
            __half2 h0 = __float22half2_rn(make_float2(f4.x, f4.y));
            __half2 h1 = __float22half2_rn(make_float2(f4.z, f4.w));
            uint2 u; u.x = *(uint32_t*)&h0; u.y = *(uint32_t*)&h1;
            *(uint2*)(sm + W_OFF + sw128((uint32_t)(e*128 + k*8))) = u;
        }
    }

    int rowA = lane & 15, chA = lane >> 4;
    int rowB = lane & 7,  chB = (lane >> 3) & 1;
    int r  = tid >> 1;          // staging: px row
    int h  = tid & 1;           // staging: ci half

#pragma unroll 1
    for (int bi = 0; bi < C3_BINS; bi++){
        int bin  = blockIdx.x + bi*256;
        int b    = bin >> 8;
        int npix = g_cnt[bin];
        int off  = g_off[bin];
        const __half* featb = g_h2 + (size_t)b*HW*64;

        float acc[6][2];
#pragma unroll
        for (int i = 0; i < 6; i++){ acc[i][0] = 0.f; acc[i][1] = 0.f; }

        int ntiles = (npix + 127) >> 7;

        for (int t = 0; t < ntiles; t++){
            int rem = npix - t*128; if (rem > 128) rem = 128;
            int ntcN = (rem + 31) >> 5;
            __syncthreads();
            if (r < ntcN*32){
                int idx = t*128 + r;
                if (idx < npix){
                    int pix = g_order[off + idx];
                    const uint4* fp = (const uint4*)(featb + (size_t)pix*64 + h*32);
#pragma unroll
                    for (int j = 0; j < 4; j++)
                        *(uint4*)(sm + F_OFF + sw128((uint32_t)(r*128 + h*64 + j*16))) = fp[j];
                } else {
                    uint4 z = make_uint4(0,0,0,0);
#pragma unroll
                    for (int j = 0; j < 4; j++)
                        *(uint4*)(sm + F_OFF + sw128((uint32_t)(r*128 + h*64 + j*16))) = z;
                }
            }
            __syncthreads();

#pragma unroll 1
            for (int ntc = 0; ntc < ntcN; ntc++){
                uint32_t bf[4][4][2];
#pragma unroll
                for (int j = 0; j < 4; j++){
                    int px = (ntc*4 + j)*8 + rowB;
#pragma unroll
                    for (int kt = 0; kt < 4; kt++){
                        uint32_t a = sbase + F_OFF + sw128((uint32_t)(px*128 + kt*32 + chB*16));
                        ldsm_x2(bf[j][kt], a);
                    }
                }
#pragma unroll 1
                for (int i = 0; i < 6; i++){
                    int e0 = (wid*6 + i)*16;
                    uint32_t af[4][4];
#pragma unroll
                    for (int kt = 0; kt < 4; kt++){
                        uint32_t a = sbase + W_OFF + sw128((uint32_t)((e0 + rowA)*128 + kt*32 + chA*16));
                        ldsm_x4(af[kt], a);
                    }
                    float d[4][4];
#pragma unroll
                    for (int j = 0; j < 4; j++)
#pragma unroll
                    for (int q = 0; q < 4; q++) d[j][q] = 0.f;
#pragma unroll
                    for (int kt = 0; kt < 4; kt++)
#pragma unroll
                    for (int j = 0; j < 4; j++)
                        mma_fp16(d[j], af[kt], bf[j][kt]);
#pragma unroll
                    for (int j = 0; j < 4; j++){
                        acc[i][0] += fmaxf(d[j][0], 0.f) + fmaxf(d[j][1], 0.f);
                        acc[i][1] += fmaxf(d[j][2], 0.f) + fmaxf(d[j][3], 0.f);
                    }
                }
            }
        }

        float inv = 1.f / (float)max(npix, 1);
#pragma unroll
        for (int i = 0; i < 6; i++){
            acc[i][0] += __shfl_xor_sync(0xffffffffu, acc[i][0], 1);
            acc[i][0] += __shfl_xor_sync(0xffffffffu, acc[i][0], 2);
            acc[i][1] += __shfl_xor_sync(0xffffffffu, acc[i][1], 1);
            acc[i][1] += __shfl_xor_sync(0xffffffffu, acc[i][1], 2);
        }
        if ((lane & 3) == 0){
            int row = lane >> 2;
            float* ob = out + (size_t)bin*EE;
#pragma unroll
            for (int i = 0; i < 6; i++){
                int e = (wid*6 + i)*16 + row;
                ob[e]     = acc[i][0] * inv;
                ob[e + 8] = acc[i][1] * inv;
            }
        }
    }
}

// ================= positional MLP ===========================================
__global__ __launch_bounds__(256) void k_pos(const float* __restrict__ cent,
        const float* __restrict__ w1, const float* __restrict__ b1,
        const float* __restrict__ w2, const float* __restrict__ b2,
        float* __restrict__ out){
    __shared__ __align__(8) float h2[384*16];
    int tid = threadIdx.x;
    int rb = blockIdx.x * 16;
    for (int lin = tid; lin < 6144; lin += 256){
        int j = lin >> 4, r = lin & 15;
        int rid = rb + r;
        float c0 = cent[rid*2+0] * (1.f/223.f);
        float c1 = cent[rid*2+1] * (1.f/223.f);
        float h = fmaxf(fmaf(c0, w1[j], fmaf(c1, w1[384+j], b1[j])), 0.f);
        h2[j*16 + r] = h;
    }
    __syncthreads();
    ull acc[3][8];
#pragma unroll
    for (int es = 0; es < 3; es++)
#pragma unroll
    for (int q = 0; q < 8; q++) acc[es][q] = 0ULL;
    for (int j = 0; j < 384; j++){
        ull hp[8];
#pragma unroll
        for (int q = 0; q < 8; q++) hp[q] = *(const ull*)&h2[j*16 + 2*q];
#pragma unroll
        for (int es = 0; es < 3; es++){
            float wv = w2[j*768 + tid + es*256];
            ull wp = pack2(wv, wv);
#pragma unroll
            for (int q = 0; q < 8; q++) ffma2(acc[es][q], hp[q], wp);
        }
    }
#pragma unroll
    for (int es = 0; es < 3; es++){
        int e = tid + es*256;
        float bv = b2[e];
#pragma unroll
        for (int q = 0; q < 8; q++){
            float2 v = unpack2(acc[es][q]);
            int rid = rb + 2*q;
            out[(size_t)rid*768 + e]     = v.x + bv;
            out[(size_t)(rid+1)*768 + e] = v.y + bv;
        }
    }
}

// ================= launcher (two-stream fork/join inside graph capture) =====
extern "C" void kernel_launch(void* const* d_in, const int* in_sizes, int n_in,
                              void* d_out, int out_size){
    const float* img  = (const float*)d_in[0];
    const int*   seg  = (const int*)d_in[1];
    const float* cent = (const float*)d_in[2];
    const float* w1   = (const float*)d_in[3];
    const float* w2   = (const float*)d_in[4];
    const float* w3   = (const float*)d_in[5];
    const float* pw1  = (const float*)d_in[6];
    const float* pb1  = (const float*)d_in[7];
    const float* pw2  = (const float*)d_in[8];
    const float* pb2  = (const float*)d_in[9];
    float* out = (float*)d_out;

    static cudaStream_t sB = nullptr;
    static cudaEvent_t  e0 = nullptr, e1 = nullptr;
    if (!sB){
        cudaStreamCreateWithFlags(&sB, cudaStreamNonBlocking);
        cudaEventCreateWithFlags(&e0, cudaEventDisableTiming);
        cudaEventCreateWithFlags(&e1, cudaEventDisableTiming);
    }

    cudaFuncSetAttribute(k_conv2,
                         cudaFuncAttributeMaxDynamicSharedMemorySize, C2_SMEM);
    cudaFuncSetAttribute(k_conv3pool,
                         cudaFuncAttributeMaxDynamicSharedMemorySize, C3_SMEM);

    // fork: stream B handles segment sort + positional MLP
    cudaEventRecord(e0, 0);
    cudaStreamWaitEvent(sB, e0, 0);

    // stream 0: conv chain
    k_conv1<<<dim3(196,4), 256>>>(img, w1);
    k_conv2<<<dim3(7,14,4), 256, C2_SMEM>>>(w2);

    // stream B: sort chain + pos (independent of conv)
    k_zero<<<1, 1024, 0, sB>>>();
    k_hist<<<dim3(49,4), 256, 0, sB>>>(seg);
    k_scan<<<1, 1024, 0, sB>>>();
    k_scatter<<<dim3(196,4), 256, 0, sB>>>(seg);
    k_pos<<<64, 256, 0, sB>>>(cent, pw1, pb1, pw2, pb2, out + (size_t)BB*SS*EE);
    cudaEventRecord(e1, sB);

    // join: conv3pool needs conv2 (stream order) + sort results (event)
    cudaStreamWaitEvent(0, e1, 0);
    k_conv3pool<<<256, 256, C3_SMEM>>>(w3, out);
}

// round 12
// speedup vs baseline: 9.6966x; 1.0365x over previous
#include <cuda_runtime.h>
#include <cuda_fp16.h>
#include <cstdint>

typedef unsigned long long ull;

#define BB 4
#define HH 224
#define WL 224
#define HW 50176
#define NC 64
#define EE 768
#define SS 256

// ---- scratch ----
__device__ __half g_h1[BB*HW*64];    // conv1 output, PIXEL-MAJOR fp16 [b][pix][ci]
__device__ __half g_h2[BB*HW*64];    // conv2 output, PIXEL-MAJOR fp16 [b][pix][ci]
__device__ int   g_cnt[BB*SS];
__device__ int   g_off[BB*SS];
__device__ int   g_cur[BB*SS];
__device__ int   g_order[BB*HW];

// ---- packed fp32x2 helpers ----
__device__ __forceinline__ ull pack2(float a, float b){
    ull d; asm("mov.b64 %0,{%1,%2};" : "=l"(d) : "f"(a), "f"(b)); return d;
}
__device__ __forceinline__ void ffma2(ull& d, ull a, ull b){
    asm("fma.rn.f32x2 %0,%1,%2,%0;" : "+l"(d) : "l"(a), "l"(b));
}
__device__ __forceinline__ float2 unpack2(ull d){
    float2 f; asm("mov.b64 {%0,%1},%2;" : "=f"(f.x), "=f"(f.y) : "l"(d)); return f;
}

__device__ __forceinline__ uint32_t smem_u32(const void* p){
    uint32_t a;
    asm("{ .reg .u64 t; cvta.to.shared.u64 t, %1; cvt.u32.u64 %0, t; }" : "=r"(a) : "l"(p));
    return a;
}
__device__ __forceinline__ uint32_t sw128(uint32_t off){ return off ^ ((off >> 3) & 0x70); }

// ---- cp.async (LDGSTS) helpers ----
__device__ __forceinline__ void cp_async16(uint32_t dst, const void* src, bool valid){
    int sz = valid ? 16 : 0;
    asm volatile("cp.async.cg.shared.global [%0], [%1], 16, %2;"
                 :: "r"(dst), "l"(src), "r"(sz));
}
#define CP_COMMIT() asm volatile("cp.async.commit_group;" ::: "memory")
#define CP_WAIT(n)  asm volatile("cp.async.wait_group %0;" :: "n"(n) : "memory")

// ---- mma.sync fp16 helpers (sm_80 PTX, works on compute_100) ----
__device__ __forceinline__ void ldsm_x4(uint32_t* r, uint32_t a){
    asm volatile("ldmatrix.sync.aligned.m8n8.x4.shared.b16 {%0,%1,%2,%3}, [%4];"
        : "=r"(r[0]),"=r"(r[1]),"=r"(r[2]),"=r"(r[3]) : "r"(a));
}
__device__ __forceinline__ void ldsm_x2(uint32_t* r, uint32_t a){
    asm volatile("ldmatrix.sync.aligned.m8n8.x2.shared.b16 {%0,%1}, [%2];"
        : "=r"(r[0]),"=r"(r[1]) : "r"(a));
}
__device__ __forceinline__ void mma_fp16(float* d, const uint32_t* a, const uint32_t* b){
    asm volatile("mma.sync.aligned.m16n8k16.row.col.f32.f16.f16.f32 "
        "{%0,%1,%2,%3}, {%4,%5,%6,%7}, {%8,%9}, {%0,%1,%2,%3};"
        : "+f"(d[0]),"+f"(d[1]),"+f"(d[2]),"+f"(d[3])
        : "r"(a[0]),"r"(a[1]),"r"(a[2]),"r"(a[3]), "r"(b[0]),"r"(b[1]));
}

// ================= zero counters ============================================
__global__ void k_zero(){
    int t = threadIdx.x;
    g_cnt[t] = 0; g_cur[t] = 0;
}

// ================= conv1: 3->64 3x3 relu, f32x2 packed, fp16 pixel-major ====
__global__ __launch_bounds__(256) void k_conv1(const float* __restrict__ img,
                                               const float* __restrict__ w1){
    __shared__ ull ws[32*28];
    int tid = threadIdx.x;
    for (int i = tid; i < 32*28; i += 256){
        int cp = i / 28, t = i % 28;
        ws[i] = (t < 27) ? pack2(w1[(2*cp)*27+t], w1[(2*cp+1)*27+t]) : 0ULL;
    }
    __syncthreads();
    int b = blockIdx.y;
    int p = blockIdx.x*256 + tid;
    int y = p / WL, x = p % WL;
    ull vp[28];
#pragma unroll
    for (int ci = 0; ci < 3; ci++)
#pragma unroll
    for (int ky = 0; ky < 3; ky++)
#pragma unroll
    for (int kx = 0; kx < 3; kx++){
        int yy = y + ky - 1, xx = x + kx - 1;
        float val = 0.f;
        if (yy >= 0 && yy < HH && xx >= 0 && xx < WL)
            val = img[(size_t)(b*3+ci)*HW + yy*WL + xx];
        vp[ci*9 + ky*3 + kx] = pack2(val, val);
    }
    vp[27] = 0ULL;
    uint32_t pk[32];
#pragma unroll 2
    for (int cp = 0; cp < 32; cp++){
        ull acc = 0ULL;
        const ulonglong2* wp = (const ulonglong2*)&ws[cp*28];
#pragma unroll
        for (int tp = 0; tp < 14; tp++){
            ulonglong2 w = wp[tp];
            ffma2(acc, vp[2*tp],   w.x);
            ffma2(acc, vp[2*tp+1], w.y);
        }
        float2 r = unpack2(acc);
        __half2 h = __floats2half2_rn(fmaxf(r.x,0.f), fmaxf(r.y,0.f));
        pk[cp] = *(uint32_t*)&h;
    }
    uint4* dst = (uint4*)(g_h1 + ((size_t)b*HW + p)*64);
#pragma unroll
    for (int j = 0; j < 8; j++)
        dst[j] = make_uint4(pk[4*j], pk[4*j+1], pk[4*j+2], pk[4*j+3]);
}

// ================= conv2: persistent + cp.async double-buffered =============
// Grid = 148 CTAs (one wave, 1/SM). Weights (72KB) staged ONCE per CTA; each
// CTA loops over its ~3 tiles (392 total = 7x x 14y x 4b) with two 76.5KB
// feature buffers: issue cp.async for tile i+1, wait_group 1, compute tile i.
// Zfill cp.async handles the halo. smem = 72 + 2*76.5 = 225KB.
#define C2_WS 0
#define C2_F0 73728
#define C2_F1 152064
#define C2_SMEM 230400
#define C2_TILES 392
#define C2_GRID 148

__device__ __forceinline__ void c2_stage(uint32_t sb, uint32_t foff, int tt, int tid){
    int b  = tt / 98;
    int rem = tt - b*98;
    int y0 = (rem / 7) * 16;
    int x0 = (rem - (rem/7)*7) * 32;
    const __half* src = g_h1 + (size_t)b*HW*64;
    for (int lin = tid; lin < 612*8; lin += 256){
        int slot = lin >> 3, part = lin & 7;
        int gy = y0 + slot/34 - 1, gx = x0 + (slot%34) - 1;
        bool v = (gy >= 0 && gy < HH && gx >= 0 && gx < WL);
        const void* s = v ? (const void*)(src + ((size_t)gy*WL + gx)*64 + part*8)
                          : (const void*)src;
        cp_async16(sb + foff + sw128((uint32_t)(slot*128 + part*16)), s, v);
    }
}

__device__ __forceinline__ void c2_compute(uint32_t sb, uint32_t foff, int tt,
                                           int wid, int lane){
    int b  = tt / 98;
    int rem = tt - b*98;
    int y0 = (rem / 7) * 16;
    int x0 = (rem - (rem/7)*7) * 32;
    __half* dsth = g_h2 + (size_t)b*HW*64;

    int rowA = lane & 15, chA = lane >> 4;
    int rowB8 = lane & 7, chB = (lane>>3)&1, grpB = lane>>4;

#pragma unroll 1
    for (int half = 0; half < 2; half++){
        float acc[2][8][4];
#pragma unroll
        for (int mx = 0; mx < 2; mx++)
#pragma unroll
        for (int nt = 0; nt < 8; nt++)
#pragma unroll
        for (int q = 0; q < 4; q++) acc[mx][nt][q] = 0.f;

        int ty = half*8 + wid;
#pragma unroll 1
        for (int pass = 0; pass < 9; pass++){
            int ky = pass / 3, kx = pass - ky*3;
            uint32_t wbase = sb + C2_WS + pass*8192;
            uint32_t bf[8][4][2];
#pragma unroll
            for (int kt = 0; kt < 4; kt++)
#pragma unroll
            for (int ntp = 0; ntp < 4; ntp++){
                uint32_t r[4];
                uint32_t a = wbase + sw128((uint32_t)(((ntp*2 + grpB)*8 + rowB8)*128 + kt*32 + chB*16));
                ldsm_x4(r, a);
                bf[2*ntp][kt][0]   = r[0]; bf[2*ntp][kt][1]   = r[1];
                bf[2*ntp+1][kt][0] = r[2]; bf[2*ntp+1][kt][1] = r[3];
            }
#pragma unroll
            for (int mx = 0; mx < 2; mx++){
                int slot = (ty + ky)*34 + mx*16 + rowA + kx;
                uint32_t af[4][4];
#pragma unroll
                for (int kt = 0; kt < 4; kt++)
                    ldsm_x4(af[kt], sb + foff + sw128((uint32_t)(slot*128 + kt*32 + chA*16)));
#pragma unroll
                for (int nt = 0; nt < 8; nt++)
#pragma unroll
                for (int kt = 0; kt < 4; kt++)
                    mma_fp16(acc[mx][nt], af[kt], bf[nt][kt]);
            }
        }
        int gy = y0 + ty;
#pragma unroll
        for (int mx = 0; mx < 2; mx++){
            int px = x0 + mx*16 + (lane>>2);
            size_t base0 = ((size_t)gy*WL + px)*64;
            size_t base1 = ((size_t)gy*WL + px + 8)*64;
#pragma unroll
            for (int nt = 0; nt < 8; nt++){
                int co = nt*8 + (lane&3)*2;
                __half2 u0 = __floats2half2_rn(fmaxf(acc[mx][nt][0],0.f), fmaxf(acc[mx][nt][1],0.f));
                __half2 u1 = __floats2half2_rn(fmaxf(acc[mx][nt][2],0.f), fmaxf(acc[mx][nt][3],0.f));
                *(uint32_t*)(dsth + base0 + co) = *(uint32_t*)&u0;
                *(uint32_t*)(dsth + base1 + co) = *(uint32_t*)&u1;
            }
        }
    }
}

__global__ __launch_bounds__(256) void k_conv2(const float* __restrict__ w2){
    extern __shared__ __align__(1024) char sm[];
    uint32_t sb = smem_u32(sm);
    int tid = threadIdx.x, wid = tid>>5, lane = tid&31;

    // ---- stage weights once: coalesced linear read, scatter STS.16 ----
    for (int lin = tid; lin < 64*64*9; lin += 256){
        float v = w2[lin];
        int co = lin / 576;
        int rem = lin - co*576;
        int ci = rem / 9;
        int k  = rem - ci*9;
        __half hv = __float2half_rn(v);
        *(__half*)(sm + C2_WS + k*8192 + sw128((uint32_t)(co*128 + ci*2))) = hv;
    }

    // my tiles: blockIdx.x, +148, +296
    int t0 = blockIdx.x;
    int n = 0;
    int tiles[3];
    for (int tt = t0; tt < C2_TILES; tt += C2_GRID) tiles[n++] = tt;
    if (n == 0) return;

    const uint32_t foff[2] = {C2_F0, C2_F1};

    // prologue: stage tile 0
    c2_stage(sb, foff[0], tiles[0], tid);
    CP_COMMIT();

    for (int k = 0; k < n; k++){
        if (k + 1 < n){
            c2_stage(sb, foff[(k+1)&1], tiles[k+1], tid);
            CP_COMMIT();
            CP_WAIT(1);          // current tile's group done, next in flight
        } else {
            CP_WAIT(0);
        }
        __syncthreads();          // staged data + weights visible to all
        c2_compute(sb, foff[k&1], tiles[k], wid, lane);
        __syncthreads();          // compute reads done before restaging buffer
    }
}

// ================= segment counting sort ====================================
__global__ __launch_bounds__(256) void k_hist(const int* __restrict__ seg){
    __shared__ int hist[SS];
    int tid = threadIdx.x;
    hist[tid] = 0;
    __syncthreads();
    int b = blockIdx.y;
    int base = blockIdx.x * 1024;
#pragma unroll
    for (int i = 0; i < 4; i++){
        int s = seg[(size_t)b*HW + base + i*256 + tid];
        atomicAdd(&hist[s], 1);
    }
    __syncthreads();
    atomicAdd(&g_cnt[b*SS + tid], hist[tid]);
}

__global__ void k_scan(){
    __shared__ int s[1024];
    int t = threadIdx.x;
    int v = g_cnt[t];
    s[t] = v;
    __syncthreads();
    for (int d = 1; d < 1024; d <<= 1){
        int add = (t >= d) ? s[t-d] : 0;
        __syncthreads();
        s[t] += add;
        __syncthreads();
    }
    g_off[t] = s[t] - v;
}

__global__ __launch_bounds__(256) void k_scatter(const int* __restrict__ seg){
    int b = blockIdx.y;
    int p = blockIdx.x*256 + threadIdx.x;
    int sgm = seg[(size_t)b*HW + p];
    int bin = b*SS + sgm;
    int idx = atomicAdd(&g_cur[bin], 1);
    g_order[g_off[bin] + idx] = p;
}

// ================= conv3+pool via mma.sync fp16 (persistent) ================
#define W_OFF 0
#define F_OFF 98304
#define C3_SMEM 114688
#define C3_BINS 4
__global__ __launch_bounds__(256, 2) void k_conv3pool(const float* __restrict__ w3,
                                                      float* __restrict__ out){
    extern __shared__ __align__(1024) char sm[];
    int tid  = threadIdx.x;
    int wid  = tid >> 5;
    int lane = tid & 31;
    uint32_t sbase = smem_u32(sm);

    // ---- stage W once: rows e = tid, tid+256, tid+512 ----
#pragma unroll
    for (int rr = 0; rr < 3; rr++){
        int e = tid + rr*256;
        const float4* wrow = (const float4*)(w3 + (size_t)e*64);
#pragma unroll
        for (int k = 0; k < 16; k++){
            float4 f4 = wrow[k];
            __half2 h0 = __float22half2_rn(make_float2(f4.x, f4.y));
            __half2 h1 = __float22half2_rn(make_float2(f4.z, f4.w));
            uint2 u; u.x = *(uint32_t*)&h0; u.y = *(uint32_t*)&h1;
            *(uint2*)(sm + W_OFF + sw128((uint32_t)(e*128 + k*8))) = u;
        }
    }

    int rowA = lane & 15, chA = lane >> 4;
    int rowB = lane & 7,  chB = (lane >> 3) & 1;
    int r  = tid >> 1;
    int h  = tid & 1;

#pragma unroll 1
    for (int bi = 0; bi < C3_BINS; bi++){
        int bin  = blockIdx.x + bi*256;
        int b    = bin >> 8;
        int npix = g_cnt[bin];
        int off  = g_off[bin];
        const __half* featb = g_h2 + (size_t)b*HW*64;

        float acc[6][2];
#pragma unroll
        for (int i = 0; i < 6; i++){ acc[i][0] = 0.f; acc[i][1] = 0.f; }

        int ntiles = (npix + 127) >> 7;

        for (int t = 0; t < ntiles; t++){
            int rem = npix - t*128; if (rem > 128) rem = 128;
            int ntcN = (rem + 31) >> 5;
            __syncthreads();
            if (r < ntcN*32){
                int idx = t*128 + r;
                if (idx < npix){
                    int pix = g_order[off + idx];
                    const uint4* fp = (const uint4*)(featb + (size_t)pix*64 + h*32);
#pragma unroll
                    for (int j = 0; j < 4; j++)
                        *(uint4*)(sm + F_OFF + sw128((uint32_t)(r*128 + h*64 + j*16))) = fp[j];
                } else {
                    uint4 z = make_uint4(0,0,0,0);
#pragma unroll
                    for (int j = 0; j < 4; j++)
                        *(uint4*)(sm + F_OFF + sw128((uint32_t)(r*128 + h*64 + j*16))) = z;
                }
            }
            __syncthreads();

#pragma unroll 1
            for (int ntc = 0; ntc < ntcN; ntc++){
                uint32_t bf[4][4][2];
#pragma unroll
                for (int j = 0; j < 4; j++){
                    int px = (ntc*4 + j)*8 + rowB;
#pragma unroll
                    for (int kt = 0; kt < 4; kt++){
                        uint32_t a = sbase + F_OFF + sw128((uint32_t)(px*128 + kt*32 + chB*16));
                        ldsm_x2(bf[j][kt], a);
                    }
                }
#pragma unroll 1
                for (int i = 0; i < 6; i++){
                    int e0 = (wid*6 + i)*16;
                    uint32_t af[4][4];
#pragma unroll
                    for (int kt = 0; kt < 4; kt++){
                        uint32_t a = sbase + W_OFF + sw128((uint32_t)((e0 + rowA)*128 + kt*32 + chA*16));
                        ldsm_x4(af[kt], a);
                    }
                    float d[4][4];
#pragma unroll
                    for (int j = 0; j < 4; j++)
#pragma unroll
                    for (int q = 0; q < 4; q++) d[j][q] = 0.f;
#pragma unroll
                    for (int kt = 0; kt < 4; kt++)
#pragma unroll
                    for (int j = 0; j < 4; j++)
                        mma_fp16(d[j], af[kt], bf[j][kt]);
#pragma unroll
                    for (int j = 0; j < 4; j++){
                        acc[i][0] += fmaxf(d[j][0], 0.f) + fmaxf(d[j][1], 0.f);
                        acc[i][1] += fmaxf(d[j][2], 0.f) + fmaxf(d[j][3], 0.f);
                    }
                }
            }
        }

        float inv = 1.f / (float)max(npix, 1);
#pragma unroll
        for (int i = 0; i < 6; i++){
            acc[i][0] += __shfl_xor_sync(0xffffffffu, acc[i][0], 1);
            acc[i][0] += __shfl_xor_sync(0xffffffffu, acc[i][0], 2);
            acc[i][1] += __shfl_xor_sync(0xffffffffu, acc[i][1], 1);
            acc[i][1] += __shfl_xor_sync(0xffffffffu, acc[i][1], 2);
        }
        if ((lane & 3) == 0){
            int row = lane >> 2;
            float* ob = out + (size_t)bin*EE;
#pragma unroll
            for (int i = 0; i < 6; i++){
                int e = (wid*6 + i)*16 + row;
                ob[e]     = acc[i][0] * inv;
                ob[e + 8] = acc[i][1] * inv;
            }
        }
    }
}

// ================= positional MLP ===========================================
__global__ __launch_bounds__(256) void k_pos(const float* __restrict__ cent,
        const float* __restrict__ w1, const float* __restrict__ b1,
        const float* __restrict__ w2, const float* __restrict__ b2,
        float* __restrict__ out){
    __shared__ __align__(8) float h2[384*16];
    int tid = threadIdx.x;
    int rb = blockIdx.x * 16;
    for (int lin = tid; lin < 6144; lin += 256){
        int j = lin >> 4, r = lin & 15;
        int rid = rb + r;
        float c0 = cent[rid*2+0] * (1.f/223.f);
        float c1 = cent[rid*2+1] * (1.f/223.f);
        float h = fmaxf(fmaf(c0, w1[j], fmaf(c1, w1[384+j], b1[j])), 0.f);
        h2[j*16 + r] = h;
    }
    __syncthreads();
    ull acc[3][8];
#pragma unroll
    for (int es = 0; es < 3; es++)
#pragma unroll
    for (int q = 0; q < 8; q++) acc[es][q] = 0ULL;
    for (int j = 0; j < 384; j++){
        ull hp[8];
#pragma unroll
        for (int q = 0; q < 8; q++) hp[q] = *(const ull*)&h2[j*16 + 2*q];
#pragma unroll
        for (int es = 0; es < 3; es++){
            float wv = w2[j*768 + tid + es*256];
            ull wp = pack2(wv, wv);
#pragma unroll
            for (int q = 0; q < 8; q++) ffma2(acc[es][q], hp[q], wp);
        }
    }
#pragma unroll
    for (int es = 0; es < 3; es++){
        int e = tid + es*256;
        float bv = b2[e];
#pragma unroll
        for (int q = 0; q < 8; q++){
            float2 v = unpack2(acc[es][q]);
            int rid = rb + 2*q;
            out[(size_t)rid*768 + e]     = v.x + bv;
            out[(size_t)(rid+1)*768 + e] = v.y + bv;
        }
    }
}

// ================= launcher (two-stream fork/join inside graph capture) =====
extern "C" void kernel_launch(void* const* d_in, const int* in_sizes, int n_in,
                              void* d_out, int out_size){
    const float* img  = (const float*)d_in[0];
    const int*   seg  = (const int*)d_in[1];
    const float* cent = (const float*)d_in[2];
    const float* w1   = (const float*)d_in[3];
    const float* w2   = (const float*)d_in[4];
    const float* w3   = (const float*)d_in[5];
    const float* pw1  = (const float*)d_in[6];
    const float* pb1  = (const float*)d_in[7];
    const float* pw2  = (const float*)d_in[8];
    const float* pb2  = (const float*)d_in[9];
    float* out = (float*)d_out;

    static cudaStream_t sB = nullptr;
    static cudaEvent_t  e0 = nullptr, e1 = nullptr;
    if (!sB){
        cudaStreamCreateWithFlags(&sB, cudaStreamNonBlocking);
        cudaEventCreateWithFlags(&e0, cudaEventDisableTiming);
        cudaEventCreateWithFlags(&e1, cudaEventDisableTiming);
    }

    cudaFuncSetAttribute(k_conv2,
                         cudaFuncAttributeMaxDynamicSharedMemorySize, C2_SMEM);
    cudaFuncSetAttribute(k_conv3pool,
                         cudaFuncAttributeMaxDynamicSharedMemorySize, C3_SMEM);

    // fork: stream B handles segment sort + positional MLP
    cudaEventRecord(e0, 0);
    cudaStreamWaitEvent(sB, e0, 0);

    // stream 0: conv chain
    k_conv1<<<dim3(196,4), 256>>>(img, w1);
    k_conv2<<<C2_GRID, 256, C2_SMEM>>>(w2);

    // stream B: sort chain + pos (independent of conv)
    k_zero<<<1, 1024, 0, sB>>>();
    k_hist<<<dim3(49,4), 256, 0, sB>>>(seg);
    k_scan<<<1, 1024, 0, sB>>>();
    k_scatter<<<dim3(196,4), 256, 0, sB>>>(seg);
    k_pos<<<64, 256, 0, sB>>>(cent, pw1, pb1, pw2, pb2, out + (size_t)BB*SS*EE);
    cudaEventRecord(e1, sB);

    // join: conv3pool needs conv2 (stream order) + sort results (event)
    cudaStreamWaitEvent(0, e1, 0);
    k_conv3pool<<<256, 256, C3_SMEM>>>(w3, out);
}

// round 13
// speedup vs baseline: 10.5587x; 1.0889x over previous
#include <cuda_runtime.h>
#include <cuda_fp16.h>
#include <cstdint>

typedef unsigned long long ull;

#define BB 4
#define HH 224
#define WL 224
#define HW 50176
#define NC 64
#define EE 768
#define SS 256

// ---- scratch ----
__device__ __half g_h1[BB*HW*64];    // conv1 output, PIXEL-MAJOR fp16 [b][pix][ci]
__device__ __half g_h2[BB*HW*64];    // conv2 output, PIXEL-MAJOR fp16 [b][pix][ci]
__device__ int   g_cnt[BB*SS];
__device__ int   g_off[BB*SS];
__device__ int   g_cur[BB*SS];
__device__ int   g_order[BB*HW];

// ---- packed fp32x2 helpers ----
__device__ __forceinline__ ull pack2(float a, float b){
    ull d; asm("mov.b64 %0,{%1,%2};" : "=l"(d) : "f"(a), "f"(b)); return d;
}
__device__ __forceinline__ void ffma2(ull& d, ull a, ull b){
    asm("fma.rn.f32x2 %0,%1,%2,%0;" : "+l"(d) : "l"(a), "l"(b));
}
__device__ __forceinline__ float2 unpack2(ull d){
    float2 f; asm("mov.b64 {%0,%1},%2;" : "=f"(f.x), "=f"(f.y) : "l"(d)); return f;
}

__device__ __forceinline__ uint32_t smem_u32(const void* p){
    uint32_t a;
    asm("{ .reg .u64 t; cvta.to.shared.u64 t, %1; cvt.u32.u64 %0, t; }" : "=r"(a) : "l"(p));
    return a;
}
__device__ __forceinline__ uint32_t sw128(uint32_t off){ return off ^ ((off >> 3) & 0x70); }

// ---- cp.async (LDGSTS) helpers ----
__device__ __forceinline__ void cp_async16(uint32_t dst, const void* src, bool valid){
    int sz = valid ? 16 : 0;
    asm volatile("cp.async.cg.shared.global [%0], [%1], 16, %2;"
                 :: "r"(dst), "l"(src), "r"(sz));
}
#define CP_COMMIT() asm volatile("cp.async.commit_group;" ::: "memory")
#define CP_WAIT(n)  asm volatile("cp.async.wait_group %0;" :: "n"(n) : "memory")

// ---- mma.sync fp16 helpers (sm_80 PTX, works on compute_100) ----
__device__ __forceinline__ void ldsm_x4(uint32_t* r, uint32_t a){
    asm volatile("ldmatrix.sync.aligned.m8n8.x4.shared.b16 {%0,%1,%2,%3}, [%4];"
        : "=r"(r[0]),"=r"(r[1]),"=r"(r[2]),"=r"(r[3]) : "r"(a));
}
__device__ __forceinline__ void ldsm_x2(uint32_t* r, uint32_t a){
    asm volatile("ldmatrix.sync.aligned.m8n8.x2.shared.b16 {%0,%1}, [%2];"
        : "=r"(r[0]),"=r"(r[1]) : "r"(a));
}
__device__ __forceinline__ void mma_fp16(float* d, const uint32_t* a, const uint32_t* b){
    asm volatile("mma.sync.aligned.m16n8k16.row.col.f32.f16.f16.f32 "
        "{%0,%1,%2,%3}, {%4,%5,%6,%7}, {%8,%9}, {%0,%1,%2,%3};"
        : "+f"(d[0]),"+f"(d[1]),"+f"(d[2]),"+f"(d[3])
        : "r"(a[0]),"r"(a[1]),"r"(a[2]),"r"(a[3]), "r"(b[0]),"r"(b[1]));
}

// ================= zero counters ============================================
__global__ void k_zero(){
    int t = threadIdx.x;
    g_cnt[t] = 0; g_cur[t] = 0;
}

// ================= conv1: 3->64 3x3 relu, f32x2 packed, fp16 pixel-major ====
__global__ __launch_bounds__(256) void k_conv1(const float* __restrict__ img,
                                               const float* __restrict__ w1){
    __shared__ ull ws[32*28];
    int tid = threadIdx.x;
    for (int i = tid; i < 32*28; i += 256){
        int cp = i / 28, t = i % 28;
        ws[i] = (t < 27) ? pack2(w1[(2*cp)*27+t], w1[(2*cp+1)*27+t]) : 0ULL;
    }
    __syncthreads();
    int b = blockIdx.y;
    int p = blockIdx.x*256 + tid;
    int y = p / WL, x = p % WL;
    ull vp[28];
#pragma unroll
    for (int ci = 0; ci < 3; ci++)
#pragma unroll
    for (int ky = 0; ky < 3; ky++)
#pragma unroll
    for (int kx = 0; kx < 3; kx++){
        int yy = y + ky - 1, xx = x + kx - 1;
        float val = 0.f;
        if (yy >= 0 && yy < HH && xx >= 0 && xx < WL)
            val = img[(size_t)(b*3+ci)*HW + yy*WL + xx];
        vp[ci*9 + ky*3 + kx] = pack2(val, val);
    }
    vp[27] = 0ULL;
    uint32_t pk[32];
#pragma unroll 2
    for (int cp = 0; cp < 32; cp++){
        ull acc = 0ULL;
        const ulonglong2* wp = (const ulonglong2*)&ws[cp*28];
#pragma unroll
        for (int tp = 0; tp < 14; tp++){
            ulonglong2 w = wp[tp];
            ffma2(acc, vp[2*tp],   w.x);
            ffma2(acc, vp[2*tp+1], w.y);
        }
        float2 r = unpack2(acc);
        __half2 h = __floats2half2_rn(fmaxf(r.x,0.f), fmaxf(r.y,0.f));
        pk[cp] = *(uint32_t*)&h;
    }
    uint4* dst = (uint4*)(g_h1 + ((size_t)b*HW + p)*64);
#pragma unroll
    for (int j = 0; j < 8; j++)
        dst[j] = make_uint4(pk[4*j], pk[4*j+1], pk[4*j+2], pk[4*j+3]);
}

// ================= conv2: persistent + cp.async double-buffered =============
#define C2_WS 0
#define C2_F0 73728
#define C2_F1 152064
#define C2_SMEM 230400
#define C2_TILES 392
#define C2_GRID 148

__device__ __forceinline__ void c2_stage(uint32_t sb, uint32_t foff, int tt, int tid){
    int b  = tt / 98;
    int rem = tt - b*98;
    int y0 = (rem / 7) * 16;
    int x0 = (rem - (rem/7)*7) * 32;
    const __half* src = g_h1 + (size_t)b*HW*64;
    for (int lin = tid; lin < 612*8; lin += 256){
        int slot = lin >> 3, part = lin & 7;
        int gy = y0 + slot/34 - 1, gx = x0 + (slot%34) - 1;
        bool v = (gy >= 0 && gy < HH && gx >= 0 && gx < WL);
        const void* s = v ? (const void*)(src + ((size_t)gy*WL + gx)*64 + part*8)
                          : (const void*)src;
        cp_async16(sb + foff + sw128((uint32_t)(slot*128 + part*16)), s, v);
    }
}

__device__ __forceinline__ void c2_compute(uint32_t sb, uint32_t foff, int tt,
                                           int wid, int lane){
    int b  = tt / 98;
    int rem = tt - b*98;
    int y0 = (rem / 7) * 16;
    int x0 = (rem - (rem/7)*7) * 32;
    __half* dsth = g_h2 + (size_t)b*HW*64;

    int rowA = lane & 15, chA = lane >> 4;
    int rowB8 = lane & 7, chB = (lane>>3)&1, grpB = lane>>4;

#pragma unroll 1
    for (int half = 0; half < 2; half++){
        float acc[2][8][4];
#pragma unroll
        for (int mx = 0; mx < 2; mx++)
#pragma unroll
        for (int nt = 0; nt < 8; nt++)
#pragma unroll
        for (int q = 0; q < 4; q++) acc[mx][nt][q] = 0.f;

        int ty = half*8 + wid;
#pragma unroll 1
        for (int pass = 0; pass < 9; pass++){
            int ky = pass / 3, kx = pass - ky*3;
            uint32_t wbase = sb + C2_WS + pass*8192;
            uint32_t bf[8][4][2];
#pragma unroll
            for (int kt = 0; kt < 4; kt++)
#pragma unroll
            for (int ntp = 0; ntp < 4; ntp++){
                uint32_t r[4];
                uint32_t a = wbase + sw128((uint32_t)(((ntp*2 + grpB)*8 + rowB8)*128 + kt*32 + chB*16));
                ldsm_x4(r, a);
                bf[2*ntp][kt][0]   = r[0]; bf[2*ntp][kt][1]   = r[1];
                bf[2*ntp+1][kt][0] = r[2]; bf[2*ntp+1][kt][1] = r[3];
            }
#pragma unroll
            for (int mx = 0; mx < 2; mx++){
                int slot = (ty + ky)*34 + mx*16 + rowA + kx;
                uint32_t af[4][4];
#pragma unroll
                for (int kt = 0; kt < 4; kt++)
                    ldsm_x4(af[kt], sb + foff + sw128((uint32_t)(slot*128 + kt*32 + chA*16)));
#pragma unroll
                for (int nt = 0; nt < 8; nt++)
#pragma unroll
                for (int kt = 0; kt < 4; kt++)
                    mma_fp16(acc[mx][nt], af[kt], bf[nt][kt]);
            }
        }
        int gy = y0 + ty;
#pragma unroll
        for (int mx = 0; mx < 2; mx++){
            int px = x0 + mx*16 + (lane>>2);
            size_t base0 = ((size_t)gy*WL + px)*64;
            size_t base1 = ((size_t)gy*WL + px + 8)*64;
#pragma unroll
            for (int nt = 0; nt < 8; nt++){
                int co = nt*8 + (lane&3)*2;
                __half2 u0 = __floats2half2_rn(fmaxf(acc[mx][nt][0],0.f), fmaxf(acc[mx][nt][1],0.f));
                __half2 u1 = __floats2half2_rn(fmaxf(acc[mx][nt][2],0.f), fmaxf(acc[mx][nt][3],0.f));
                *(uint32_t*)(dsth + base0 + co) = *(uint32_t*)&u0;
                *(uint32_t*)(dsth + base1 + co) = *(uint32_t*)&u1;
            }
        }
    }
}

__global__ __launch_bounds__(256) void k_conv2(const float* __restrict__ w2){
    extern __shared__ __align__(1024) char sm[];
    uint32_t sb = smem_u32(sm);
    int tid = threadIdx.x, wid = tid>>5, lane = tid&31;

    for (int lin = tid; lin < 64*64*9; lin += 256){
        float v = w2[lin];
        int co = lin / 576;
        int rem = lin - co*576;
        int ci = rem / 9;
        int k  = rem - ci*9;
        __half hv = __float2half_rn(v);
        *(__half*)(sm + C2_WS + k*8192 + sw128((uint32_t)(co*128 + ci*2))) = hv;
    }

    int t0 = blockIdx.x;
    int n = 0;
    int tiles[3];
    for (int tt = t0; tt < C2_TILES; tt += C2_GRID) tiles[n++] = tt;
    if (n == 0) return;

    const uint32_t foff[2] = {C2_F0, C2_F1};

    c2_stage(sb, foff[0], tiles[0], tid);
    CP_COMMIT();

    for (int k = 0; k < n; k++){
        if (k + 1 < n){
            c2_stage(sb, foff[(k+1)&1], tiles[k+1], tid);
            CP_COMMIT();
            CP_WAIT(1);
        } else {
            CP_WAIT(0);
        }
        __syncthreads();
        c2_compute(sb, foff[k&1], tiles[k], wid, lane);
        __syncthreads();
    }
}

// ================= segment counting sort ====================================
__global__ __launch_bounds__(256) void k_hist(const int* __restrict__ seg){
    __shared__ int hist[SS];
    int tid = threadIdx.x;
    hist[tid] = 0;
    __syncthreads();
    int b = blockIdx.y;
    int base = blockIdx.x * 1024;
#pragma unroll
    for (int i = 0; i < 4; i++){
        int s = seg[(size_t)b*HW + base + i*256 + tid];
        atomicAdd(&hist[s], 1);
    }
    __syncthreads();
    atomicAdd(&g_cnt[b*SS + tid], hist[tid]);
}

__global__ void k_scan(){
    __shared__ int s[1024];
    int t = threadIdx.x;
    int v = g_cnt[t];
    s[t] = v;
    __syncthreads();
    for (int d = 1; d < 1024; d <<= 1){
        int add = (t >= d) ? s[t-d] : 0;
        __syncthreads();
        s[t] += add;
        __syncthreads();
    }
    g_off[t] = s[t] - v;
}

__global__ __launch_bounds__(256) void k_scatter(const int* __restrict__ seg){
    int b = blockIdx.y;
    int p = blockIdx.x*256 + threadIdx.x;
    int sgm = seg[(size_t)b*HW + p];
    int bin = b*SS + sgm;
    int idx = atomicAdd(&g_cur[bin], 1);
    g_order[g_off[bin] + idx] = p;
}

// ================= conv3+pool: af-resident + cp.async double-buffer =========
// Grid 148, 1 CTA/SM, one wave; bins strided (+148, ~7/CTA). Weight fragments
// af[6][4][4] (96 regs/thread) loaded ONCE per warp -- zero weight LDSM in the
// mainloop. Feature B-frags via paired ldsm_x4 (2 px-tiles/instr). Features
// double-buffered with cp.async zfill. Per 32-px group: 8 LDSM + 96 HMMA.
#define W_OFF 0
#define F3_0  98304
#define F3_1  114688
#define C3_SMEM 131072
#define C3_GRID 148

__device__ __forceinline__ void c3_stage(uint32_t sb, uint32_t foff,
                                         const __half* featb, int off,
                                         int tbase, int npix, int nrows, int tid){
    // nrows px rows to stage (zfill beyond npix); 16B chunks: lin = row*8+part
    for (int lin = tid; lin < nrows*8; lin += 256){
        int r = lin >> 3, part = lin & 7;
        int idx = tbase + r;
        bool v = idx < npix;
        const void* s;
        if (v){
            int pix = g_order[off + idx];
            s = (const void*)(featb + (size_t)pix*64 + part*8);
        } else s = (const void*)featb;
        cp_async16(sb + foff + sw128((uint32_t)(r*128 + part*16)), s, v);
    }
}

__global__ __launch_bounds__(256, 1) void k_conv3pool(const float* __restrict__ w3,
                                                      float* __restrict__ out){
    extern __shared__ __align__(1024) char sm[];
    int tid  = threadIdx.x;
    int wid  = tid >> 5;
    int lane = tid & 31;
    uint32_t sbase = smem_u32(sm);

    // ---- stage W once: rows e = tid, tid+256, tid+512 ----
#pragma unroll
    for (int rr = 0; rr < 3; rr++){
        int e = tid + rr*256;
        const float4* wrow = (const float4*)(w3 + (size_t)e*64);
#pragma unroll
        for (int k = 0; k < 16; k++){
            float4 f4 = wrow[k];
            __half2 h0 = __float22half2_rn(make_float2(f4.x, f4.y));
            __half2 h1 = __float22half2_rn(make_float2(f4.z, f4.w));
            uint2 u; u.x = *(uint32_t*)&h0; u.y = *(uint32_t*)&h1;
            *(uint2*)(sm + W_OFF + sw128((uint32_t)(e*128 + k*8))) = u;
        }
    }
    __syncthreads();

    // ---- load weight fragments into registers ONCE ----
    int rowA = lane & 15, chA = lane >> 4;
    uint32_t af[6][4][4];
#pragma unroll
    for (int i = 0; i < 6; i++){
        int e0 = (wid*6 + i)*16;
#pragma unroll
        for (int kt = 0; kt < 4; kt++)
            ldsm_x4(af[i][kt], sbase + W_OFF + sw128((uint32_t)((e0 + rowA)*128 + kt*32 + chA*16)));
    }

    int rowB = lane & 7, chB = (lane >> 3) & 1, grpB = lane >> 4;
    const uint32_t foff[2] = {F3_0, F3_1};

#pragma unroll 1
    for (int bin = blockIdx.x; bin < BB*SS; bin += C3_GRID){
        int b    = bin >> 8;
        int npix = g_cnt[bin];
        int off  = g_off[bin];
        const __half* featb = g_h2 + (size_t)b*HW*64;

        float acc[6][2];
#pragma unroll
        for (int i = 0; i < 6; i++){ acc[i][0] = 0.f; acc[i][1] = 0.f; }

        int ntiles = (npix + 127) >> 7;

        // prologue: stage tile 0
        {
            int rem0 = npix; if (rem0 > 128) rem0 = 128;
            int nr0 = ((rem0 + 31) >> 5) * 32;
            c3_stage(sbase, foff[0], featb, off, 0, npix, nr0, tid);
            CP_COMMIT();
        }

        for (int t = 0; t < ntiles; t++){
            int rem = npix - t*128; if (rem > 128) rem = 128;
            int ntcN = (rem + 31) >> 5;
            if (t + 1 < ntiles){
                int rem1 = npix - (t+1)*128; if (rem1 > 128) rem1 = 128;
                int nr1 = ((rem1 + 31) >> 5) * 32;
                c3_stage(sbase, foff[(t+1)&1], featb, off, (t+1)*128, npix, nr1, tid);
                CP_COMMIT();
                CP_WAIT(1);
            } else {
                CP_WAIT(0);
            }
            __syncthreads();
            uint32_t fb = sbase + foff[t&1];

#pragma unroll 1
            for (int ntc = 0; ntc < ntcN; ntc++){
                // B-frags: 4 j-tiles via 2 paired ldsm_x4
                uint32_t bf[4][4][2];
#pragma unroll
                for (int kt = 0; kt < 4; kt++)
#pragma unroll
                for (int jp = 0; jp < 2; jp++){
                    uint32_t r[4];
                    int px = (ntc*4 + jp*2 + grpB)*8 + rowB;
                    ldsm_x4(r, fb + sw128((uint32_t)(px*128 + kt*32 + chB*16)));
                    bf[jp*2][kt][0]   = r[0]; bf[jp*2][kt][1]   = r[1];
                    bf[jp*2+1][kt][0] = r[2]; bf[jp*2+1][kt][1] = r[3];
                }
#pragma unroll
                for (int i = 0; i < 6; i++){
                    float d[4][4];
#pragma unroll
                    for (int j = 0; j < 4; j++)
#pragma unroll
                    for (int q = 0; q < 4; q++) d[j][q] = 0.f;
#pragma unroll
                    for (int kt = 0; kt < 4; kt++)
#pragma unroll
                    for (int j = 0; j < 4; j++)
                        mma_fp16(d[j], af[i][kt], bf[j][kt]);
#pragma unroll
                    for (int j = 0; j < 4; j++){
                        acc[i][0] += fmaxf(d[j][0], 0.f) + fmaxf(d[j][1], 0.f);
                        acc[i][1] += fmaxf(d[j][2], 0.f) + fmaxf(d[j][3], 0.f);
                    }
                }
            }
            __syncthreads();   // compute reads done before restaging this buffer
        }

        float inv = 1.f / (float)max(npix, 1);
#pragma unroll
        for (int i = 0; i < 6; i++){
            acc[i][0] += __shfl_xor_sync(0xffffffffu, acc[i][0], 1);
            acc[i][0] += __shfl_xor_sync(0xffffffffu, acc[i][0], 2);
            acc[i][1] += __shfl_xor_sync(0xffffffffu, acc[i][1], 1);
            acc[i][1] += __shfl_xor_sync(0xffffffffu, acc[i][1], 2);
        }
        if ((lane & 3) == 0){
            int row = lane >> 2;
            float* ob = out + (size_t)bin*EE;
#pragma unroll
            for (int i = 0; i < 6; i++){
                int e = (wid*6 + i)*16 + row;
                ob[e]     = acc[i][0] * inv;
                ob[e + 8] = acc[i][1] * inv;
            }
        }
    }
}

// ================= positional MLP ===========================================
__global__ __launch_bounds__(256) void k_pos(const float* __restrict__ cent,
        const float* __restrict__ w1, const float* __restrict__ b1,
        const float* __restrict__ w2, const float* __restrict__ b2,
        float* __restrict__ out){
    __shared__ __align__(8) float h2[384*16];
    int tid = threadIdx.x;
    int rb = blockIdx.x * 16;
    for (int lin = tid; lin < 6144; lin += 256){
        int j = lin >> 4, r = lin & 15;
        int rid = rb + r;
        float c0 = cent[rid*2+0] * (1.f/223.f);
        float c1 = cent[rid*2+1] * (1.f/223.f);
        float h = fmaxf(fmaf(c0, w1[j], fmaf(c1, w1[384+j], b1[j])), 0.f);
        h2[j*16 + r] = h;
    }
    __syncthreads();
    ull acc[3][8];
#pragma unroll
    for (int es = 0; es < 3; es++)
#pragma unroll
    for (int q = 0; q < 8; q++) acc[es][q] = 0ULL;
    for (int j = 0; j < 384; j++){
        ull hp[8];
#pragma unroll
        for (int q = 0; q < 8; q++) hp[q] = *(const ull*)&h2[j*16 + 2*q];
#pragma unroll
        for (int es = 0; es < 3; es++){
            float wv = w2[j*768 + tid + es*256];
            ull wp = pack2(wv, wv);
#pragma unroll
            for (int q = 0; q < 8; q++) ffma2(acc[es][q], hp[q], wp);
        }
    }
#pragma unroll
    for (int es = 0; es < 3; es++){
        int e = tid + es*256;
        float bv = b2[e];
#pragma unroll
        for (int q = 0; q < 8; q++){
            float2 v = unpack2(acc[es][q]);
            int rid = rb + 2*q;
            out[(size_t)rid*768 + e]     = v.x + bv;
            out[(size_t)(rid+1)*768 + e] = v.y + bv;
        }
    }
}

// ================= launcher (two-stream fork/join inside graph capture) =====
extern "C" void kernel_launch(void* const* d_in, const int* in_sizes, int n_in,
                              void* d_out, int out_size){
    const float* img  = (const float*)d_in[0];
    const int*   seg  = (const int*)d_in[1];
    const float* cent = (const float*)d_in[2];
    const float* w1   = (const float*)d_in[3];
    const float* w2   = (const float*)d_in[4];
    const float* w3   = (const float*)d_in[5];
    const float* pw1  = (const float*)d_in[6];
    const float* pb1  = (const float*)d_in[7];
    const float* pw2  = (const float*)d_in[8];
    const float* pb2  = (const float*)d_in[9];
    float* out = (float*)d_out;

    static cudaStream_t sB = nullptr;
    static cudaEvent_t  e0 = nullptr, e1 = nullptr;
    if (!sB){
        cudaStreamCreateWithFlags(&sB, cudaStreamNonBlocking);
        cudaEventCreateWithFlags(&e0, cudaEventDisableTiming);
        cudaEventCreateWithFlags(&e1, cudaEventDisableTiming);
    }

    cudaFuncSetAttribute(k_conv2,
                         cudaFuncAttributeMaxDynamicSharedMemorySize, C2_SMEM);
    cudaFuncSetAttribute(k_conv3pool,
                         cudaFuncAttributeMaxDynamicSharedMemorySize, C3_SMEM);

    // fork: stream B handles segment sort + positional MLP
    cudaEventRecord(e0, 0);
    cudaStreamWaitEvent(sB, e0, 0);

    // stream 0: conv chain
    k_conv1<<<dim3(196,4), 256>>>(img, w1);
    k_conv2<<<C2_GRID, 256, C2_SMEM>>>(w2);

    // stream B: sort chain + pos (independent of conv)
    k_zero<<<1, 1024, 0, sB>>>();
    k_hist<<<dim3(49,4), 256, 0, sB>>>(seg);
    k_scan<<<1, 1024, 0, sB>>>();
    k_scatter<<<dim3(196,4), 256, 0, sB>>>(seg);
    k_pos<<<64, 256, 0, sB>>>(cent, pw1, pb1, pw2, pb2, out + (size_t)BB*SS*EE);
    cudaEventRecord(e1, sB);

    // join: conv3pool needs conv2 (stream order) + sort results (event)
    cudaStreamWaitEvent(0, e1, 0);
    k_conv3pool<<<C3_GRID, 256, C3_SMEM>>>(w3, out);
}

// round 14
// speedup vs baseline: 10.9316x; 1.0353x over previous
#include <cuda_runtime.h>
#include <cuda_fp16.h>
#include <cstdint>

typedef unsigned long long ull;

#define BB 4
#define HH 224
#define WL 224
#define HW 50176
#define NC 64
#define EE 768
#define SS 256

// ---- scratch ----
__device__ __half g_h1[BB*HW*64];    // conv1 output, PIXEL-MAJOR fp16 [b][pix][ci]
__device__ __half g_h2[BB*HW*64];    // conv2 output, PIXEL-MAJOR fp16 [b][pix][ci]
__device__ int   g_cnt[BB*SS];
__device__ int   g_off[BB*SS];
__device__ int   g_cur[BB*SS];
__device__ int   g_order[BB*HW];

// ---- packed fp32x2 helpers ----
__device__ __forceinline__ ull pack2(float a, float b){
    ull d; asm("mov.b64 %0,{%1,%2};" : "=l"(d) : "f"(a), "f"(b)); return d;
}
__device__ __forceinline__ void ffma2(ull& d, ull a, ull b){
    asm("fma.rn.f32x2 %0,%1,%2,%0;" : "+l"(d) : "l"(a), "l"(b));
}
__device__ __forceinline__ float2 unpack2(ull d){
    float2 f; asm("mov.b64 {%0,%1},%2;" : "=f"(f.x), "=f"(f.y) : "l"(d)); return f;
}

__device__ __forceinline__ uint32_t smem_u32(const void* p){
    uint32_t a;
    asm("{ .reg .u64 t; cvta.to.shared.u64 t, %1; cvt.u32.u64 %0, t; }" : "=r"(a) : "l"(p));
    return a;
}
__device__ __forceinline__ uint32_t sw128(uint32_t off){ return off ^ ((off >> 3) & 0x70); }

// ---- cp.async (LDGSTS) helpers ----
__device__ __forceinline__ void cp_async16(uint32_t dst, const void* src, bool valid){
    int sz = valid ? 16 : 0;
    asm volatile("cp.async.cg.shared.global [%0], [%1], 16, %2;"
                 :: "r"(dst), "l"(src), "r"(sz));
}
#define CP_COMMIT() asm volatile("cp.async.commit_group;" ::: "memory")
#define CP_WAIT(n)  asm volatile("cp.async.wait_group %0;" :: "n"(n) : "memory")

// ---- mma.sync fp16 helpers (sm_80 PTX, works on compute_100) ----
__device__ __forceinline__ void ldsm_x4(uint32_t* r, uint32_t a){
    asm volatile("ldmatrix.sync.aligned.m8n8.x4.shared.b16 {%0,%1,%2,%3}, [%4];"
        : "=r"(r[0]),"=r"(r[1]),"=r"(r[2]),"=r"(r[3]) : "r"(a));
}
__device__ __forceinline__ void ldsm_x2(uint32_t* r, uint32_t a){
    asm volatile("ldmatrix.sync.aligned.m8n8.x2.shared.b16 {%0,%1}, [%2];"
        : "=r"(r[0]),"=r"(r[1]) : "r"(a));
}
__device__ __forceinline__ void mma_fp16(float* d, const uint32_t* a, const uint32_t* b){
    asm volatile("mma.sync.aligned.m16n8k16.row.col.f32.f16.f16.f32 "
        "{%0,%1,%2,%3}, {%4,%5,%6,%7}, {%8,%9}, {%0,%1,%2,%3};"
        : "+f"(d[0]),"+f"(d[1]),"+f"(d[2]),"+f"(d[3])
        : "r"(a[0]),"r"(a[1]),"r"(a[2]),"r"(a[3]), "r"(b[0]),"r"(b[1]));
}

// ================= zero counters ============================================
__global__ void k_zero(){
    int t = threadIdx.x;
    g_cnt[t] = 0; g_cur[t] = 0;
}

// ================= conv1: 3->64 3x3 relu, f32x2 packed, fp16 pixel-major ====
__global__ __launch_bounds__(256) void k_conv1(const float* __restrict__ img,
                                               const float* __restrict__ w1){
    __shared__ ull ws[32*28];
    int tid = threadIdx.x;
    for (int i = tid; i < 32*28; i += 256){
        int cp = i / 28, t = i % 28;
        ws[i] = (t < 27) ? pack2(w1[(2*cp)*27+t], w1[(2*cp+1)*27+t]) : 0ULL;
    }
    __syncthreads();
    int b = blockIdx.y;
    int p = blockIdx.x*256 + tid;
    int y = p / WL, x = p % WL;
    ull vp[28];
#pragma unroll
    for (int ci = 0; ci < 3; ci++)
#pragma unroll
    for (int ky = 0; ky < 3; ky++)
#pragma unroll
    for (int kx = 0; kx < 3; kx++){
        int yy = y + ky - 1, xx = x + kx - 1;
        float val = 0.f;
        if (yy >= 0 && yy < HH && xx >= 0 && xx < WL)
            val = img[(size_t)(b*3+ci)*HW + yy*WL + xx];
        vp[ci*9 + ky*3 + kx] = pack2(val, val);
    }
    vp[27] = 0ULL;
    uint32_t pk[32];
#pragma unroll 2
    for (int cp = 0; cp < 32; cp++){
        ull acc = 0ULL;
        const ulonglong2* wp = (const ulonglong2*)&ws[cp*28];
#pragma unroll
        for (int tp = 0; tp < 14; tp++){
            ulonglong2 w = wp[tp];
            ffma2(acc, vp[2*tp],   w.x);
            ffma2(acc, vp[2*tp+1], w.y);
        }
        float2 r = unpack2(acc);
        __half2 h = __floats2half2_rn(fmaxf(r.x,0.f), fmaxf(r.y,0.f));
        pk[cp] = *(uint32_t*)&h;
    }
    uint4* dst = (uint4*)(g_h1 + ((size_t)b*HW + p)*64);
#pragma unroll
    for (int j = 0; j < 8; j++)
        dst[j] = make_uint4(pk[4*j], pk[4*j+1], pk[4*j+2], pk[4*j+3]);
}

// ================= conv2: persistent + cp.async double-buffered =============
#define C2_WS 0
#define C2_F0 73728
#define C2_F1 152064
#define C2_SMEM 230400
#define C2_TILES 392
#define C2_GRID 148

__device__ __forceinline__ void c2_stage(uint32_t sb, uint32_t foff, int tt, int tid){
    int b  = tt / 98;
    int rem = tt - b*98;
    int y0 = (rem / 7) * 16;
    int x0 = (rem - (rem/7)*7) * 32;
    const __half* src = g_h1 + (size_t)b*HW*64;
    for (int lin = tid; lin < 612*8; lin += 256){
        int slot = lin >> 3, part = lin & 7;
        int gy = y0 + slot/34 - 1, gx = x0 + (slot%34) - 1;
        bool v = (gy >= 0 && gy < HH && gx >= 0 && gx < WL);
        const void* s = v ? (const void*)(src + ((size_t)gy*WL + gx)*64 + part*8)
                          : (const void*)src;
        cp_async16(sb + foff + sw128((uint32_t)(slot*128 + part*16)), s, v);
    }
}

__device__ __forceinline__ void c2_compute(uint32_t sb, uint32_t foff, int tt,
                                           int wid, int lane){
    int b  = tt / 98;
    int rem = tt - b*98;
    int y0 = (rem / 7) * 16;
    int x0 = (rem - (rem/7)*7) * 32;
    __half* dsth = g_h2 + (size_t)b*HW*64;

    int rowA = lane & 15, chA = lane >> 4;
    int rowB8 = lane & 7, chB = (lane>>3)&1, grpB = lane>>4;

#pragma unroll 1
    for (int half = 0; half < 2; half++){
        float acc[2][8][4];
#pragma unroll
        for (int mx = 0; mx < 2; mx++)
#pragma unroll
        for (int nt = 0; nt < 8; nt++)
#pragma unroll
        for (int q = 0; q < 4; q++) acc[mx][nt][q] = 0.f;

        int ty = half*8 + wid;
#pragma unroll 1
        for (int pass = 0; pass < 9; pass++){
            int ky = pass / 3, kx = pass - ky*3;
            uint32_t wbase = sb + C2_WS + pass*8192;
            uint32_t bf[8][4][2];
#pragma unroll
            for (int kt = 0; kt < 4; kt++)
#pragma unroll
            for (int ntp = 0; ntp < 4; ntp++){
                uint32_t r[4];
                uint32_t a = wbase + sw128((uint32_t)(((ntp*2 + grpB)*8 + rowB8)*128 + kt*32 + chB*16));
                ldsm_x4(r, a);
                bf[2*ntp][kt][0]   = r[0]; bf[2*ntp][kt][1]   = r[1];
                bf[2*ntp+1][kt][0] = r[2]; bf[2*ntp+1][kt][1] = r[3];
            }
#pragma unroll
            for (int mx = 0; mx < 2; mx++){
                int slot = (ty + ky)*34 + mx*16 + rowA + kx;
                uint32_t af[4][4];
#pragma unroll
                for (int kt = 0; kt < 4; kt++)
                    ldsm_x4(af[kt], sb + foff + sw128((uint32_t)(slot*128 + kt*32 + chA*16)));
#pragma unroll
                for (int nt = 0; nt < 8; nt++)
#pragma unroll
                for (int kt = 0; kt < 4; kt++)
                    mma_fp16(acc[mx][nt], af[kt], bf[nt][kt]);
            }
        }
        int gy = y0 + ty;
#pragma unroll
        for (int mx = 0; mx < 2; mx++){
            int px = x0 + mx*16 + (lane>>2);
            size_t base0 = ((size_t)gy*WL + px)*64;
            size_t base1 = ((size_t)gy*WL + px + 8)*64;
#pragma unroll
            for (int nt = 0; nt < 8; nt++){
                int co = nt*8 + (lane&3)*2;
                __half2 u0 = __floats2half2_rn(fmaxf(acc[mx][nt][0],0.f), fmaxf(acc[mx][nt][1],0.f));
                __half2 u1 = __floats2half2_rn(fmaxf(acc[mx][nt][2],0.f), fmaxf(acc[mx][nt][3],0.f));
                *(uint32_t*)(dsth + base0 + co) = *(uint32_t*)&u0;
                *(uint32_t*)(dsth + base1 + co) = *(uint32_t*)&u1;
            }
        }
    }
}

__global__ __launch_bounds__(256) void k_conv2(const float* __restrict__ w2){
    extern __shared__ __align__(1024) char sm[];
    uint32_t sb = smem_u32(sm);
    int tid = threadIdx.x, wid = tid>>5, lane = tid&31;

    for (int lin = tid; lin < 64*64*9; lin += 256){
        float v = w2[lin];
        int co = lin / 576;
        int rem = lin - co*576;
        int ci = rem / 9;
        int k  = rem - ci*9;
        __half hv = __float2half_rn(v);
        *(__half*)(sm + C2_WS + k*8192 + sw128((uint32_t)(co*128 + ci*2))) = hv;
    }

    int t0 = blockIdx.x;
    int n = 0;
    int tiles[3];
    for (int tt = t0; tt < C2_TILES; tt += C2_GRID) tiles[n++] = tt;
    if (n == 0) return;

    const uint32_t foff[2] = {C2_F0, C2_F1};

    c2_stage(sb, foff[0], tiles[0], tid);
    CP_COMMIT();

    for (int k = 0; k < n; k++){
        if (k + 1 < n){
            c2_stage(sb, foff[(k+1)&1], tiles[k+1], tid);
            CP_COMMIT();
            CP_WAIT(1);
        } else {
            CP_WAIT(0);
        }
        __syncthreads();
        c2_compute(sb, foff[k&1], tiles[k], wid, lane);
        __syncthreads();
    }
}

// ================= segment counting sort ====================================
__global__ __launch_bounds__(256) void k_hist(const int* __restrict__ seg){
    __shared__ int hist[SS];
    int tid = threadIdx.x;
    hist[tid] = 0;
    __syncthreads();
    int b = blockIdx.y;
    int base = blockIdx.x * 1024;
#pragma unroll
    for (int i = 0; i < 4; i++){
        int s = seg[(size_t)b*HW + base + i*256 + tid];
        atomicAdd(&hist[s], 1);
    }
    __syncthreads();
    atomicAdd(&g_cnt[b*SS + tid], hist[tid]);
}

__global__ void k_scan(){
    __shared__ int s[1024];
    int t = threadIdx.x;
    int v = g_cnt[t];
    s[t] = v;
    __syncthreads();
    for (int d = 1; d < 1024; d <<= 1){
        int add = (t >= d) ? s[t-d] : 0;
        __syncthreads();
        s[t] += add;
        __syncthreads();
    }
    g_off[t] = s[t] - v;
}

__global__ __launch_bounds__(256) void k_scatter(const int* __restrict__ seg){
    int b = blockIdx.y;
    int p = blockIdx.x*256 + threadIdx.x;
    int sgm = seg[(size_t)b*HW + p];
    int bin = b*SS + sgm;
    int idx = atomicAdd(&g_cur[bin], 1);
    g_order[g_off[bin] + idx] = p;
}

// ================= conv3+pool: af-resident + CROSS-BIN cp.async pipeline ====
// Grid 148, 1 CTA/SM, one wave; ~7 bins/CTA. Weight frags af[6][4][4] in regs
// (loaded once). The (bin, tile) sequence is flattened into one pipeline:
// while computing the last tile of bin i, tile 0 of bin i+1 is being staged
// into the other buffer -- no cold prologue per bin.
#define W_OFF 0
#define F3_0  98304
#define F3_1  114688
#define C3_SMEM 131072
#define C3_GRID 148

__device__ __forceinline__ void c3_stage(uint32_t sb, uint32_t foff,
                                         const __half* featb, int off,
                                         int tbase, int npix, int nrows, int tid){
    for (int lin = tid; lin < nrows*8; lin += 256){
        int r = lin >> 3, part = lin & 7;
        int idx = tbase + r;
        bool v = idx < npix;
        const void* s;
        if (v){
            int pix = g_order[off + idx];
            s = (const void*)(featb + (size_t)pix*64 + part*8);
        } else s = (const void*)featb;
        cp_async16(sb + foff + sw128((uint32_t)(r*128 + part*16)), s, v);
    }
}

__global__ __launch_bounds__(256, 1) void k_conv3pool(const float* __restrict__ w3,
                                                      float* __restrict__ out){
    extern __shared__ __align__(1024) char sm[];
    int tid  = threadIdx.x;
    int wid  = tid >> 5;
    int lane = tid & 31;
    uint32_t sbase = smem_u32(sm);

    // ---- stage W once ----
#pragma unroll
    for (int rr = 0; rr < 3; rr++){
        int e = tid + rr*256;
        const float4* wrow = (const float4*)(w3 + (size_t)e*64);
#pragma unroll
        for (int k = 0; k < 16; k++){
            float4 f4 = wrow[k];
            __half2 h0 = __float22half2_rn(make_float2(f4.x, f4.y));
            __half2 h1 = __float22half2_rn(make_float2(f4.z, f4.w));
            uint2 u; u.x = *(uint32_t*)&h0; u.y = *(uint32_t*)&h1;
            *(uint2*)(sm + W_OFF + sw128((uint32_t)(e*128 + k*8))) = u;
        }
    }
    __syncthreads();

    // ---- weight fragments resident in registers ----
    int rowA = lane & 15, chA = lane >> 4;
    uint32_t af[6][4][4];
#pragma unroll
    for (int i = 0; i < 6; i++){
        int e0 = (wid*6 + i)*16;
#pragma unroll
        for (int kt = 0; kt < 4; kt++)
            ldsm_x4(af[i][kt], sbase + W_OFF + sw128((uint32_t)((e0 + rowA)*128 + kt*32 + chA*16)));
    }

    int rowB = lane & 7, chB = (lane >> 3) & 1, grpB = lane >> 4;
    const uint32_t foff[2] = {F3_0, F3_1};

    int mybins[7]; int nb = 0;
    for (int bin = blockIdx.x; bin < BB*SS; bin += C3_GRID) mybins[nb++] = bin;

    // prologue: stage tile 0 of bin 0
    {
        int bin = mybins[0];
        int npix = g_cnt[bin], off = g_off[bin];
        const __half* fb = g_h2 + (size_t)(bin >> 8)*HW*64;
        int rem0 = npix > 128 ? 128 : (npix < 0 ? 0 : npix);
        int nr0 = ((rem0 + 31) >> 5) * 32;
        c3_stage(sbase, foff[0], fb, off, 0, npix, nr0, tid);
    }
    CP_COMMIT();
    int pbuf = 0;

#pragma unroll 1
    for (int bi = 0; bi < nb; bi++){
        int bin  = mybins[bi];
        int npix = g_cnt[bin];
        int off  = g_off[bin];
        int ntiles = (npix + 127) >> 7; if (ntiles < 1) ntiles = 1;

        float acc[6][2];
#pragma unroll
        for (int i = 0; i < 6; i++){ acc[i][0] = 0.f; acc[i][1] = 0.f; }

        for (int t = 0; t < ntiles; t++){
            int rem = npix - t*128;
            if (rem > 128) rem = 128;
            if (rem < 0) rem = 0;
            int ntcN = (rem + 31) >> 5;

            // select next (cross-bin) tile and stage it
            bool has_next = false; int nbin = 0, ntb = 0;
            if (t + 1 < ntiles){ nbin = bin; ntb = t + 1; has_next = true; }
            else if (bi + 1 < nb){ nbin = mybins[bi+1]; ntb = 0; has_next = true; }
            if (has_next){
                int nnp = g_cnt[nbin], noff = g_off[nbin];
                const __half* nfb = g_h2 + (size_t)(nbin >> 8)*HW*64;
                int nrem = nnp - ntb*128;
                if (nrem > 128) nrem = 128;
                if (nrem < 0) nrem = 0;
                int nr = ((nrem + 31) >> 5) * 32;
                c3_stage(sbase, foff[pbuf^1], nfb, noff, ntb*128, nnp, nr, tid);
                CP_COMMIT();
                CP_WAIT(1);
            } else {
                CP_WAIT(0);
            }
            __syncthreads();
            uint32_t fbp = sbase + foff[pbuf];

#pragma unroll 1
            for (int ntc = 0; ntc < ntcN; ntc++){
                uint32_t bf[4][4][2];
#pragma unroll
                for (int kt = 0; kt < 4; kt++)
#pragma unroll
                for (int jp = 0; jp < 2; jp++){
                    uint32_t r[4];
                    int px = (ntc*4 + jp*2 + grpB)*8 + rowB;
                    ldsm_x4(r, fbp + sw128((uint32_t)(px*128 + kt*32 + chB*16)));
                    bf[jp*2][kt][0]   = r[0]; bf[jp*2][kt][1]   = r[1];
                    bf[jp*2+1][kt][0] = r[2]; bf[jp*2+1][kt][1] = r[3];
                }
#pragma unroll
                for (int i = 0; i < 6; i++){
                    float d[4][4];
#pragma unroll
                    for (int j = 0; j < 4; j++)
#pragma unroll
                    for (int q = 0; q < 4; q++) d[j][q] = 0.f;
#pragma unroll
                    for (int kt = 0; kt < 4; kt++)
#pragma unroll
                    for (int j = 0; j < 4; j++)
                        mma_fp16(d[j], af[i][kt], bf[j][kt]);
#pragma unroll
                    for (int j = 0; j < 4; j++){
                        acc[i][0] += fmaxf(d[j][0], 0.f) + fmaxf(d[j][1], 0.f);
                        acc[i][1] += fmaxf(d[j][2], 0.f) + fmaxf(d[j][3], 0.f);
                    }
                }
            }
            __syncthreads();   // compute reads done before restaging this buffer
            pbuf ^= 1;
        }

        float inv = 1.f / (float)max(npix, 1);
#pragma unroll
        for (int i = 0; i < 6; i++){
            acc[i][0] += __shfl_xor_sync(0xffffffffu, acc[i][0], 1);
            acc[i][0] += __shfl_xor_sync(0xffffffffu, acc[i][0], 2);
            acc[i][1] += __shfl_xor_sync(0xffffffffu, acc[i][1], 1);
            acc[i][1] += __shfl_xor_sync(0xffffffffu, acc[i][1], 2);
        }
        if ((lane & 3) == 0){
            int row = lane >> 2;
            float* ob = out + (size_t)bin*EE;
#pragma unroll
            for (int i = 0; i < 6; i++){
                int e = (wid*6 + i)*16 + row;
                ob[e]     = acc[i][0] * inv;
                ob[e + 8] = acc[i][1] * inv;
            }
        }
    }
}

// ================= positional MLP: 128 CTAs (4 e-quarters x 32 row-groups) ==
#define POS_ROWS 32
__global__ __launch_bounds__(192) void k_pos(const float* __restrict__ cent,
        const float* __restrict__ w1, const float* __restrict__ b1,
        const float* __restrict__ w2, const float* __restrict__ b2,
        float* __restrict__ out){
    __shared__ __align__(16) float h2[384*POS_ROWS];   // 48 KB
    int tid = threadIdx.x;          // e offset within quarter (0..191)
    int eq  = blockIdx.x;           // 0..3
    int rb  = blockIdx.y * POS_ROWS;
    for (int lin = tid; lin < 384*POS_ROWS; lin += 192){
        int j = lin >> 5, r = lin & 31;
        int rid = rb + r;
        float c0 = cent[rid*2+0] * (1.f/223.f);
        float c1 = cent[rid*2+1] * (1.f/223.f);
        h2[j*POS_ROWS + r] = fmaxf(fmaf(c0, w1[j], fmaf(c1, w1[384+j], b1[j])), 0.f);
    }
    __syncthreads();
    int e = eq*192 + tid;
    ull acc[16];
#pragma unroll
    for (int q = 0; q < 16; q++) acc[q] = 0ULL;
    for (int j = 0; j < 384; j++){
        float wv = w2[(size_t)j*768 + e];
        ull wp = pack2(wv, wv);
        const ull* hp = (const ull*)&h2[j*POS_ROWS];
#pragma unroll
        for (int q = 0; q < 16; q++) ffma2(acc[q], hp[q], wp);
    }
    float bv = b2[e];
#pragma unroll
    for (int q = 0; q < 16; q++){
        float2 v = unpack2(acc[q]);
        int rid = rb + 2*q;
        out[(size_t)rid*768 + e]     = v.x + bv;
        out[(size_t)(rid+1)*768 + e] = v.y + bv;
    }
}

// ================= launcher (two-stream fork/join inside graph capture) =====
extern "C" void kernel_launch(void* const* d_in, const int* in_sizes, int n_in,
                              void* d_out, int out_size){
    const float* img  = (const float*)d_in[0];
    const int*   seg  = (const int*)d_in[1];
    const float* cent = (const float*)d_in[2];
    const float* w1   = (const float*)d_in[3];
    const float* w2   = (const float*)d_in[4];
    const float* w3   = (const float*)d_in[5];
    const float* pw1  = (const float*)d_in[6];
    const float* pb1  = (const float*)d_in[7];
    const float* pw2  = (const float*)d_in[8];
    const float* pb2  = (const float*)d_in[9];
    float* out = (float*)d_out;

    static cudaStream_t sB = nullptr;
    static cudaEvent_t  e0 = nullptr, e1 = nullptr;
    if (!sB){
        cudaStreamCreateWithFlags(&sB, cudaStreamNonBlocking);
        cudaEventCreateWithFlags(&e0, cudaEventDisableTiming);
        cudaEventCreateWithFlags(&e1, cudaEventDisableTiming);
    }

    cudaFuncSetAttribute(k_conv2,
                         cudaFuncAttributeMaxDynamicSharedMemorySize, C2_SMEM);
    cudaFuncSetAttribute(k_conv3pool,
                         cudaFuncAttributeMaxDynamicSharedMemorySize, C3_SMEM);

    // fork: stream B handles segment sort + positional MLP
    cudaEventRecord(e0, 0);
    cudaStreamWaitEvent(sB, e0, 0);

    // stream 0: conv chain
    k_conv1<<<dim3(196,4), 256>>>(img, w1);
    k_conv2<<<C2_GRID, 256, C2_SMEM>>>(w2);

    // stream B: sort chain + pos (independent of conv)
    k_zero<<<1, 1024, 0, sB>>>();
    k_hist<<<dim3(49,4), 256, 0, sB>>>(seg);
    k_scan<<<1, 1024, 0, sB>>>();
    k_scatter<<<dim3(196,4), 256, 0, sB>>>(seg);
    k_pos<<<dim3(4,32), 192, 0, sB>>>(cent, pw1, pb1, pw2, pb2, out + (size_t)BB*SS*EE);
    cudaEventRecord(e1, sB);

    // join: conv3pool needs conv2 (stream order) + sort results (event)
    cudaStreamWaitEvent(0, e1, 0);
    k_conv3pool<<<C3_GRID, 256, C3_SMEM>>>(w3, out);
}

// round 15
// speedup vs baseline: 11.0483x; 1.0107x over previous
#include <cuda_runtime.h>
#include <cuda_fp16.h>
#include <cstdint>

typedef unsigned long long ull;

#define BB 4
#define HH 224
#define WL 224
#define HW 50176
#define NC 64
#define EE 768
#define SS 256

// ---- scratch ----
__device__ __half g_h1[BB*HW*64];    // conv1 output, PIXEL-MAJOR fp16 [b][pix][ci]
__device__ __half g_h2[BB*HW*64];    // conv2 output, PIXEL-MAJOR fp16 [b][pix][ci]
__device__ int   g_cnt[BB*SS];
__device__ int   g_off[BB*SS];
__device__ int   g_cur[BB*SS];
__device__ int   g_order[BB*HW];

// ---- packed fp32x2 helpers ----
__device__ __forceinline__ ull pack2(float a, float b){
    ull d; asm("mov.b64 %0,{%1,%2};" : "=l"(d) : "f"(a), "f"(b)); return d;
}
__device__ __forceinline__ void ffma2(ull& d, ull a, ull b){
    asm("fma.rn.f32x2 %0,%1,%2,%0;" : "+l"(d) : "l"(a), "l"(b));
}
__device__ __forceinline__ float2 unpack2(ull d){
    float2 f; asm("mov.b64 {%0,%1},%2;" : "=f"(f.x), "=f"(f.y) : "l"(d)); return f;
}

__device__ __forceinline__ uint32_t smem_u32(const void* p){
    uint32_t a;
    asm("{ .reg .u64 t; cvta.to.shared.u64 t, %1; cvt.u32.u64 %0, t; }" : "=r"(a) : "l"(p));
    return a;
}
__device__ __forceinline__ uint32_t sw128(uint32_t off){ return off ^ ((off >> 3) & 0x70); }

// ---- cp.async (LDGSTS) helpers ----
__device__ __forceinline__ void cp_async16(uint32_t dst, const void* src, bool valid){
    int sz = valid ? 16 : 0;
    asm volatile("cp.async.cg.shared.global [%0], [%1], 16, %2;"
                 :: "r"(dst), "l"(src), "r"(sz));
}
#define CP_COMMIT() asm volatile("cp.async.commit_group;" ::: "memory")
#define CP_WAIT(n)  asm volatile("cp.async.wait_group %0;" :: "n"(n) : "memory")

// ---- mma.sync fp16 helpers (sm_80 PTX, works on compute_100) ----
__device__ __forceinline__ void ldsm_x4(uint32_t* r, uint32_t a){
    asm volatile("ldmatrix.sync.aligned.m8n8.x4.shared.b16 {%0,%1,%2,%3}, [%4];"
        : "=r"(r[0]),"=r"(r[1]),"=r"(r[2]),"=r"(r[3]) : "r"(a));
}
__device__ __forceinline__ void ldsm_x2(uint32_t* r, uint32_t a){
    asm volatile("ldmatrix.sync.aligned.m8n8.x2.shared.b16 {%0,%1}, [%2];"
        : "=r"(r[0]),"=r"(r[1]) : "r"(a));
}
__device__ __forceinline__ void mma_fp16(float* d, const uint32_t* a, const uint32_t* b){
    asm volatile("mma.sync.aligned.m16n8k16.row.col.f32.f16.f16.f32 "
        "{%0,%1,%2,%3}, {%4,%5,%6,%7}, {%8,%9}, {%0,%1,%2,%3};"
        : "+f"(d[0]),"+f"(d[1]),"+f"(d[2]),"+f"(d[3])
        : "r"(a[0]),"r"(a[1]),"r"(a[2]),"r"(a[3]), "r"(b[0]),"r"(b[1]));
}

// ================= zero counters ============================================
__global__ void k_zero(){
    int t = threadIdx.x;
    g_cnt[t] = 0; g_cur[t] = 0;
}

// ================= conv1: 3->64 3x3 relu, f32x2 packed, fp16 pixel-major ====
__global__ __launch_bounds__(256) void k_conv1(const float* __restrict__ img,
                                               const float* __restrict__ w1){
    __shared__ ull ws[32*28];
    int tid = threadIdx.x;
    for (int i = tid; i < 32*28; i += 256){
        int cp = i / 28, t = i % 28;
        ws[i] = (t < 27) ? pack2(w1[(2*cp)*27+t], w1[(2*cp+1)*27+t]) : 0ULL;
    }
    __syncthreads();
    int b = blockIdx.y;
    int p = blockIdx.x*256 + tid;
    int y = p / WL, x = p % WL;
    ull vp[28];
#pragma unroll
    for (int ci = 0; ci < 3; ci++)
#pragma unroll
    for (int ky = 0; ky < 3; ky++)
#pragma unroll
    for (int kx = 0; kx < 3; kx++){
        int yy = y + ky - 1, xx = x + kx - 1;
        float val = 0.f;
        if (yy >= 0 && yy < HH && xx >= 0 && xx < WL)
            val = img[(size_t)(b*3+ci)*HW + yy*WL + xx];
        vp[ci*9 + ky*3 + kx] = pack2(val, val);
    }
    vp[27] = 0ULL;
    uint32_t pk[32];
#pragma unroll 2
    for (int cp = 0; cp < 32; cp++){
        ull acc = 0ULL;
        const ulonglong2* wp = (const ulonglong2*)&ws[cp*28];
#pragma unroll
        for (int tp = 0; tp < 14; tp++){
            ulonglong2 w = wp[tp];
            ffma2(acc, vp[2*tp],   w.x);
            ffma2(acc, vp[2*tp+1], w.y);
        }
        float2 r = unpack2(acc);
        __half2 h = __floats2half2_rn(fmaxf(r.x,0.f), fmaxf(r.y,0.f));
        pk[cp] = *(uint32_t*)&h;
    }
    uint4* dst = (uint4*)(g_h1 + ((size_t)b*HW + p)*64);
#pragma unroll
    for (int j = 0; j < 8; j++)
        dst[j] = make_uint4(pk[4*j], pk[4*j+1], pk[4*j+2], pk[4*j+3]);
}

// ================= conv2: persistent + cp.async + kt-outer (weights 1x) =====
// Reordered mainloop: pass -> kt -> {bf weights for all 8 nt: 4 ldsm_x4} ->
// (half, mx): {af: 1 ldsm_x4; 8 HMMA}. Weight LDSM halves (288->144/tile/warp,
// total 432->288). acc[2][2][8][4]=128 regs, bf 16, af 4 -> ~170 regs, no
// spills. Accumulation order per element (pass asc, kt asc) unchanged ->
// bit-identical output.
#define C2_WS 0
#define C2_F0 73728
#define C2_F1 152064
#define C2_SMEM 230400
#define C2_TILES 392
#define C2_GRID 148

__device__ __forceinline__ void c2_stage(uint32_t sb, uint32_t foff, int tt, int tid){
    int b  = tt / 98;
    int rem = tt - b*98;
    int y0 = (rem / 7) * 16;
    int x0 = (rem - (rem/7)*7) * 32;
    const __half* src = g_h1 + (size_t)b*HW*64;
    for (int lin = tid; lin < 612*8; lin += 256){
        int slot = lin >> 3, part = lin & 7;
        int gy = y0 + slot/34 - 1, gx = x0 + (slot%34) - 1;
        bool v = (gy >= 0 && gy < HH && gx >= 0 && gx < WL);
        const void* s = v ? (const void*)(src + ((size_t)gy*WL + gx)*64 + part*8)
                          : (const void*)src;
        cp_async16(sb + foff + sw128((uint32_t)(slot*128 + part*16)), s, v);
    }
}

__device__ __forceinline__ void c2_compute(uint32_t sb, uint32_t foff, int tt,
                                           int wid, int lane){
    int b  = tt / 98;
    int rem = tt - b*98;
    int y0 = (rem / 7) * 16;
    int x0 = (rem - (rem/7)*7) * 32;
    __half* dsth = g_h2 + (size_t)b*HW*64;

    int rowA = lane & 15, chA = lane >> 4;
    int rowB8 = lane & 7, chB = (lane>>3)&1, grpB = lane>>4;

    float acc[2][2][8][4];     // [half][mx][nt][q]
#pragma unroll
    for (int h = 0; h < 2; h++)
#pragma unroll
    for (int mx = 0; mx < 2; mx++)
#pragma unroll
    for (int nt = 0; nt < 8; nt++)
#pragma unroll
    for (int q = 0; q < 4; q++) acc[h][mx][nt][q] = 0.f;

#pragma unroll 1
    for (int pass = 0; pass < 9; pass++){
        int ky = pass / 3, kx = pass - ky*3;
        uint32_t wbase = sb + C2_WS + pass*8192;
#pragma unroll
        for (int kt = 0; kt < 4; kt++){
            uint32_t bf[8][2];
#pragma unroll
            for (int ntp = 0; ntp < 4; ntp++){
                uint32_t r[4];
                uint32_t a = wbase + sw128((uint32_t)(((ntp*2 + grpB)*8 + rowB8)*128 + kt*32 + chB*16));
                ldsm_x4(r, a);
                bf[2*ntp][0]   = r[0]; bf[2*ntp][1]   = r[1];
                bf[2*ntp+1][0] = r[2]; bf[2*ntp+1][1] = r[3];
            }
#pragma unroll
            for (int half = 0; half < 2; half++){
                int ty = half*8 + wid;
#pragma unroll
                for (int mx = 0; mx < 2; mx++){
                    int slot = (ty + ky)*34 + mx*16 + rowA + kx;
                    uint32_t af[4];
                    ldsm_x4(af, sb + foff + sw128((uint32_t)(slot*128 + kt*32 + chA*16)));
#pragma unroll
                    for (int nt = 0; nt < 8; nt++)
                        mma_fp16(acc[half][mx][nt], af, bf[nt]);
                }
            }
        }
    }

    // epilogue: relu -> fp16 pixel-major (both halves)
#pragma unroll
    for (int half = 0; half < 2; half++){
        int gy = y0 + half*8 + wid;
#pragma unroll
        for (int mx = 0; mx < 2; mx++){
            int px = x0 + mx*16 + (lane>>2);
            size_t base0 = ((size_t)gy*WL + px)*64;
            size_t base1 = ((size_t)gy*WL + px + 8)*64;
#pragma unroll
            for (int nt = 0; nt < 8; nt++){
                int co = nt*8 + (lane&3)*2;
                __half2 u0 = __floats2half2_rn(fmaxf(acc[half][mx][nt][0],0.f), fmaxf(acc[half][mx][nt][1],0.f));
                __half2 u1 = __floats2half2_rn(fmaxf(acc[half][mx][nt][2],0.f), fmaxf(acc[half][mx][nt][3],0.f));
                *(uint32_t*)(dsth + base0 + co) = *(uint32_t*)&u0;
                *(uint32_t*)(dsth + base1 + co) = *(uint32_t*)&u1;
            }
        }
    }
}

__global__ __launch_bounds__(256) void k_conv2(const float* __restrict__ w2){
    extern __shared__ __align__(1024) char sm[];
    uint32_t sb = smem_u32(sm);
    int tid = threadIdx.x, wid = tid>>5, lane = tid&31;

    for (int lin = tid; lin < 64*64*9; lin += 256){
        float v = w2[lin];
        int co = lin / 576;
        int rem = lin - co*576;
        int ci = rem / 9;
        int k  = rem - ci*9;
        __half hv = __float2half_rn(v);
        *(__half*)(sm + C2_WS + k*8192 + sw128((uint32_t)(co*128 + ci*2))) = hv;
    }

    int t0 = blockIdx.x;
    int n = 0;
    int tiles[3];
    for (int tt = t0; tt < C2_TILES; tt += C2_GRID) tiles[n++] = tt;
    if (n == 0) return;

    const uint32_t foff[2] = {C2_F0, C2_F1};

    c2_stage(sb, foff[0], tiles[0], tid);
    CP_COMMIT();

    for (int k = 0; k < n; k++){
        if (k + 1 < n){
            c2_stage(sb, foff[(k+1)&1], tiles[k+1], tid);
            CP_COMMIT();
            CP_WAIT(1);
        } else {
            CP_WAIT(0);
        }
        __syncthreads();
        c2_compute(sb, foff[k&1], tiles[k], wid, lane);
        __syncthreads();
    }
}

// ================= segment counting sort ====================================
__global__ __launch_bounds__(256) void k_hist(const int* __restrict__ seg){
    __shared__ int hist[SS];
    int tid = threadIdx.x;
    hist[tid] = 0;
    __syncthreads();
    int b = blockIdx.y;
    int base = blockIdx.x * 1024;
#pragma unroll
    for (int i = 0; i < 4; i++){
        int s = seg[(size_t)b*HW + base + i*256 + tid];
        atomicAdd(&hist[s], 1);
    }
    __syncthreads();
    atomicAdd(&g_cnt[b*SS + tid], hist[tid]);
}

__global__ void k_scan(){
    __shared__ int s[1024];
    int t = threadIdx.x;
    int v = g_cnt[t];
    s[t] = v;
    __syncthreads();
    for (int d = 1; d < 1024; d <<= 1){
        int add = (t >= d) ? s[t-d] : 0;
        __syncthreads();
        s[t] += add;
        __syncthreads();
    }
    g_off[t] = s[t] - v;
}

__global__ __launch_bounds__(256) void k_scatter(const int* __restrict__ seg){
    int b = blockIdx.y;
    int p = blockIdx.x*256 + threadIdx.x;
    int sgm = seg[(size_t)b*HW + p];
    int bin = b*SS + sgm;
    int idx = atomicAdd(&g_cur[bin], 1);
    g_order[g_off[bin] + idx] = p;
}

// ================= conv3+pool: af-resident, 256-px tiles, cross-bin pipe ====
// Grid 148, 1 CTA/SM, one wave; ~7 bins/CTA. Weight frags af[6][4][4] in regs.
// 256-px double-buffered tiles (32KB each) halve stage/sync iterations; the
// (bin, tile) sequence is one flattened cp.async pipeline.
#define W_OFF 0
#define F3_0  98304
#define F3_1  131072
#define C3_SMEM 163840
#define C3_GRID 148
#define C3_TPX 256

__device__ __forceinline__ void c3_stage(uint32_t sb, uint32_t foff,
                                         const __half* featb, int off,
                                         int tbase, int npix, int nrows, int tid){
    for (int lin = tid; lin < nrows*8; lin += 256){
        int r = lin >> 3, part = lin & 7;
        int idx = tbase + r;
        bool v = idx < npix;
        const void* s;
        if (v){
            int pix = g_order[off + idx];
            s = (const void*)(featb + (size_t)pix*64 + part*8);
        } else s = (const void*)featb;
        cp_async16(sb + foff + sw128((uint32_t)(r*128 + part*16)), s, v);
    }
}

__global__ __launch_bounds__(256, 1) void k_conv3pool(const float* __restrict__ w3,
                                                      float* __restrict__ out){
    extern __shared__ __align__(1024) char sm[];
    int tid  = threadIdx.x;
    int wid  = tid >> 5;
    int lane = tid & 31;
    uint32_t sbase = smem_u32(sm);

    // ---- stage W once ----
#pragma unroll
    for (int rr = 0; rr < 3; rr++){
        int e = tid + rr*256;
        const float4* wrow = (const float4*)(w3 + (size_t)e*64);
#pragma unroll
        for (int k = 0; k < 16; k++){
            float4 f4 = wrow[k];
            __half2 h0 = __float22half2_rn(make_float2(f4.x, f4.y));
            __half2 h1 = __float22half2_rn(make_float2(f4.z, f4.w));
            uint2 u; u.x = *(uint32_t*)&h0; u.y = *(uint32_t*)&h1;
            *(uint2*)(sm + W_OFF + sw128((uint32_t)(e*128 + k*8))) = u;
        }
    }
    __syncthreads();

    // ---- weight fragments resident in registers ----
    int rowA = lane & 15, chA = lane >> 4;
    uint32_t af[6][4][4];
#pragma unroll
    for (int i = 0; i < 6; i++){
        int e0 = (wid*6 + i)*16;
#pragma unroll
        for (int kt = 0; kt < 4; kt++)
            ldsm_x4(af[i][kt], sbase + W_OFF + sw128((uint32_t)((e0 + rowA)*128 + kt*32 + chA*16)));
    }

    int rowB = lane & 7, chB = (lane >> 3) & 1, grpB = lane >> 4;
    const uint32_t foff[2] = {F3_0, F3_1};

    int mybins[7]; int nb = 0;
    for (int bin = blockIdx.x; bin < BB*SS; bin += C3_GRID) mybins[nb++] = bin;

    // prologue: stage tile 0 of bin 0
    {
        int bin = mybins[0];
        int npix = g_cnt[bin], off = g_off[bin];
        const __half* fb = g_h2 + (size_t)(bin >> 8)*HW*64;
        int rem0 = npix > C3_TPX ? C3_TPX : (npix < 0 ? 0 : npix);
        int nr0 = ((rem0 + 31) >> 5) * 32;
        c3_stage(sbase, foff[0], fb, off, 0, npix, nr0, tid);
    }
    CP_COMMIT();
    int pbuf = 0;

#pragma unroll 1
    for (int bi = 0; bi < nb; bi++){
        int bin  = mybins[bi];
        int npix = g_cnt[bin];
        int off  = g_off[bin];
        int ntiles = (npix + C3_TPX-1) / C3_TPX; if (ntiles < 1) ntiles = 1;

        float acc[6][2];
#pragma unroll
        for (int i = 0; i < 6; i++){ acc[i][0] = 0.f; acc[i][1] = 0.f; }

        for (int t = 0; t < ntiles; t++){
            int rem = npix - t*C3_TPX;
            if (rem > C3_TPX) rem = C3_TPX;
            if (rem < 0) rem = 0;
            int ntcN = (rem + 31) >> 5;

            // select next (cross-bin) tile and stage it
            bool has_next = false; int nbin = 0, ntb = 0;
            if (t + 1 < ntiles){ nbin = bin; ntb = t + 1; has_next = true; }
            else if (bi + 1 < nb){ nbin = mybins[bi+1]; ntb = 0; has_next = true; }
            if (has_next){
                int nnp = g_cnt[nbin], noff = g_off[nbin];
                const __half* nfb = g_h2 + (size_t)(nbin >> 8)*HW*64;
                int nrem = nnp - ntb*C3_TPX;
                if (nrem > C3_TPX) nrem = C3_TPX;
                if (nrem < 0) nrem = 0;
                int nr = ((nrem + 31) >> 5) * 32;
                c3_stage(sbase, foff[pbuf^1], nfb, noff, ntb*C3_TPX, nnp, nr, tid);
                CP_COMMIT();
                CP_WAIT(1);
            } else {
                CP_WAIT(0);
            }
            __syncthreads();
            uint32_t fbp = sbase + foff[pbuf];

#pragma unroll 1
            for (int ntc = 0; ntc < ntcN; ntc++){
                uint32_t bf[4][4][2];
#pragma unroll
                for (int kt = 0; kt < 4; kt++)
#pragma unroll
                for (int jp = 0; jp < 2; jp++){
                    uint32_t r[4];
                    int px = (ntc*4 + jp*2 + grpB)*8 + rowB;
                    ldsm_x4(r, fbp + sw128((uint32_t)(px*128 + kt*32 + chB*16)));
                    bf[jp*2][kt][0]   = r[0]; bf[jp*2][kt][1]   = r[1];
                    bf[jp*2+1][kt][0] = r[2]; bf[jp*2+1][kt][1] = r[3];
                }
#pragma unroll
                for (int i = 0; i < 6; i++){
                    float d[4][4];
#pragma unroll
                    for (int j = 0; j < 4; j++)
#pragma unroll
                    for (int q = 0; q < 4; q++) d[j][q] = 0.f;
#pragma unroll
                    for (int kt = 0; kt < 4; kt++)
#pragma unroll
                    for (int j = 0; j < 4; j++)
                        mma_fp16(d[j], af[i][kt], bf[j][kt]);
#pragma unroll
                    for (int j = 0; j < 4; j++){
                        acc[i][0] += fmaxf(d[j][0], 0.f) + fmaxf(d[j][1], 0.f);
                        acc[i][1] += fmaxf(d[j][2], 0.f) + fmaxf(d[j][3], 0.f);
                    }
                }
            }
            __syncthreads();   // compute reads done before restaging this buffer
            pbuf ^= 1;
        }

        float inv = 1.f / (float)max(npix, 1);
#pragma unroll
        for (int i = 0; i < 6; i++){
            acc[i][0] += __shfl_xor_sync(0xffffffffu, acc[i][0], 1);
            acc[i][0] += __shfl_xor_sync(0xffffffffu, acc[i][0], 2);
            acc[i][1] += __shfl_xor_sync(0xffffffffu, acc[i][1], 1);
            acc[i][1] += __shfl_xor_sync(0xffffffffu, acc[i][1], 2);
        }
        if ((lane & 3) == 0){
            int row = lane >> 2;
            float* ob = out + (size_t)bin*EE;
#pragma unroll
            for (int i = 0; i < 6; i++){
                int e = (wid*6 + i)*16 + row;
                ob[e]     = acc[i][0] * inv;
                ob[e + 8] = acc[i][1] * inv;
            }
        }
    }
}

// ================= positional MLP: 128 CTAs (4 e-quarters x 32 row-groups) ==
#define POS_ROWS 32
__global__ __launch_bounds__(192) void k_pos(const float* __restrict__ cent,
        const float* __restrict__ w1, const float* __restrict__ b1,
        const float* __restrict__ w2, const float* __restrict__ b2,
        float* __restrict__ out){
    __shared__ __align__(16) float h2[384*POS_ROWS];   // 48 KB
    int tid = threadIdx.x;
    int eq  = blockIdx.x;
    int rb  = blockIdx.y * POS_ROWS;
    for (int lin = tid; lin < 384*POS_ROWS; lin += 192){
        int j = lin >> 5, r = lin & 31;
        int rid = rb + r;
        float c0 = cent[rid*2+0] * (1.f/223.f);
        float c1 = cent[rid*2+1] * (1.f/223.f);
        h2[j*POS_ROWS + r] = fmaxf(fmaf(c0, w1[j], fmaf(c1, w1[384+j], b1[j])), 0.f);
    }
    __syncthreads();
    int e = eq*192 + tid;
    ull acc[16];
#pragma unroll
    for (int q = 0; q < 16; q++) acc[q] = 0ULL;
    for (int j = 0; j < 384; j++){
        float wv = w2[(size_t)j*768 + e];
        ull wp = pack2(wv, wv);
        const ull* hp = (const ull*)&h2[j*POS_ROWS];
#pragma unroll
        for (int q = 0; q < 16; q++) ffma2(acc[q], hp[q], wp);
    }
    float bv = b2[e];
#pragma unroll
    for (int q = 0; q < 16; q++){
        float2 v = unpack2(acc[q]);
        int rid = rb + 2*q;
        out[(size_t)rid*768 + e]     = v.x + bv;
        out[(size_t)(rid+1)*768 + e] = v.y + bv;
    }
}

// ================= launcher (two-stream fork/join inside graph capture) =====
extern "C" void kernel_launch(void* const* d_in, const int* in_sizes, int n_in,
                              void* d_out, int out_size){
    const float* img  = (const float*)d_in[0];
    const int*   seg  = (const int*)d_in[1];
    const float* cent = (const float*)d_in[2];
    const float* w1   = (const float*)d_in[3];
    const float* w2   = (const float*)d_in[4];
    const float* w3   = (const float*)d_in[5];
    const float* pw1  = (const float*)d_in[6];
    const float* pb1  = (const float*)d_in[7];
    const float* pw2  = (const float*)d_in[8];
    const float* pb2  = (const float*)d_in[9];
    float* out = (float*)d_out;

    static cudaStream_t sB = nullptr;
    static cudaEvent_t  e0 = nullptr, e1 = nullptr;
    if (!sB){
        cudaStreamCreateWithFlags(&sB, cudaStreamNonBlocking);
        cudaEventCreateWithFlags(&e0, cudaEventDisableTiming);
        cudaEventCreateWithFlags(&e1, cudaEventDisableTiming);
    }

    cudaFuncSetAttribute(k_conv2,
                         cudaFuncAttributeMaxDynamicSharedMemorySize, C2_SMEM);
    cudaFuncSetAttribute(k_conv3pool,
                         cudaFuncAttributeMaxDynamicSharedMemorySize, C3_SMEM);

    // fork: stream B handles segment sort + positional MLP
    cudaEventRecord(e0, 0);
    cudaStreamWaitEvent(sB, e0, 0);

    // stream 0: conv chain
    k_conv1<<<dim3(196,4), 256>>>(img, w1);
    k_conv2<<<C2_GRID, 256, C2_SMEM>>>(w2);

    // stream B: sort chain + pos (independent of conv)
    k_zero<<<1, 1024, 0, sB>>>();
    k_hist<<<dim3(49,4), 256, 0, sB>>>(seg);
    k_scan<<<1, 1024, 0, sB>>>();
    k_scatter<<<dim3(196,4), 256, 0, sB>>>(seg);
    k_pos<<<dim3(4,32), 192, 0, sB>>>(cent, pw1, pb1, pw2, pb2, out + (size_t)BB*SS*EE);
    cudaEventRecord(e1, sB);

    // join: conv3pool needs conv2 (stream order) + sort results (event)
    cudaStreamWaitEvent(0, e1, 0);
    k_conv3pool<<<C3_GRID, 256, C3_SMEM>>>(w3, out);
}